// round 1
// baseline (speedup 1.0000x reference)
#include <cuda_runtime.h>
#include <math.h>

// Problem constants (shape-specialized)
#define BB 4
#define NN 16384
#define CC 512
#define HH 8
#define DD 64
#define NT (BB*NN)     // 65536 rows
#define W3 (3*CC)      // 1536

// -log2(10)/16  (freqs_i = 10^{-i/16} = exp2(i * this))
#define FREQ_COEF (-0.20762050593046014f)

// Scratch (device globals: allocation-free rule)
__device__ float g_q[(size_t)BB*HH*NN*DD];
__device__ float g_k[(size_t)BB*HH*NN*DD];
__device__ float g_v[(size_t)BB*HH*NN*DD];
__device__ float g_attn[(size_t)NT*CC];
__device__ float g_kv[BB*HH*DD*DD];
__device__ float g_ksum[BB*HH*DD];

// ---------------------------------------------------------------------------
// Zero kv / ksum accumulators (must run every launch: graph replays)
// ---------------------------------------------------------------------------
__global__ void zero_kv_kernel() {
    int i = blockIdx.x * blockDim.x + threadIdx.x;
    if (i < BB*HH*DD*DD) g_kv[i] = 0.f;
    if (i < BB*HH*DD)    g_ksum[i] = 0.f;
}

// ---------------------------------------------------------------------------
// GEMM1: qkv = x @ w_qkv + b_qkv, fused epilogue:
//   - split into q/k/v per 512-col section (tile n-width 64 never straddles)
//   - axial RoPE on q,k (pairs are local to the 4-wide col microtile)
//   - elu(x)+1  ( = x+1 for x>0, exp(x) otherwise )
//   - scatter into [b][h][n][d] layout
// Block: 256 threads, 64x64 tile, 4x4 microtile, K-step 16.
// ---------------------------------------------------------------------------
__global__ __launch_bounds__(256) void gemm_qkv_kernel(
    const float* __restrict__ x,
    const float* __restrict__ w,
    const float* __restrict__ bias)
{
    __shared__ __align__(16) float As[16][65];
    __shared__ __align__(16) float Bs[16][68];

    const int tid = threadIdx.x;
    const int tx = tid & 15, ty = tid >> 4;
    const int m0 = blockIdx.y << 6;
    const int n0 = blockIdx.x << 6;

    float acc[4][4] = {};

    const int ar  = tid >> 2;          // 0..63
    const int ac4 = (tid & 3) << 2;    // 0,4,8,12
    const int br  = tid >> 4;          // 0..15
    const int bc4 = (tid & 15) << 2;   // 0..60

    for (int k0 = 0; k0 < CC; k0 += 16) {
        float4 av = *(const float4*)(x + (size_t)(m0 + ar) * CC + k0 + ac4);
        float4 bv = *(const float4*)(w + (size_t)(k0 + br) * W3 + n0 + bc4);
        As[ac4+0][ar] = av.x; As[ac4+1][ar] = av.y;
        As[ac4+2][ar] = av.z; As[ac4+3][ar] = av.w;
        *(float4*)(&Bs[br][bc4]) = bv;
        __syncthreads();
#pragma unroll
        for (int kk = 0; kk < 16; kk++) {
            float a[4], b[4];
#pragma unroll
            for (int i = 0; i < 4; i++) a[i] = As[kk][(ty<<2)+i];
#pragma unroll
            for (int j = 0; j < 4; j++) b[j] = Bs[kk][(tx<<2)+j];
#pragma unroll
            for (int i = 0; i < 4; i++)
#pragma unroll
                for (int j = 0; j < 4; j++)
                    acc[i][j] = fmaf(a[i], b[j], acc[i][j]);
        }
        __syncthreads();
    }

    // --- epilogue ---
    const int sect = n0 >> 9;             // 0=q 1=k 2=v
    const int h    = (n0 & 511) >> 6;     // head (constant per block)
    const int d0   = tx << 2;             // in-head dim 0..60

    float bvals[4];
#pragma unroll
    for (int j = 0; j < 4; j++) bvals[j] = bias[n0 + d0 + j];

#pragma unroll
    for (int i = 0; i < 4; i++) {
        const int r = m0 + (ty<<2) + i;
        const int bidx = r >> 14;          // / 16384
        const int t    = r & (NN-1);
        float val[4];
#pragma unroll
        for (int j = 0; j < 4; j++) val[j] = acc[i][j] + bvals[j];

        if (sect == 2) {
            float* dst = g_v + ((size_t)(bidx*HH + h)*NN + t)*DD + d0;
            *(float4*)dst = make_float4(val[0], val[1], val[2], val[3]);
        } else {
            const float pos_x = (float)(t & 127);   // t % width(128)
            const float pos_y = (float)(t >> 7);    // t / width
            float* dst = (sect == 0 ? g_q : g_k)
                       + ((size_t)(bidx*HH + h)*NN + t)*DD + d0;
            float outv[4];
#pragma unroll
            for (int p = 0; p < 2; p++) {
                const int d  = d0 + 2*p;
                const int fi = (d < 32) ? (d >> 1) : ((d - 32) >> 1);
                const float pos = (d < 32) ? pos_x : pos_y;
                const float freq = exp2f((float)fi * FREQ_COEF);
                float s, c;
                sincosf(pos * freq, &s, &c);
                const float xr = val[2*p], xi = val[2*p+1];
                float orr = xr*c - xi*s;
                float oii = xr*s + xi*c;
                orr = (orr > 0.f) ? (orr + 1.f) : expf(orr);  // elu+1
                oii = (oii > 0.f) ? (oii + 1.f) : expf(oii);
                outv[2*p]   = orr;
                outv[2*p+1] = oii;
            }
            *(float4*)dst = make_float4(outv[0], outv[1], outv[2], outv[3]);
        }
    }
}

// ---------------------------------------------------------------------------
// kv[b,h,d,e] = sum_n k[n,d] v[n,e];  ksum[b,h,d] = sum_n k[n,d]
// grid (32 bh, 64 n-chunks of 256 rows), partial sums + atomicAdd.
// ---------------------------------------------------------------------------
__global__ __launch_bounds__(256) void kv_reduce_kernel() {
    const int bh  = blockIdx.x;
    const int tid = threadIdx.x;
    const int tx = tid & 15, ty = tid >> 4;
    const float* kb = g_k + (size_t)bh * NN * DD;
    const float* vb = g_v + (size_t)bh * NN * DD;
    const int n0 = blockIdx.y * 256;

    __shared__ __align__(16) float kr[8][64];
    __shared__ __align__(16) float vr[8][64];

    float acc[4][4] = {};
    float ks[4] = {};

    const int  lrow = (tid & 127) >> 4;   // 0..7
    const int  lc4  = (tid & 15) << 2;
    const bool isv  = (tid >= 128);
    const float* src = isv ? vb : kb;

    for (int r8 = 0; r8 < 256; r8 += 8) {
        float4 t4 = *(const float4*)(src + (size_t)(n0 + r8 + lrow)*DD + lc4);
        if (isv) *(float4*)&vr[lrow][lc4] = t4;
        else     *(float4*)&kr[lrow][lc4] = t4;
        __syncthreads();
#pragma unroll
        for (int rr = 0; rr < 8; rr++) {
            float a[4], b[4];
#pragma unroll
            for (int i = 0; i < 4; i++) a[i] = kr[rr][(ty<<2)+i];
#pragma unroll
            for (int j = 0; j < 4; j++) b[j] = vr[rr][(tx<<2)+j];
#pragma unroll
            for (int i = 0; i < 4; i++) {
#pragma unroll
                for (int j = 0; j < 4; j++)
                    acc[i][j] = fmaf(a[i], b[j], acc[i][j]);
                ks[i] += a[i];
            }
        }
        __syncthreads();
    }

    float* kvp = g_kv + bh*DD*DD;
#pragma unroll
    for (int i = 0; i < 4; i++)
#pragma unroll
        for (int j = 0; j < 4; j++)
            atomicAdd(&kvp[((ty<<2)+i)*DD + (tx<<2)+j], acc[i][j]);
    if (tx == 0) {
#pragma unroll
        for (int i = 0; i < 4; i++)
            atomicAdd(&g_ksum[bh*DD + (ty<<2)+i], ks[i]);
    }
}

// ---------------------------------------------------------------------------
// attn[b,n,h*64+e] = (sum_d q[n,d] kv[d,e]) / (q[n]·ksum + 1e-6)
// One block per (bh, 256-row chunk). kv tile cached in smem.
// ---------------------------------------------------------------------------
__global__ __launch_bounds__(256) void attn_out_kernel() {
    const int bh = blockIdx.x;
    const int b  = bh >> 3, h = bh & 7;
    const int tid = threadIdx.x;

    __shared__ float kvs[64*64];
    __shared__ float kss[64];
    __shared__ float qs[4][64];

    for (int i = tid; i < 4096; i += 256) kvs[i] = g_kv[bh*4096 + i];
    if (tid < 64) kss[tid] = g_ksum[bh*64 + tid];
    __syncthreads();

    const int n0  = blockIdx.y * 256;
    const int row = tid >> 6;   // 0..3
    const int e   = tid & 63;
    const float* qb = g_q + (size_t)bh * NN * DD;

    for (int rr = 0; rr < 256; rr += 4) {
        const int t = n0 + rr + row;
        qs[row][e] = qb[(size_t)t*DD + e];
        __syncthreads();
        float acc = 0.f, z = 0.f;
#pragma unroll
        for (int dd = 0; dd < 64; dd++) {
            const float qd = qs[row][dd];
            acc = fmaf(qd, kvs[dd*64 + e], acc);
            z   = fmaf(qd, kss[dd], z);
        }
        const float zi = 1.f / (z + 1e-6f);
        g_attn[((size_t)b*NN + t)*CC + h*DD + e] = acc * zi;
        __syncthreads();
    }
}

// ---------------------------------------------------------------------------
// GEMM2: out = attn @ w_proj + b_proj  (65536 x 512 x 512)
// ---------------------------------------------------------------------------
__global__ __launch_bounds__(256) void gemm_proj_kernel(
    const float* __restrict__ w,
    const float* __restrict__ bias,
    float* __restrict__ out)
{
    __shared__ __align__(16) float As[16][65];
    __shared__ __align__(16) float Bs[16][68];

    const int tid = threadIdx.x;
    const int tx = tid & 15, ty = tid >> 4;
    const int m0 = blockIdx.y << 6;
    const int n0 = blockIdx.x << 6;

    float acc[4][4] = {};

    const int ar  = tid >> 2;
    const int ac4 = (tid & 3) << 2;
    const int br  = tid >> 4;
    const int bc4 = (tid & 15) << 2;

    for (int k0 = 0; k0 < CC; k0 += 16) {
        float4 av = *(const float4*)(g_attn + (size_t)(m0 + ar) * CC + k0 + ac4);
        float4 bv = *(const float4*)(w + (size_t)(k0 + br) * CC + n0 + bc4);
        As[ac4+0][ar] = av.x; As[ac4+1][ar] = av.y;
        As[ac4+2][ar] = av.z; As[ac4+3][ar] = av.w;
        *(float4*)(&Bs[br][bc4]) = bv;
        __syncthreads();
#pragma unroll
        for (int kk = 0; kk < 16; kk++) {
            float a[4], b[4];
#pragma unroll
            for (int i = 0; i < 4; i++) a[i] = As[kk][(ty<<2)+i];
#pragma unroll
            for (int j = 0; j < 4; j++) b[j] = Bs[kk][(tx<<2)+j];
#pragma unroll
            for (int i = 0; i < 4; i++)
#pragma unroll
                for (int j = 0; j < 4; j++)
                    acc[i][j] = fmaf(a[i], b[j], acc[i][j]);
        }
        __syncthreads();
    }

    const int d0 = tx << 2;
    float bvals[4];
#pragma unroll
    for (int j = 0; j < 4; j++) bvals[j] = bias[n0 + d0 + j];
#pragma unroll
    for (int i = 0; i < 4; i++) {
        const int r = m0 + (ty<<2) + i;
        *(float4*)(out + (size_t)r*CC + n0 + d0) =
            make_float4(acc[i][0]+bvals[0], acc[i][1]+bvals[1],
                        acc[i][2]+bvals[2], acc[i][3]+bvals[3]);
    }
}

// ---------------------------------------------------------------------------
extern "C" void kernel_launch(void* const* d_in, const int* in_sizes, int n_in,
                              void* d_out, int out_size) {
    const float* x      = (const float*)d_in[0];
    const float* w_qkv  = (const float*)d_in[1];
    const float* b_qkv  = (const float*)d_in[2];
    const float* w_proj = (const float*)d_in[3];
    const float* b_proj = (const float*)d_in[4];
    float* out = (float*)d_out;

    zero_kv_kernel<<<512, 256>>>();
    gemm_qkv_kernel<<<dim3(24, 1024), 256>>>(x, w_qkv, b_qkv);
    kv_reduce_kernel<<<dim3(32, 64), 256>>>();
    attn_out_kernel<<<dim3(32, 64), 256>>>();
    gemm_proj_kernel<<<dim3(8, 1024), 256>>>(w_proj, b_proj, out);
}

// round 2
// speedup vs baseline: 3.6567x; 3.6567x over previous
#include <cuda_runtime.h>
#include <math.h>

// Problem constants (shape-specialized)
#define BB 4
#define NN 16384
#define CC 512
#define HH 8
#define DD 64
#define NT (BB*NN)     // 65536 rows
#define W3 (3*CC)      // 1536

// -log2(10)/16  (freqs_i = 10^{-i/16} = exp2(i * this))
#define FREQ_COEF (-0.20762050593046014f)

// Scratch (device globals: allocation-free rule)
__device__ float g_q[(size_t)BB*HH*NN*DD];
__device__ float g_k[(size_t)BB*HH*NN*DD];
__device__ float g_v[(size_t)BB*HH*NN*DD];
__device__ float g_attn[(size_t)NT*CC];
__device__ float g_kv[BB*HH*DD*DD];
__device__ float g_ksum[BB*HH*DD];
__device__ float g_trig[128*16*2];   // [pos][fi][{cos,sin}]

// ---------------------------------------------------------------------------
// helpers
// ---------------------------------------------------------------------------
__device__ __forceinline__ unsigned f2tf(float f) {
    unsigned u; asm("cvt.rna.tf32.f32 %0, %1;" : "=r"(u) : "f"(f)); return u;
}

__device__ __forceinline__ void mma8(float* c, const unsigned* a, const unsigned* b) {
    asm volatile(
        "mma.sync.aligned.m16n8k8.row.col.f32.tf32.tf32.f32 "
        "{%0,%1,%2,%3},{%4,%5,%6,%7},{%8,%9},{%0,%1,%2,%3};\n"
        : "+f"(c[0]), "+f"(c[1]), "+f"(c[2]), "+f"(c[3])
        : "r"(a[0]), "r"(a[1]), "r"(a[2]), "r"(a[3]), "r"(b[0]), "r"(b[1]));
}

// ---------------------------------------------------------------------------
// init: zero kv/ksum accumulators + build trig table (every launch: graph replays)
// grid 512 x 256 = 131072 threads
// ---------------------------------------------------------------------------
__global__ void init_kernel() {
    int i = blockIdx.x * blockDim.x + threadIdx.x;
    if (i < BB*HH*DD*DD) g_kv[i] = 0.f;
    if (i < BB*HH*DD)    g_ksum[i] = 0.f;
    if (i < 128*16) {
        int pos = i >> 4, fi = i & 15;
        float freq = exp2f((float)fi * FREQ_COEF);
        float s, c;
        sincosf((float)pos * freq, &s, &c);
        g_trig[i*2]   = c;
        g_trig[i*2+1] = s;
    }
}

// ---------------------------------------------------------------------------
// GEMM1: qkv = x @ w_qkv + b_qkv  (65536 x 1536 x 512), tf32 mma
// Block 256 thr, tile 128x128, warp tile 64x32, K stage 32.
// Fused epilogue: RoPE (table) + elu+1, scatter to g_q/g_k/g_v [b][h][n][d].
// ---------------------------------------------------------------------------
__global__ __launch_bounds__(256, 2) void gemm_qkv_kernel(
    const float* __restrict__ x,
    const float* __restrict__ w,
    const float* __restrict__ bias)
{
    __shared__ unsigned As[128][36];   // [m][k], bank-safe stride 36
    __shared__ unsigned Bs[32][136];   // [k][n], bank-safe stride 136

    const int tid  = threadIdx.x;
    const int warp = tid >> 5, lane = tid & 31;
    const int gid  = lane >> 2, tig = lane & 3;
    const int m0 = blockIdx.y << 7, n0 = blockIdx.x << 7;
    const int wm = (warp >> 2) << 6;   // 0 / 64
    const int wn = (warp & 3) << 5;    // 0,32,64,96

    float c[4][4][4];
#pragma unroll
    for (int i = 0; i < 4; i++)
#pragma unroll
        for (int j = 0; j < 4; j++)
#pragma unroll
            for (int r = 0; r < 4; r++) c[i][j][r] = 0.f;

    const int arow = tid >> 3, acol = (tid & 7) << 2;
    const int brow = tid >> 5, bcol = (tid & 31) << 2;

    for (int k0 = 0; k0 < CC; k0 += 32) {
#pragma unroll
        for (int i = 0; i < 4; i++) {
            float4 t = *(const float4*)(x + (size_t)(m0 + arow + 32*i)*CC + k0 + acol);
            uint4 u = make_uint4(f2tf(t.x), f2tf(t.y), f2tf(t.z), f2tf(t.w));
            *(uint4*)&As[arow + 32*i][acol] = u;
        }
#pragma unroll
        for (int i = 0; i < 4; i++) {
            float4 t = *(const float4*)(w + (size_t)(k0 + brow + 8*i)*W3 + n0 + bcol);
            uint4 u = make_uint4(f2tf(t.x), f2tf(t.y), f2tf(t.z), f2tf(t.w));
            *(uint4*)&Bs[brow + 8*i][bcol] = u;
        }
        __syncthreads();
#pragma unroll
        for (int kk = 0; kk < 32; kk += 8) {
            unsigned a[4][4], b[4][2];
#pragma unroll
            for (int mf = 0; mf < 4; mf++) {
                const int r = wm + mf*16 + gid;
                a[mf][0] = As[r][kk+tig];
                a[mf][1] = As[r+8][kk+tig];
                a[mf][2] = As[r][kk+tig+4];
                a[mf][3] = As[r+8][kk+tig+4];
            }
#pragma unroll
            for (int nf = 0; nf < 4; nf++) {
                const int cc = wn + nf*8 + gid;
                b[nf][0] = Bs[kk+tig][cc];
                b[nf][1] = Bs[kk+tig+4][cc];
            }
#pragma unroll
            for (int mf = 0; mf < 4; mf++)
#pragma unroll
                for (int nf = 0; nf < 4; nf++)
                    mma8(c[mf][nf], a[mf], b[nf]);
        }
        __syncthreads();
    }

    // --- epilogue ---
    const int sect = n0 >> 9;             // 0=q 1=k 2=v (block never straddles)
#pragma unroll
    for (int nf = 0; nf < 4; nf++) {
        const int col = n0 + wn + nf*8 + 2*tig;   // even
        const int h   = (col >> 6) & 7;
        const int d   = col & 63;
        const float b0v = bias[col], b1v = bias[col+1];
        const int  fi  = (d & 31) >> 1;
        const bool axx = (d < 32);
#pragma unroll
        for (int mf = 0; mf < 4; mf++) {
#pragma unroll
            for (int hf = 0; hf < 2; hf++) {
                const int r    = m0 + wm + mf*16 + gid + 8*hf;
                const int bidx = r >> 14;
                const int t    = r & (NN-1);
                float v0 = c[mf][nf][2*hf]   + b0v;
                float v1 = c[mf][nf][2*hf+1] + b1v;
                const size_t base = ((size_t)(bidx*HH + h)*NN + t)*DD + d;
                if (sect == 2) {
                    *(float2*)(g_v + base) = make_float2(v0, v1);
                } else {
                    const int pos = axx ? (t & 127) : (t >> 7);
                    const float2 cs = *(const float2*)(g_trig + ((pos << 4) + fi)*2);
                    float orr = v0*cs.x - v1*cs.y;
                    float oii = v0*cs.y + v1*cs.x;
                    orr = (orr > 0.f) ? orr + 1.f : __expf(orr);   // elu+1
                    oii = (oii > 0.f) ? oii + 1.f : __expf(oii);
                    float* dst = (sect == 0) ? g_q : g_k;
                    *(float2*)(dst + base) = make_float2(orr, oii);
                }
            }
        }
    }
}

// ---------------------------------------------------------------------------
// kv[b,h,d,e] = sum_n k[n,d] v[n,e];  ksum via ones-column (col 64 of V tile).
// grid (32 bh, 16 k-chunks of 1024), block 256 (4 e-warps x 2 k-slices).
// tf32 mma, A = k^T via smem transpose. atomicAdd fp32 accumulation.
// ---------------------------------------------------------------------------
__global__ __launch_bounds__(256, 2) void kv_mma_kernel() {
    __shared__ unsigned Ks[64][68];   // [d][n]
    __shared__ unsigned Vs[64][72];   // [n][e], col 64 = 1.0, 65-71 = 0

    const int tid  = threadIdx.x;
    const int warp = tid >> 5, lane = tid & 31;
    const int gid  = lane >> 2, tig = lane & 3;
    const int bh    = blockIdx.x;
    const int nbase = blockIdx.y << 10;
    const int wn  = (warp & 3) << 4;   // 0,16,32,48
    const int ksl = (warp >> 2) << 5;  // 0 / 32

    float c[4][2][4], cx[4][4];
#pragma unroll
    for (int i = 0; i < 4; i++) {
#pragma unroll
        for (int j = 0; j < 2; j++)
#pragma unroll
            for (int r = 0; r < 4; r++) c[i][j][r] = 0.f;
#pragma unroll
        for (int r = 0; r < 4; r++) cx[i][r] = 0.f;
    }

    if (tid < 64) {
        Vs[tid][64] = 0x3F800000u;   // tf32(1.0)
#pragma unroll
        for (int j = 65; j < 72; j++) Vs[tid][j] = 0u;
    }

    const float* kb = g_k + (size_t)bh*NN*DD;
    const float* vb = g_v + (size_t)bh*NN*DD;

    for (int s = 0; s < 16; s++) {
        const int n0 = nbase + s*64;
        {   // K transpose load
            const int n  = tid & 63;
            const int db = (tid >> 6) << 2;
#pragma unroll
            for (int i = 0; i < 4; i++) {
                const int d4 = db + i*16;
                float4 t = *(const float4*)(kb + (size_t)(n0 + n)*DD + d4);
                Ks[d4+0][n] = f2tf(t.x);
                Ks[d4+1][n] = f2tf(t.y);
                Ks[d4+2][n] = f2tf(t.z);
                Ks[d4+3][n] = f2tf(t.w);
            }
        }
        {   // V load
            const int n  = tid >> 2;
            const int eb = (tid & 3) << 2;
#pragma unroll
            for (int i = 0; i < 4; i++) {
                const int e4 = eb + i*16;
                float4 t = *(const float4*)(vb + (size_t)(n0 + n)*DD + e4);
                uint4 u = make_uint4(f2tf(t.x), f2tf(t.y), f2tf(t.z), f2tf(t.w));
                *(uint4*)&Vs[n][e4] = u;
            }
        }
        __syncthreads();
#pragma unroll
        for (int kk2 = 0; kk2 < 32; kk2 += 8) {
            const int kk = ksl + kk2;
            unsigned a[4][4], b[2][2], bx[2];
#pragma unroll
            for (int mf = 0; mf < 4; mf++) {
                const int r = mf*16 + gid;
                a[mf][0] = Ks[r][kk+tig];
                a[mf][1] = Ks[r+8][kk+tig];
                a[mf][2] = Ks[r][kk+tig+4];
                a[mf][3] = Ks[r+8][kk+tig+4];
            }
#pragma unroll
            for (int nf = 0; nf < 2; nf++) {
                const int e = wn + nf*8 + gid;
                b[nf][0] = Vs[kk+tig][e];
                b[nf][1] = Vs[kk+tig+4][e];
            }
            if (wn == 0) { bx[0] = Vs[kk+tig][64+gid]; bx[1] = Vs[kk+tig+4][64+gid]; }
#pragma unroll
            for (int mf = 0; mf < 4; mf++) {
#pragma unroll
                for (int nf = 0; nf < 2; nf++) mma8(c[mf][nf], a[mf], b[nf]);
                if (wn == 0) mma8(cx[mf], a[mf], bx);
            }
        }
        __syncthreads();
    }

    float* kvp = g_kv + bh*DD*DD;
#pragma unroll
    for (int mf = 0; mf < 4; mf++)
#pragma unroll
        for (int nf = 0; nf < 2; nf++) {
            const int e = wn + nf*8 + 2*tig;
#pragma unroll
            for (int hf = 0; hf < 2; hf++) {
                const int dd = mf*16 + gid + 8*hf;
                atomicAdd(&kvp[dd*DD + e],     c[mf][nf][2*hf]);
                atomicAdd(&kvp[dd*DD + e + 1], c[mf][nf][2*hf+1]);
            }
        }
    if (wn == 0 && tig == 0) {
#pragma unroll
        for (int mf = 0; mf < 4; mf++)
#pragma unroll
            for (int hf = 0; hf < 2; hf++)
                atomicAdd(&g_ksum[bh*DD + mf*16 + gid + 8*hf], cx[mf][2*hf]);
    }
}

// ---------------------------------------------------------------------------
// attn[b,n,h*64+e] = (q @ kv)[n,e] * zinv[n];  z via ksum appended at col 64.
// grid (32 bh, 256 row-chunks of 64), block 256 (4 m-warps x 2 n-warps).
// ---------------------------------------------------------------------------
__global__ __launch_bounds__(256) void attn_mma_kernel() {
    __shared__ unsigned Qs[64][68];    // [n][d]
    __shared__ unsigned KVs[64][72];   // [d][e], col 64 = ksum[d]
    __shared__ float zbuf[64];

    const int tid  = threadIdx.x;
    const int warp = tid >> 5, lane = tid & 31;
    const int gid  = lane >> 2, tig = lane & 3;
    const int bh = blockIdx.x, b = bh >> 3, h = bh & 7;
    const int n0 = blockIdx.y << 6;
    const int wm = (warp >> 1) << 4;   // 0,16,32,48
    const int wn = (warp & 1) << 5;    // 0,32

    {   // kv tile
        const int d  = tid >> 2;
        const int eb = (tid & 3) << 2;
        const float* kvp = g_kv + bh*DD*DD;
#pragma unroll
        for (int i = 0; i < 4; i++) {
            const int e4 = eb + i*16;
            float4 t = *(const float4*)(kvp + d*DD + e4);
            uint4 u = make_uint4(f2tf(t.x), f2tf(t.y), f2tf(t.z), f2tf(t.w));
            *(uint4*)&KVs[d][e4] = u;
        }
    }
    if (tid < 64) {
        KVs[tid][64] = f2tf(g_ksum[bh*DD + tid]);
#pragma unroll
        for (int j = 65; j < 72; j++) KVs[tid][j] = 0u;
    }
    {   // q tile
        const int r  = tid >> 2;
        const int db = (tid & 3) << 2;
        const float* qb = g_q + ((size_t)bh*NN + n0)*DD;
#pragma unroll
        for (int i = 0; i < 4; i++) {
            const int d4 = db + i*16;
            float4 t = *(const float4*)(qb + (size_t)r*DD + d4);
            uint4 u = make_uint4(f2tf(t.x), f2tf(t.y), f2tf(t.z), f2tf(t.w));
            *(uint4*)&Qs[r][d4] = u;
        }
    }
    __syncthreads();

    float c[4][4], cz[4];
#pragma unroll
    for (int j = 0; j < 4; j++) {
#pragma unroll
        for (int r = 0; r < 4; r++) c[j][r] = 0.f;
        cz[j] = 0.f;
    }

#pragma unroll
    for (int kk = 0; kk < 64; kk += 8) {
        unsigned a[4], bfr[4][2], bz[2];
        const int r = wm + gid;
        a[0] = Qs[r][kk+tig];
        a[1] = Qs[r+8][kk+tig];
        a[2] = Qs[r][kk+tig+4];
        a[3] = Qs[r+8][kk+tig+4];
#pragma unroll
        for (int nf = 0; nf < 4; nf++) {
            const int e = wn + nf*8 + gid;
            bfr[nf][0] = KVs[kk+tig][e];
            bfr[nf][1] = KVs[kk+tig+4][e];
        }
        if (wn) { bz[0] = KVs[kk+tig][64+gid]; bz[1] = KVs[kk+tig+4][64+gid]; }
#pragma unroll
        for (int nf = 0; nf < 4; nf++) mma8(c[nf], a, bfr[nf]);
        if (wn) mma8(cz, a, bz);
    }
    if (wn && tig == 0) {
        zbuf[wm + gid]     = 1.f/(cz[0] + 1e-6f);
        zbuf[wm + gid + 8] = 1.f/(cz[2] + 1e-6f);
    }
    __syncthreads();

    float* ob = g_attn + ((size_t)b*NN + n0)*CC + h*DD;
#pragma unroll
    for (int nf = 0; nf < 4; nf++) {
        const int e = wn + nf*8 + 2*tig;
#pragma unroll
        for (int hf = 0; hf < 2; hf++) {
            const int row = wm + gid + 8*hf;
            const float zi = zbuf[row];
            *(float2*)(ob + (size_t)row*CC + e) =
                make_float2(c[nf][2*hf]*zi, c[nf][2*hf+1]*zi);
        }
    }
}

// ---------------------------------------------------------------------------
// GEMM2: out = attn @ w_proj + b_proj  (65536 x 512 x 512), tf32 mma
// ---------------------------------------------------------------------------
__global__ __launch_bounds__(256, 2) void gemm_proj_kernel(
    const float* __restrict__ w,
    const float* __restrict__ bias,
    float* __restrict__ out)
{
    __shared__ unsigned As[128][36];
    __shared__ unsigned Bs[32][136];

    const int tid  = threadIdx.x;
    const int warp = tid >> 5, lane = tid & 31;
    const int gid  = lane >> 2, tig = lane & 3;
    const int m0 = blockIdx.y << 7, n0 = blockIdx.x << 7;
    const int wm = (warp >> 2) << 6;
    const int wn = (warp & 3) << 5;

    float c[4][4][4];
#pragma unroll
    for (int i = 0; i < 4; i++)
#pragma unroll
        for (int j = 0; j < 4; j++)
#pragma unroll
            for (int r = 0; r < 4; r++) c[i][j][r] = 0.f;

    const int arow = tid >> 3, acol = (tid & 7) << 2;
    const int brow = tid >> 5, bcol = (tid & 31) << 2;

    for (int k0 = 0; k0 < CC; k0 += 32) {
#pragma unroll
        for (int i = 0; i < 4; i++) {
            float4 t = *(const float4*)(g_attn + (size_t)(m0 + arow + 32*i)*CC + k0 + acol);
            uint4 u = make_uint4(f2tf(t.x), f2tf(t.y), f2tf(t.z), f2tf(t.w));
            *(uint4*)&As[arow + 32*i][acol] = u;
        }
#pragma unroll
        for (int i = 0; i < 4; i++) {
            float4 t = *(const float4*)(w + (size_t)(k0 + brow + 8*i)*CC + n0 + bcol);
            uint4 u = make_uint4(f2tf(t.x), f2tf(t.y), f2tf(t.z), f2tf(t.w));
            *(uint4*)&Bs[brow + 8*i][bcol] = u;
        }
        __syncthreads();
#pragma unroll
        for (int kk = 0; kk < 32; kk += 8) {
            unsigned a[4][4], b[4][2];
#pragma unroll
            for (int mf = 0; mf < 4; mf++) {
                const int r = wm + mf*16 + gid;
                a[mf][0] = As[r][kk+tig];
                a[mf][1] = As[r+8][kk+tig];
                a[mf][2] = As[r][kk+tig+4];
                a[mf][3] = As[r+8][kk+tig+4];
            }
#pragma unroll
            for (int nf = 0; nf < 4; nf++) {
                const int cc = wn + nf*8 + gid;
                b[nf][0] = Bs[kk+tig][cc];
                b[nf][1] = Bs[kk+tig+4][cc];
            }
#pragma unroll
            for (int mf = 0; mf < 4; mf++)
#pragma unroll
                for (int nf = 0; nf < 4; nf++)
                    mma8(c[mf][nf], a[mf], b[nf]);
        }
        __syncthreads();
    }

#pragma unroll
    for (int nf = 0; nf < 4; nf++) {
        const int col = n0 + wn + nf*8 + 2*tig;
        const float b0v = bias[col], b1v = bias[col+1];
#pragma unroll
        for (int mf = 0; mf < 4; mf++) {
#pragma unroll
            for (int hf = 0; hf < 2; hf++) {
                const int r = m0 + wm + mf*16 + gid + 8*hf;
                *(float2*)(out + (size_t)r*CC + col) =
                    make_float2(c[mf][nf][2*hf] + b0v, c[mf][nf][2*hf+1] + b1v);
            }
        }
    }
}

// ---------------------------------------------------------------------------
extern "C" void kernel_launch(void* const* d_in, const int* in_sizes, int n_in,
                              void* d_out, int out_size) {
    const float* x      = (const float*)d_in[0];
    const float* w_qkv  = (const float*)d_in[1];
    const float* b_qkv  = (const float*)d_in[2];
    const float* w_proj = (const float*)d_in[3];
    const float* b_proj = (const float*)d_in[4];
    float* out = (float*)d_out;

    init_kernel<<<512, 256>>>();
    gemm_qkv_kernel<<<dim3(12, 512), 256>>>(x, w_qkv, b_qkv);
    kv_mma_kernel<<<dim3(32, 16), 256>>>();
    attn_mma_kernel<<<dim3(32, 256), 256>>>();
    gemm_proj_kernel<<<dim3(4, 512), 256>>>(w_proj, b_proj, out);
}

// round 4
// speedup vs baseline: 4.6472x; 1.2709x over previous
#include <cuda_runtime.h>
#include <cuda_fp16.h>
#include <math.h>
#include <stdint.h>

// Problem constants (shape-specialized)
#define BB 4
#define NN 16384
#define CC 512
#define HH 8
#define DD 64
#define NT (BB*NN)     // 65536 rows
#define W3 (3*CC)      // 1536

// -log2(10)/16  (freqs_i = 10^{-i/16} = exp2(i * this))
#define FREQ_COEF (-0.20762050593046014f)

// Scratch (device globals: allocation-free rule)
__device__ float  g_q[(size_t)BB*HH*NN*DD];
__device__ float  g_k[(size_t)BB*HH*NN*DD];
__device__ float  g_v[(size_t)BB*HH*NN*DD];
__device__ __half g_attn[(size_t)NT*CC];
__device__ float  g_kv[BB*HH*DD*DD];
__device__ float  g_ksum[BB*HH*DD];
__device__ float  g_trig[128*16*2];      // [pos][fi][{cos,sin}]
__device__ __half g_wt1[(size_t)W3*CC];  // w_qkv^T  [n][k] half
__device__ __half g_wt2[(size_t)CC*CC];  // w_proj^T [n][k] half

// ---------------------------------------------------------------------------
// helpers
// ---------------------------------------------------------------------------
__device__ __forceinline__ unsigned f2tf(float f) {
    unsigned u; asm("cvt.rna.tf32.f32 %0, %1;" : "=r"(u) : "f"(f)); return u;
}

// fp16 mma m16n8k16, fp32 accumulate
__device__ __forceinline__ void mma16(float* c, const unsigned* a, const unsigned* b) {
    asm volatile(
        "mma.sync.aligned.m16n8k16.row.col.f32.f16.f16.f32 "
        "{%0,%1,%2,%3},{%4,%5,%6,%7},{%8,%9},{%0,%1,%2,%3};\n"
        : "+f"(c[0]), "+f"(c[1]), "+f"(c[2]), "+f"(c[3])
        : "r"(a[0]), "r"(a[1]), "r"(a[2]), "r"(a[3]), "r"(b[0]), "r"(b[1]));
}

// tf32 mma m16n8k8 (kv / attn kernels)
__device__ __forceinline__ void mma8(float* c, const unsigned* a, const unsigned* b) {
    asm volatile(
        "mma.sync.aligned.m16n8k8.row.col.f32.tf32.tf32.f32 "
        "{%0,%1,%2,%3},{%4,%5,%6,%7},{%8,%9},{%0,%1,%2,%3};\n"
        : "+f"(c[0]), "+f"(c[1]), "+f"(c[2]), "+f"(c[3])
        : "r"(a[0]), "r"(a[1]), "r"(a[2]), "r"(a[3]), "r"(b[0]), "r"(b[1]));
}

__device__ __forceinline__ unsigned pack_h2(float a, float b) {
    __half2 h = __floats2half2_rn(a, b);
    return *(unsigned*)&h;
}

// ---------------------------------------------------------------------------
// init: zero kv/ksum + trig table (runs every launch: graph replays)
// ---------------------------------------------------------------------------
__global__ void init_kernel() {
    int i = blockIdx.x * blockDim.x + threadIdx.x;
    if (i < BB*HH*DD*DD) g_kv[i] = 0.f;
    if (i < BB*HH*DD)    g_ksum[i] = 0.f;
    if (i < 128*16) {
        int pos = i >> 4, fi = i & 15;
        float freq = exp2f((float)fi * FREQ_COEF);
        float s, c;
        sincosf((float)pos * freq, &s, &c);
        g_trig[i*2]   = c;
        g_trig[i*2+1] = s;
    }
}

// ---------------------------------------------------------------------------
// Transpose weights to K-major half: src fp32 [512][N] -> dst half [N][512]
// ---------------------------------------------------------------------------
__global__ void transpose_w_kernel(const float* __restrict__ src,
                                   __half* __restrict__ dst, int N) {
    __shared__ float tile[32][33];
    const int k0 = blockIdx.y << 5, n0 = blockIdx.x << 5;
    const int tx = threadIdx.x, ty = threadIdx.y;   // 32 x 8
#pragma unroll
    for (int i = 0; i < 32; i += 8)
        tile[ty+i][tx] = src[(size_t)(k0+ty+i)*N + n0 + tx];
    __syncthreads();
#pragma unroll
    for (int i = 0; i < 32; i += 8)
        dst[(size_t)(n0+ty+i)*CC + k0 + tx] = __float2half_rn(tile[tx][ty+i]);
}

// ---------------------------------------------------------------------------
// GEMM1 (fp16 mma): qkv = x @ w_qkv + b_qkv, fused RoPE + elu+1 epilogue.
// Block 256, tile 128x128, warp tile 64x32, K stage 32, m16n8k16.
// smem: half [row][40] padded — conflict-free fragment LDS.
// ---------------------------------------------------------------------------
__global__ __launch_bounds__(256, 2) void gemm_qkv_kernel(
    const float* __restrict__ x,
    const float* __restrict__ bias)
{
    __shared__ __align__(16) __half As[128][40];   // [m][k]
    __shared__ __align__(16) __half Bs[128][40];   // [n][k]

    const int tid  = threadIdx.x;
    const int warp = tid >> 5, lane = tid & 31;
    const int gid  = lane >> 2, tig = lane & 3;
    const int m0 = blockIdx.y << 7, n0 = blockIdx.x << 7;
    const int wm = (warp >> 2) << 6;   // 0 / 64
    const int wn = (warp & 3) << 5;    // 0,32,64,96

    float c[4][4][4];
#pragma unroll
    for (int i = 0; i < 4; i++)
#pragma unroll
        for (int j = 0; j < 4; j++)
#pragma unroll
            for (int r = 0; r < 4; r++) c[i][j][r] = 0.f;

    const int lrow = tid >> 3;          // 0..31
    const int lc4  = (tid & 7) << 2;    // 0..28 step 4

    for (int k0 = 0; k0 < CC; k0 += 32) {
#pragma unroll
        for (int i = 0; i < 4; i++) {
            float4 t = *(const float4*)(x + (size_t)(m0 + lrow + 32*i)*CC + k0 + lc4);
            *(uint2*)&As[lrow + 32*i][lc4] =
                make_uint2(pack_h2(t.x, t.y), pack_h2(t.z, t.w));
        }
#pragma unroll
        for (int i = 0; i < 4; i++) {
            uint2 u = *(const uint2*)(g_wt1 + (size_t)(n0 + lrow + 32*i)*CC + k0 + lc4);
            *(uint2*)&Bs[lrow + 32*i][lc4] = u;
        }
        __syncthreads();
#pragma unroll
        for (int kk = 0; kk < 32; kk += 16) {
            unsigned a[4][4], b[4][2];
#pragma unroll
            for (int mf = 0; mf < 4; mf++) {
                const int r = wm + mf*16 + gid;
                a[mf][0] = *(const unsigned*)&As[r][kk + 2*tig];
                a[mf][1] = *(const unsigned*)&As[r+8][kk + 2*tig];
                a[mf][2] = *(const unsigned*)&As[r][kk + 8 + 2*tig];
                a[mf][3] = *(const unsigned*)&As[r+8][kk + 8 + 2*tig];
            }
#pragma unroll
            for (int nf = 0; nf < 4; nf++) {
                const int cc = wn + nf*8 + gid;
                b[nf][0] = *(const unsigned*)&Bs[cc][kk + 2*tig];
                b[nf][1] = *(const unsigned*)&Bs[cc][kk + 8 + 2*tig];
            }
#pragma unroll
            for (int mf = 0; mf < 4; mf++)
#pragma unroll
                for (int nf = 0; nf < 4; nf++)
                    mma16(c[mf][nf], a[mf], b[nf]);
        }
        __syncthreads();
    }

    // --- epilogue: RoPE + elu+1, scatter to g_q/g_k/g_v [b][h][n][d] ---
    const int sect = n0 >> 9;             // 0=q 1=k 2=v (block never straddles)
#pragma unroll
    for (int nf = 0; nf < 4; nf++) {
        const int col = n0 + wn + nf*8 + 2*tig;   // even
        const int h   = (col >> 6) & 7;
        const int d   = col & 63;
        const float b0v = bias[col], b1v = bias[col+1];
        const int  fi  = (d & 31) >> 1;
        const bool axx = (d < 32);
#pragma unroll
        for (int mf = 0; mf < 4; mf++) {
#pragma unroll
            for (int hf = 0; hf < 2; hf++) {
                const int r    = m0 + wm + mf*16 + gid + 8*hf;
                const int bidx = r >> 14;
                const int t    = r & (NN-1);
                float v0 = c[mf][nf][2*hf]   + b0v;
                float v1 = c[mf][nf][2*hf+1] + b1v;
                const size_t base = ((size_t)(bidx*HH + h)*NN + t)*DD + d;
                if (sect == 2) {
                    *(float2*)(g_v + base) = make_float2(v0, v1);
                } else {
                    const int pos = axx ? (t & 127) : (t >> 7);
                    const float2 cs = *(const float2*)(g_trig + ((pos << 4) + fi)*2);
                    float orr = v0*cs.x - v1*cs.y;
                    float oii = v0*cs.y + v1*cs.x;
                    orr = (orr > 0.f) ? orr + 1.f : __expf(orr);   // elu+1
                    oii = (oii > 0.f) ? oii + 1.f : __expf(oii);
                    float* dst = (sect == 0) ? g_q : g_k;
                    *(float2*)(dst + base) = make_float2(orr, oii);
                }
            }
        }
    }
}

// ---------------------------------------------------------------------------
// kv[b,h,d,e] = sum_n k[n,d] v[n,e];  ksum via ones-column. tf32 mma.
// ---------------------------------------------------------------------------
__global__ __launch_bounds__(256, 2) void kv_mma_kernel() {
    __shared__ unsigned Ks[64][68];   // [d][n]
    __shared__ unsigned Vs[64][72];   // [n][e], col 64 = 1.0

    const int tid  = threadIdx.x;
    const int warp = tid >> 5, lane = tid & 31;
    const int gid  = lane >> 2, tig = lane & 3;
    const int bh    = blockIdx.x;
    const int nbase = blockIdx.y << 10;
    const int wn  = (warp & 3) << 4;
    const int ksl = (warp >> 2) << 5;

    float c[4][2][4], cx[4][4];
#pragma unroll
    for (int i = 0; i < 4; i++) {
#pragma unroll
        for (int j = 0; j < 2; j++)
#pragma unroll
            for (int r = 0; r < 4; r++) c[i][j][r] = 0.f;
#pragma unroll
        for (int r = 0; r < 4; r++) cx[i][r] = 0.f;
    }

    if (tid < 64) {
        Vs[tid][64] = 0x3F800000u;
#pragma unroll
        for (int j = 65; j < 72; j++) Vs[tid][j] = 0u;
    }

    const float* kb = g_k + (size_t)bh*NN*DD;
    const float* vb = g_v + (size_t)bh*NN*DD;

    for (int s = 0; s < 16; s++) {
        const int n0 = nbase + s*64;
        {
            const int n  = tid & 63;
            const int db = (tid >> 6) << 2;
#pragma unroll
            for (int i = 0; i < 4; i++) {
                const int d4 = db + i*16;
                float4 t = *(const float4*)(kb + (size_t)(n0 + n)*DD + d4);
                Ks[d4+0][n] = f2tf(t.x);
                Ks[d4+1][n] = f2tf(t.y);
                Ks[d4+2][n] = f2tf(t.z);
                Ks[d4+3][n] = f2tf(t.w);
            }
        }
        {
            const int n  = tid >> 2;
            const int eb = (tid & 3) << 2;
#pragma unroll
            for (int i = 0; i < 4; i++) {
                const int e4 = eb + i*16;
                float4 t = *(const float4*)(vb + (size_t)(n0 + n)*DD + e4);
                *(uint4*)&Vs[n][e4] =
                    make_uint4(f2tf(t.x), f2tf(t.y), f2tf(t.z), f2tf(t.w));
            }
        }
        __syncthreads();
#pragma unroll
        for (int kk2 = 0; kk2 < 32; kk2 += 8) {
            const int kk = ksl + kk2;
            unsigned a[4][4], b[2][2], bx[2];
#pragma unroll
            for (int mf = 0; mf < 4; mf++) {
                const int r = mf*16 + gid;
                a[mf][0] = Ks[r][kk+tig];
                a[mf][1] = Ks[r+8][kk+tig];
                a[mf][2] = Ks[r][kk+tig+4];
                a[mf][3] = Ks[r+8][kk+tig+4];
            }
#pragma unroll
            for (int nf = 0; nf < 2; nf++) {
                const int e = wn + nf*8 + gid;
                b[nf][0] = Vs[kk+tig][e];
                b[nf][1] = Vs[kk+tig+4][e];
            }
            if (wn == 0) { bx[0] = Vs[kk+tig][64+gid]; bx[1] = Vs[kk+tig+4][64+gid]; }
#pragma unroll
            for (int mf = 0; mf < 4; mf++) {
#pragma unroll
                for (int nf = 0; nf < 2; nf++) mma8(c[mf][nf], a[mf], b[nf]);
                if (wn == 0) mma8(cx[mf], a[mf], bx);
            }
        }
        __syncthreads();
    }

    float* kvp = g_kv + bh*DD*DD;
#pragma unroll
    for (int mf = 0; mf < 4; mf++)
#pragma unroll
        for (int nf = 0; nf < 2; nf++) {
            const int e = wn + nf*8 + 2*tig;
#pragma unroll
            for (int hf = 0; hf < 2; hf++) {
                const int dd = mf*16 + gid + 8*hf;
                atomicAdd(&kvp[dd*DD + e],     c[mf][nf][2*hf]);
                atomicAdd(&kvp[dd*DD + e + 1], c[mf][nf][2*hf+1]);
            }
        }
    if (wn == 0 && tig == 0) {
#pragma unroll
        for (int mf = 0; mf < 4; mf++)
#pragma unroll
            for (int hf = 0; hf < 2; hf++)
                atomicAdd(&g_ksum[bh*DD + mf*16 + gid + 8*hf], cx[mf][2*hf]);
    }
}

// ---------------------------------------------------------------------------
// attn = (q @ kv) * zinv  (tf32 mma); writes g_attn as half.
// ---------------------------------------------------------------------------
__global__ __launch_bounds__(256) void attn_mma_kernel() {
    __shared__ unsigned Qs[64][68];
    __shared__ unsigned KVs[64][72];
    __shared__ float zbuf[64];

    const int tid  = threadIdx.x;
    const int warp = tid >> 5, lane = tid & 31;
    const int gid  = lane >> 2, tig = lane & 3;
    const int bh = blockIdx.x, b = bh >> 3, h = bh & 7;
    const int n0 = blockIdx.y << 6;
    const int wm = (warp >> 1) << 4;
    const int wn = (warp & 1) << 5;

    {
        const int d  = tid >> 2;
        const int eb = (tid & 3) << 2;
        const float* kvp = g_kv + bh*DD*DD;
#pragma unroll
        for (int i = 0; i < 4; i++) {
            const int e4 = eb + i*16;
            float4 t = *(const float4*)(kvp + d*DD + e4);
            *(uint4*)&KVs[d][e4] =
                make_uint4(f2tf(t.x), f2tf(t.y), f2tf(t.z), f2tf(t.w));
        }
    }
    if (tid < 64) {
        KVs[tid][64] = f2tf(g_ksum[bh*DD + tid]);
#pragma unroll
        for (int j = 65; j < 72; j++) KVs[tid][j] = 0u;
    }
    {
        const int r  = tid >> 2;
        const int db = (tid & 3) << 2;
        const float* qb = g_q + ((size_t)bh*NN + n0)*DD;
#pragma unroll
        for (int i = 0; i < 4; i++) {
            const int d4 = db + i*16;
            float4 t = *(const float4*)(qb + (size_t)r*DD + d4);
            *(uint4*)&Qs[r][d4] =
                make_uint4(f2tf(t.x), f2tf(t.y), f2tf(t.z), f2tf(t.w));
        }
    }
    __syncthreads();

    float c[4][4], cz[4];
#pragma unroll
    for (int j = 0; j < 4; j++) {
#pragma unroll
        for (int r = 0; r < 4; r++) c[j][r] = 0.f;
        cz[j] = 0.f;
    }

#pragma unroll
    for (int kk = 0; kk < 64; kk += 8) {
        unsigned a[4], bfr[4][2], bz[2];
        const int r = wm + gid;
        a[0] = Qs[r][kk+tig];
        a[1] = Qs[r+8][kk+tig];
        a[2] = Qs[r][kk+tig+4];
        a[3] = Qs[r+8][kk+tig+4];
#pragma unroll
        for (int nf = 0; nf < 4; nf++) {
            const int e = wn + nf*8 + gid;
            bfr[nf][0] = KVs[kk+tig][e];
            bfr[nf][1] = KVs[kk+tig+4][e];
        }
        if (wn) { bz[0] = KVs[kk+tig][64+gid]; bz[1] = KVs[kk+tig+4][64+gid]; }
#pragma unroll
        for (int nf = 0; nf < 4; nf++) mma8(c[nf], a, bfr[nf]);
        if (wn) mma8(cz, a, bz);
    }
    if (wn && tig == 0) {
        zbuf[wm + gid]     = 1.f/(cz[0] + 1e-6f);
        zbuf[wm + gid + 8] = 1.f/(cz[2] + 1e-6f);
    }
    __syncthreads();

    __half* ob = g_attn + ((size_t)b*NN + n0)*CC + h*DD;
#pragma unroll
    for (int nf = 0; nf < 4; nf++) {
        const int e = wn + nf*8 + 2*tig;
#pragma unroll
        for (int hf = 0; hf < 2; hf++) {
            const int row = wm + gid + 8*hf;
            const float zi = zbuf[row];
            *(__half2*)(ob + (size_t)row*CC + e) =
                __floats2half2_rn(c[nf][2*hf]*zi, c[nf][2*hf+1]*zi);
        }
    }
}

// ---------------------------------------------------------------------------
// GEMM2 (fp16 mma): out = attn @ w_proj + b_proj  (65536 x 512 x 512)
// attn is already half — direct uint2 loads.
// ---------------------------------------------------------------------------
__global__ __launch_bounds__(256, 2) void gemm_proj_kernel(
    const float* __restrict__ bias,
    float* __restrict__ out)
{
    __shared__ __align__(16) __half As[128][40];
    __shared__ __align__(16) __half Bs[128][40];

    const int tid  = threadIdx.x;
    const int warp = tid >> 5, lane = tid & 31;
    const int gid  = lane >> 2, tig = lane & 3;
    const int m0 = blockIdx.y << 7, n0 = blockIdx.x << 7;
    const int wm = (warp >> 2) << 6;
    const int wn = (warp & 3) << 5;

    float c[4][4][4];
#pragma unroll
    for (int i = 0; i < 4; i++)
#pragma unroll
        for (int j = 0; j < 4; j++)
#pragma unroll
            for (int r = 0; r < 4; r++) c[i][j][r] = 0.f;

    const int lrow = tid >> 3;
    const int lc4  = (tid & 7) << 2;

    for (int k0 = 0; k0 < CC; k0 += 32) {
#pragma unroll
        for (int i = 0; i < 4; i++) {
            uint2 u = *(const uint2*)(g_attn + (size_t)(m0 + lrow + 32*i)*CC + k0 + lc4);
            *(uint2*)&As[lrow + 32*i][lc4] = u;
        }
#pragma unroll
        for (int i = 0; i < 4; i++) {
            uint2 u = *(const uint2*)(g_wt2 + (size_t)(n0 + lrow + 32*i)*CC + k0 + lc4);
            *(uint2*)&Bs[lrow + 32*i][lc4] = u;
        }
        __syncthreads();
#pragma unroll
        for (int kk = 0; kk < 32; kk += 16) {
            unsigned a[4][4], b[4][2];
#pragma unroll
            for (int mf = 0; mf < 4; mf++) {
                const int r = wm + mf*16 + gid;
                a[mf][0] = *(const unsigned*)&As[r][kk + 2*tig];
                a[mf][1] = *(const unsigned*)&As[r+8][kk + 2*tig];
                a[mf][2] = *(const unsigned*)&As[r][kk + 8 + 2*tig];
                a[mf][3] = *(const unsigned*)&As[r+8][kk + 8 + 2*tig];
            }
#pragma unroll
            for (int nf = 0; nf < 4; nf++) {
                const int cc = wn + nf*8 + gid;
                b[nf][0] = *(const unsigned*)&Bs[cc][kk + 2*tig];
                b[nf][1] = *(const unsigned*)&Bs[cc][kk + 8 + 2*tig];
            }
#pragma unroll
            for (int mf = 0; mf < 4; mf++)
#pragma unroll
                for (int nf = 0; nf < 4; nf++)
                    mma16(c[mf][nf], a[mf], b[nf]);
        }
        __syncthreads();
    }

#pragma unroll
    for (int nf = 0; nf < 4; nf++) {
        const int col = n0 + wn + nf*8 + 2*tig;
        const float b0v = bias[col], b1v = bias[col+1];
#pragma unroll
        for (int mf = 0; mf < 4; mf++) {
#pragma unroll
            for (int hf = 0; hf < 2; hf++) {
                const int r = m0 + wm + mf*16 + gid + 8*hf;
                *(float2*)(out + (size_t)r*CC + col) =
                    make_float2(c[mf][nf][2*hf] + b0v, c[mf][nf][2*hf+1] + b1v);
            }
        }
    }
}

// ---------------------------------------------------------------------------
extern "C" void kernel_launch(void* const* d_in, const int* in_sizes, int n_in,
                              void* d_out, int out_size) {
    const float* x      = (const float*)d_in[0];
    const float* w_qkv  = (const float*)d_in[1];
    const float* b_qkv  = (const float*)d_in[2];
    const float* w_proj = (const float*)d_in[3];
    const float* b_proj = (const float*)d_in[4];
    float* out = (float*)d_out;

    __half* wt1p; __half* wt2p;
    cudaGetSymbolAddress((void**)&wt1p, g_wt1);
    cudaGetSymbolAddress((void**)&wt2p, g_wt2);

    init_kernel<<<512, 256>>>();
    transpose_w_kernel<<<dim3(48, 16), dim3(32, 8)>>>(w_qkv, wt1p, W3);
    transpose_w_kernel<<<dim3(16, 16), dim3(32, 8)>>>(w_proj, wt2p, CC);
    gemm_qkv_kernel<<<dim3(12, 512), 256>>>(x, b_qkv);
    kv_mma_kernel<<<dim3(32, 16), 256>>>();
    attn_mma_kernel<<<dim3(32, 256), 256>>>();
    gemm_proj_kernel<<<dim3(4, 512), 256>>>(b_proj, out);
}

// round 5
// speedup vs baseline: 4.9949x; 1.0748x over previous
#include <cuda_runtime.h>
#include <cuda_fp16.h>
#include <math.h>
#include <stdint.h>

// Problem constants (shape-specialized)
#define BB 4
#define NN 16384
#define CC 512
#define HH 8
#define DD 64
#define NT (BB*NN)     // 65536 rows
#define W3 (3*CC)      // 1536

#define FREQ_COEF (-0.20762050593046014f)

// Scratch (device globals: allocation-free rule)
__device__ __half g_xh[(size_t)NT*CC];     // x as half
__device__ __half g_q[(size_t)BB*HH*NN*DD];
__device__ __half g_k[(size_t)BB*HH*NN*DD];
__device__ __half g_v[(size_t)BB*HH*NN*DD];
__device__ __half g_attn[(size_t)NT*CC];
__device__ float  g_kv[BB*HH*DD*DD];
__device__ float  g_ksum[BB*HH*DD];
__device__ float  g_trig[128*16*2];        // [pos][fi][{cos,sin}]
__device__ __half g_wt1[(size_t)W3*CC];    // w_qkv^T  [n][k] half
__device__ __half g_wt2[(size_t)CC*CC];    // w_proj^T [n][k] half

// ---------------------------------------------------------------------------
// helpers
// ---------------------------------------------------------------------------
__device__ __forceinline__ unsigned f2tf(float f) {
    unsigned u; asm("cvt.rna.tf32.f32 %0, %1;" : "=r"(u) : "f"(f)); return u;
}

__device__ __forceinline__ uint32_t smem_u32(const void* p) {
    uint32_t a;
    asm("{ .reg .u64 t; cvta.to.shared.u64 t, %1; cvt.u32.u64 %0, t; }"
        : "=r"(a) : "l"(p));
    return a;
}

#define CP_ASYNC_16(sa, gp) \
    asm volatile("cp.async.cg.shared.global [%0], [%1], 16;" :: "r"(sa), "l"(gp))
#define CP_ASYNC_COMMIT() asm volatile("cp.async.commit_group;" ::: "memory")
#define CP_ASYNC_WAIT1()  asm volatile("cp.async.wait_group 1;" ::: "memory")

// fp16 mma m16n8k16, fp32 accumulate
__device__ __forceinline__ void mma16(float* c, const unsigned* a, const unsigned* b) {
    asm volatile(
        "mma.sync.aligned.m16n8k16.row.col.f32.f16.f16.f32 "
        "{%0,%1,%2,%3},{%4,%5,%6,%7},{%8,%9},{%0,%1,%2,%3};\n"
        : "+f"(c[0]), "+f"(c[1]), "+f"(c[2]), "+f"(c[3])
        : "r"(a[0]), "r"(a[1]), "r"(a[2]), "r"(a[3]), "r"(b[0]), "r"(b[1]));
}

// tf32 mma m16n8k8 (kv / attn kernels)
__device__ __forceinline__ void mma8(float* c, const unsigned* a, const unsigned* b) {
    asm volatile(
        "mma.sync.aligned.m16n8k8.row.col.f32.tf32.tf32.f32 "
        "{%0,%1,%2,%3},{%4,%5,%6,%7},{%8,%9},{%0,%1,%2,%3};\n"
        : "+f"(c[0]), "+f"(c[1]), "+f"(c[2]), "+f"(c[3])
        : "r"(a[0]), "r"(a[1]), "r"(a[2]), "r"(a[3]), "r"(b[0]), "r"(b[1]));
}

// half pair -> two fp32 bit patterns (exact; valid tf32 operands)
__device__ __forceinline__ void h2_to_u2(unsigned h2bits, unsigned& u0, unsigned& u1) {
    __half2 h = *(__half2*)&h2bits;
    float2 f = __half22float2(h);
    u0 = __float_as_uint(f.x);
    u1 = __float_as_uint(f.y);
}

// ---------------------------------------------------------------------------
// init: zero kv/ksum + trig table (runs every launch: graph replays)
// ---------------------------------------------------------------------------
__global__ void init_kernel() {
    int i = blockIdx.x * blockDim.x + threadIdx.x;
    if (i < BB*HH*DD*DD) g_kv[i] = 0.f;
    if (i < BB*HH*DD)    g_ksum[i] = 0.f;
    if (i < 128*16) {
        int pos = i >> 4, fi = i & 15;
        float freq = exp2f((float)fi * FREQ_COEF);
        float s, c;
        sincosf((float)pos * freq, &s, &c);
        g_trig[i*2]   = c;
        g_trig[i*2+1] = s;
    }
}

// ---------------------------------------------------------------------------
// convert x fp32 -> half mirror (8 elems/thread)
// ---------------------------------------------------------------------------
__global__ void convert_x_kernel(const float* __restrict__ x) {
    const size_t i = ((size_t)blockIdx.x * 256 + threadIdx.x) * 8;
    float4 a = *(const float4*)(x + i);
    float4 b = *(const float4*)(x + i + 4);
    __half2 h0 = __floats2half2_rn(a.x, a.y);
    __half2 h1 = __floats2half2_rn(a.z, a.w);
    __half2 h2 = __floats2half2_rn(b.x, b.y);
    __half2 h3 = __floats2half2_rn(b.z, b.w);
    *(uint4*)(g_xh + i) = make_uint4(*(unsigned*)&h0, *(unsigned*)&h1,
                                     *(unsigned*)&h2, *(unsigned*)&h3);
}

// ---------------------------------------------------------------------------
// Transpose weights to K-major half: src fp32 [512][N] -> dst half [N][512]
// ---------------------------------------------------------------------------
__global__ void transpose_w_kernel(const float* __restrict__ src,
                                   __half* __restrict__ dst, int N) {
    __shared__ float tile[32][33];
    const int k0 = blockIdx.y << 5, n0 = blockIdx.x << 5;
    const int tx = threadIdx.x, ty = threadIdx.y;   // 32 x 8
#pragma unroll
    for (int i = 0; i < 32; i += 8)
        tile[ty+i][tx] = src[(size_t)(k0+ty+i)*N + n0 + tx];
    __syncthreads();
#pragma unroll
    for (int i = 0; i < 32; i += 8)
        dst[(size_t)(n0+ty+i)*CC + k0 + tx] = __float2half_rn(tile[tx][ty+i]);
}

// ---------------------------------------------------------------------------
// Pipelined fp16 GEMM core: 3-stage cp.async, tile 128x128, warp 64x32, K=32.
// Dynamic smem: A stages [3][128][40], B stages [3][128][40] halves = 61440 B
// ---------------------------------------------------------------------------
#define STG_H 5120           // halves per stage buffer (128*40)
#define SMEM_PIPE_BYTES (6 * STG_H * 2)

// issue one stage's A+B copies (2 chunks each per thread)
__device__ __forceinline__ void issue_stage(
    uint32_t smbase, int stage, const __half* gA, const __half* gB,
    int m0, int n0, int k0, int tid)
{
    const int lrow = tid >> 1;            // 0..127
    const int lc8  = (tid & 1) << 4;      // 0 or 16 halves
    const uint32_t saA = smbase + (stage*STG_H + lrow*40 + lc8)*2;
    const __half* gpA = gA + (size_t)(m0 + lrow)*CC + k0 + lc8;
    CP_ASYNC_16(saA,      gpA);
    CP_ASYNC_16(saA + 16, gpA + 8);
    const uint32_t saB = smbase + ((3 + stage)*STG_H + lrow*40 + lc8)*2;
    const __half* gpB = gB + (size_t)(n0 + lrow)*CC + k0 + lc8;
    CP_ASYNC_16(saB,      gpB);
    CP_ASYNC_16(saB + 16, gpB + 8);
}

// compute one stage into c[4][4][4]
__device__ __forceinline__ void compute_stage(
    const __half* smp, int stage, int wm, int wn, int gid, int tig,
    float c[4][4][4])
{
    const __half* As = smp + stage*STG_H;
    const __half* Bs = smp + (3 + stage)*STG_H;
#pragma unroll
    for (int kk = 0; kk < 32; kk += 16) {
        unsigned a[4][4], b[4][2];
#pragma unroll
        for (int mf = 0; mf < 4; mf++) {
            const int r = wm + mf*16 + gid;
            a[mf][0] = *(const unsigned*)(As + r*40     + kk + 2*tig);
            a[mf][1] = *(const unsigned*)(As + (r+8)*40 + kk + 2*tig);
            a[mf][2] = *(const unsigned*)(As + r*40     + kk + 8 + 2*tig);
            a[mf][3] = *(const unsigned*)(As + (r+8)*40 + kk + 8 + 2*tig);
        }
#pragma unroll
        for (int nf = 0; nf < 4; nf++) {
            const int cc = wn + nf*8 + gid;
            b[nf][0] = *(const unsigned*)(Bs + cc*40 + kk + 2*tig);
            b[nf][1] = *(const unsigned*)(Bs + cc*40 + kk + 8 + 2*tig);
        }
#pragma unroll
        for (int mf = 0; mf < 4; mf++)
#pragma unroll
            for (int nf = 0; nf < 4; nf++)
                mma16(c[mf][nf], a[mf], b[nf]);
    }
}

// ---------------------------------------------------------------------------
// GEMM1: qkv = x @ w_qkv + b_qkv, fused RoPE + elu+1, scatter half q/k/v.
// ---------------------------------------------------------------------------
__global__ __launch_bounds__(256, 2) void gemm_qkv_kernel(
    const float* __restrict__ bias)
{
    extern __shared__ __half smp[];
    const uint32_t smbase = smem_u32(smp);
    const int tid  = threadIdx.x;
    const int warp = tid >> 5, lane = tid & 31;
    const int gid  = lane >> 2, tig = lane & 3;
    const int m0 = blockIdx.y << 7, n0 = blockIdx.x << 7;
    const int wm = (warp >> 2) << 6;
    const int wn = (warp & 3) << 5;

    float c[4][4][4];
#pragma unroll
    for (int i = 0; i < 4; i++)
#pragma unroll
        for (int j = 0; j < 4; j++)
#pragma unroll
            for (int r = 0; r < 4; r++) c[i][j][r] = 0.f;

    issue_stage(smbase, 0, g_xh, g_wt1, m0, n0, 0, tid);  CP_ASYNC_COMMIT();
    issue_stage(smbase, 1, g_xh, g_wt1, m0, n0, 32, tid); CP_ASYNC_COMMIT();

    for (int s = 0; s < 16; s++) {
        CP_ASYNC_WAIT1();
        __syncthreads();
        if (s + 2 < 16) {
            issue_stage(smbase, (s+2)%3, g_xh, g_wt1, m0, n0, (s+2)*32, tid);
            CP_ASYNC_COMMIT();
        } else {
            CP_ASYNC_COMMIT();   // keep group count uniform
        }
        compute_stage(smp, s%3, wm, wn, gid, tig, c);
        __syncthreads();
    }

    // --- epilogue: RoPE + elu+1, scatter half to g_q/g_k/g_v ---
    const int sect = n0 >> 9;             // 0=q 1=k 2=v
#pragma unroll
    for (int nf = 0; nf < 4; nf++) {
        const int col = n0 + wn + nf*8 + 2*tig;
        const int h   = (col >> 6) & 7;
        const int d   = col & 63;
        const float b0v = bias[col], b1v = bias[col+1];
        const int  fi  = (d & 31) >> 1;
        const bool axx = (d < 32);
#pragma unroll
        for (int mf = 0; mf < 4; mf++) {
#pragma unroll
            for (int hf = 0; hf < 2; hf++) {
                const int r    = m0 + wm + mf*16 + gid + 8*hf;
                const int bidx = r >> 14;
                const int t    = r & (NN-1);
                float v0 = c[mf][nf][2*hf]   + b0v;
                float v1 = c[mf][nf][2*hf+1] + b1v;
                const size_t base = ((size_t)(bidx*HH + h)*NN + t)*DD + d;
                if (sect == 2) {
                    *(__half2*)(g_v + base) = __floats2half2_rn(v0, v1);
                } else {
                    const int pos = axx ? (t & 127) : (t >> 7);
                    const float2 cs = *(const float2*)(g_trig + ((pos << 4) + fi)*2);
                    float orr = v0*cs.x - v1*cs.y;
                    float oii = v0*cs.y + v1*cs.x;
                    orr = (orr > 0.f) ? orr + 1.f : __expf(orr);
                    oii = (oii > 0.f) ? oii + 1.f : __expf(oii);
                    __half* dst = (sect == 0) ? g_q : g_k;
                    *(__half2*)(dst + base) = __floats2half2_rn(orr, oii);
                }
            }
        }
    }
}

// ---------------------------------------------------------------------------
// GEMM2: out = attn @ w_proj + b_proj (attn already half)
// ---------------------------------------------------------------------------
__global__ __launch_bounds__(256, 2) void gemm_proj_kernel(
    const float* __restrict__ bias,
    float* __restrict__ out)
{
    extern __shared__ __half smp[];
    const uint32_t smbase = smem_u32(smp);
    const int tid  = threadIdx.x;
    const int warp = tid >> 5, lane = tid & 31;
    const int gid  = lane >> 2, tig = lane & 3;
    const int m0 = blockIdx.y << 7, n0 = blockIdx.x << 7;
    const int wm = (warp >> 2) << 6;
    const int wn = (warp & 3) << 5;

    float c[4][4][4];
#pragma unroll
    for (int i = 0; i < 4; i++)
#pragma unroll
        for (int j = 0; j < 4; j++)
#pragma unroll
            for (int r = 0; r < 4; r++) c[i][j][r] = 0.f;

    issue_stage(smbase, 0, g_attn, g_wt2, m0, n0, 0, tid);  CP_ASYNC_COMMIT();
    issue_stage(smbase, 1, g_attn, g_wt2, m0, n0, 32, tid); CP_ASYNC_COMMIT();

    for (int s = 0; s < 16; s++) {
        CP_ASYNC_WAIT1();
        __syncthreads();
        if (s + 2 < 16) {
            issue_stage(smbase, (s+2)%3, g_attn, g_wt2, m0, n0, (s+2)*32, tid);
            CP_ASYNC_COMMIT();
        } else {
            CP_ASYNC_COMMIT();
        }
        compute_stage(smp, s%3, wm, wn, gid, tig, c);
        __syncthreads();
    }

#pragma unroll
    for (int nf = 0; nf < 4; nf++) {
        const int col = n0 + wn + nf*8 + 2*tig;
        const float b0v = bias[col], b1v = bias[col+1];
#pragma unroll
        for (int mf = 0; mf < 4; mf++) {
#pragma unroll
            for (int hf = 0; hf < 2; hf++) {
                const int r = m0 + wm + mf*16 + gid + 8*hf;
                *(float2*)(out + (size_t)r*CC + col) =
                    make_float2(c[mf][nf][2*hf] + b0v, c[mf][nf][2*hf+1] + b1v);
            }
        }
    }
}

// ---------------------------------------------------------------------------
// kv[b,h,d,e] = sum_n k[n,d] v[n,e];  ksum via ones-column. tf32 mma,
// inputs now half (exact convert).
// ---------------------------------------------------------------------------
__global__ __launch_bounds__(256, 2) void kv_mma_kernel() {
    __shared__ unsigned Ks[64][68];   // [d][n]
    __shared__ unsigned Vs[64][72];   // [n][e], col 64 = 1.0

    const int tid  = threadIdx.x;
    const int warp = tid >> 5, lane = tid & 31;
    const int gid  = lane >> 2, tig = lane & 3;
    const int bh    = blockIdx.x;
    const int nbase = blockIdx.y << 10;
    const int wn  = (warp & 3) << 4;
    const int ksl = (warp >> 2) << 5;

    float c[4][2][4], cx[4][4];
#pragma unroll
    for (int i = 0; i < 4; i++) {
#pragma unroll
        for (int j = 0; j < 2; j++)
#pragma unroll
            for (int r = 0; r < 4; r++) c[i][j][r] = 0.f;
#pragma unroll
        for (int r = 0; r < 4; r++) cx[i][r] = 0.f;
    }

    if (tid < 64) {
        Vs[tid][64] = 0x3F800000u;
#pragma unroll
        for (int j = 65; j < 72; j++) Vs[tid][j] = 0u;
    }

    const __half* kb = g_k + (size_t)bh*NN*DD;
    const __half* vb = g_v + (size_t)bh*NN*DD;

    for (int s = 0; s < 16; s++) {
        const int n0 = nbase + s*64;
        {
            const int n  = tid & 63;
            const int db = (tid >> 6) << 2;
#pragma unroll
            for (int i = 0; i < 4; i++) {
                const int d4 = db + i*16;
                uint2 u = *(const uint2*)(kb + (size_t)(n0 + n)*DD + d4);
                unsigned u0,u1,u2,u3;
                h2_to_u2(u.x, u0, u1);
                h2_to_u2(u.y, u2, u3);
                Ks[d4+0][n] = u0; Ks[d4+1][n] = u1;
                Ks[d4+2][n] = u2; Ks[d4+3][n] = u3;
            }
        }
        {
            const int n  = tid >> 2;
            const int eb = (tid & 3) << 2;
#pragma unroll
            for (int i = 0; i < 4; i++) {
                const int e4 = eb + i*16;
                uint2 u = *(const uint2*)(vb + (size_t)(n0 + n)*DD + e4);
                unsigned u0,u1,u2,u3;
                h2_to_u2(u.x, u0, u1);
                h2_to_u2(u.y, u2, u3);
                Vs[n][e4+0] = u0; Vs[n][e4+1] = u1;
                Vs[n][e4+2] = u2; Vs[n][e4+3] = u3;
            }
        }
        __syncthreads();
#pragma unroll
        for (int kk2 = 0; kk2 < 32; kk2 += 8) {
            const int kk = ksl + kk2;
            unsigned a[4][4], b[2][2], bx[2];
#pragma unroll
            for (int mf = 0; mf < 4; mf++) {
                const int r = mf*16 + gid;
                a[mf][0] = Ks[r][kk+tig];
                a[mf][1] = Ks[r+8][kk+tig];
                a[mf][2] = Ks[r][kk+tig+4];
                a[mf][3] = Ks[r+8][kk+tig+4];
            }
#pragma unroll
            for (int nf = 0; nf < 2; nf++) {
                const int e = wn + nf*8 + gid;
                b[nf][0] = Vs[kk+tig][e];
                b[nf][1] = Vs[kk+tig+4][e];
            }
            if (wn == 0) { bx[0] = Vs[kk+tig][64+gid]; bx[1] = Vs[kk+tig+4][64+gid]; }
#pragma unroll
            for (int mf = 0; mf < 4; mf++) {
#pragma unroll
                for (int nf = 0; nf < 2; nf++) mma8(c[mf][nf], a[mf], b[nf]);
                if (wn == 0) mma8(cx[mf], a[mf], bx);
            }
        }
        __syncthreads();
    }

    float* kvp = g_kv + bh*DD*DD;
#pragma unroll
    for (int mf = 0; mf < 4; mf++)
#pragma unroll
        for (int nf = 0; nf < 2; nf++) {
            const int e = wn + nf*8 + 2*tig;
#pragma unroll
            for (int hf = 0; hf < 2; hf++) {
                const int dd = mf*16 + gid + 8*hf;
                atomicAdd(&kvp[dd*DD + e],     c[mf][nf][2*hf]);
                atomicAdd(&kvp[dd*DD + e + 1], c[mf][nf][2*hf+1]);
            }
        }
    if (wn == 0 && tig == 0) {
#pragma unroll
        for (int mf = 0; mf < 4; mf++)
#pragma unroll
            for (int hf = 0; hf < 2; hf++)
                atomicAdd(&g_ksum[bh*DD + mf*16 + gid + 8*hf], cx[mf][2*hf]);
    }
}

// ---------------------------------------------------------------------------
// attn = (q @ kv) * zinv  (tf32 mma); q half input, writes g_attn half.
// ---------------------------------------------------------------------------
__global__ __launch_bounds__(256) void attn_mma_kernel() {
    __shared__ unsigned Qs[64][68];
    __shared__ unsigned KVs[64][72];
    __shared__ float zbuf[64];

    const int tid  = threadIdx.x;
    const int warp = tid >> 5, lane = tid & 31;
    const int gid  = lane >> 2, tig = lane & 3;
    const int bh = blockIdx.x, b = bh >> 3, h = bh & 7;
    const int n0 = blockIdx.y << 6;
    const int wm = (warp >> 1) << 4;
    const int wn = (warp & 1) << 5;

    {
        const int d  = tid >> 2;
        const int eb = (tid & 3) << 2;
        const float* kvp = g_kv + bh*DD*DD;
#pragma unroll
        for (int i = 0; i < 4; i++) {
            const int e4 = eb + i*16;
            float4 t = *(const float4*)(kvp + d*DD + e4);
            *(uint4*)&KVs[d][e4] =
                make_uint4(f2tf(t.x), f2tf(t.y), f2tf(t.z), f2tf(t.w));
        }
    }
    if (tid < 64) {
        KVs[tid][64] = f2tf(g_ksum[bh*DD + tid]);
#pragma unroll
        for (int j = 65; j < 72; j++) KVs[tid][j] = 0u;
    }
    {
        const int r  = tid >> 2;
        const int db = (tid & 3) << 2;
        const __half* qb = g_q + ((size_t)bh*NN + n0)*DD;
#pragma unroll
        for (int i = 0; i < 4; i++) {
            const int d4 = db + i*16;
            uint2 u = *(const uint2*)(qb + (size_t)r*DD + d4);
            unsigned u0,u1,u2,u3;
            h2_to_u2(u.x, u0, u1);
            h2_to_u2(u.y, u2, u3);
            Qs[r][d4+0] = u0; Qs[r][d4+1] = u1;
            Qs[r][d4+2] = u2; Qs[r][d4+3] = u3;
        }
    }
    __syncthreads();

    float c[4][4], cz[4];
#pragma unroll
    for (int j = 0; j < 4; j++) {
#pragma unroll
        for (int r = 0; r < 4; r++) c[j][r] = 0.f;
        cz[j] = 0.f;
    }

#pragma unroll
    for (int kk = 0; kk < 64; kk += 8) {
        unsigned a[4], bfr[4][2], bz[2];
        const int r = wm + gid;
        a[0] = Qs[r][kk+tig];
        a[1] = Qs[r+8][kk+tig];
        a[2] = Qs[r][kk+tig+4];
        a[3] = Qs[r+8][kk+tig+4];
#pragma unroll
        for (int nf = 0; nf < 4; nf++) {
            const int e = wn + nf*8 + gid;
            bfr[nf][0] = KVs[kk+tig][e];
            bfr[nf][1] = KVs[kk+tig+4][e];
        }
        if (wn) { bz[0] = KVs[kk+tig][64+gid]; bz[1] = KVs[kk+tig+4][64+gid]; }
#pragma unroll
        for (int nf = 0; nf < 4; nf++) mma8(c[nf], a, bfr[nf]);
        if (wn) mma8(cz, a, bz);
    }
    if (wn && tig == 0) {
        zbuf[wm + gid]     = 1.f/(cz[0] + 1e-6f);
        zbuf[wm + gid + 8] = 1.f/(cz[2] + 1e-6f);
    }
    __syncthreads();

    __half* ob = g_attn + ((size_t)b*NN + n0)*CC + h*DD;
#pragma unroll
    for (int nf = 0; nf < 4; nf++) {
        const int e = wn + nf*8 + 2*tig;
#pragma unroll
        for (int hf = 0; hf < 2; hf++) {
            const int row = wm + gid + 8*hf;
            const float zi = zbuf[row];
            *(__half2*)(ob + (size_t)row*CC + e) =
                __floats2half2_rn(c[nf][2*hf]*zi, c[nf][2*hf+1]*zi);
        }
    }
}

// ---------------------------------------------------------------------------
extern "C" void kernel_launch(void* const* d_in, const int* in_sizes, int n_in,
                              void* d_out, int out_size) {
    const float* x      = (const float*)d_in[0];
    const float* w_qkv  = (const float*)d_in[1];
    const float* b_qkv  = (const float*)d_in[2];
    const float* w_proj = (const float*)d_in[3];
    const float* b_proj = (const float*)d_in[4];
    float* out = (float*)d_out;

    cudaFuncSetAttribute(gemm_qkv_kernel,
        cudaFuncAttributeMaxDynamicSharedMemorySize, SMEM_PIPE_BYTES);
    cudaFuncSetAttribute(gemm_proj_kernel,
        cudaFuncAttributeMaxDynamicSharedMemorySize, SMEM_PIPE_BYTES);

    __half* wt1p; __half* wt2p;
    cudaGetSymbolAddress((void**)&wt1p, g_wt1);
    cudaGetSymbolAddress((void**)&wt2p, g_wt2);

    init_kernel<<<512, 256>>>();
    convert_x_kernel<<<16384, 256>>>(x);
    transpose_w_kernel<<<dim3(48, 16), dim3(32, 8)>>>(w_qkv, wt1p, W3);
    transpose_w_kernel<<<dim3(16, 16), dim3(32, 8)>>>(w_proj, wt2p, CC);
    gemm_qkv_kernel<<<dim3(12, 512), 256, SMEM_PIPE_BYTES>>>(b_qkv);
    kv_mma_kernel<<<dim3(32, 16), 256>>>();
    attn_mma_kernel<<<dim3(32, 256), 256>>>();
    gemm_proj_kernel<<<dim3(4, 512), 256, SMEM_PIPE_BYTES>>>(b_proj, out);
}

// round 6
// speedup vs baseline: 5.8082x; 1.1628x over previous
#include <cuda_runtime.h>
#include <cuda_fp16.h>
#include <math.h>
#include <stdint.h>

// Problem constants (shape-specialized)
#define BB 4
#define NN 16384
#define CC 512
#define HH 8
#define DD 64
#define NT (BB*NN)     // 65536 rows
#define W3 (3*CC)      // 1536

#define FREQ_COEF (-0.20762050593046014f)

// Scratch (device globals: allocation-free rule)
__device__ __half g_xh[(size_t)NT*CC];     // x as half
__device__ __half g_q[(size_t)BB*HH*NN*DD];
__device__ __half g_k[(size_t)BB*HH*NN*DD];
__device__ __half g_v[(size_t)BB*HH*NN*DD];
__device__ __half g_attn[(size_t)NT*CC];
__device__ float  g_kv[BB*HH*DD*DD];
__device__ float  g_ksum[BB*HH*DD];
__device__ float  g_trig[128*16*2];        // [pos][fi][{cos,sin}]
__device__ __half g_wt1[(size_t)W3*CC];    // w_qkv^T  [n][k] half
__device__ __half g_wt2[(size_t)CC*CC];    // w_proj^T [n][k] half

// ---------------------------------------------------------------------------
// helpers
// ---------------------------------------------------------------------------
__device__ __forceinline__ unsigned f2tf(float f) {
    unsigned u; asm("cvt.rna.tf32.f32 %0, %1;" : "=r"(u) : "f"(f)); return u;
}

__device__ __forceinline__ uint32_t smem_u32(const void* p) {
    uint32_t a;
    asm("{ .reg .u64 t; cvta.to.shared.u64 t, %1; cvt.u32.u64 %0, t; }"
        : "=r"(a) : "l"(p));
    return a;
}

#define CP_ASYNC_16(sa, gp) \
    asm volatile("cp.async.cg.shared.global [%0], [%1], 16;" :: "r"(sa), "l"(gp))
#define CP_ASYNC_COMMIT() asm volatile("cp.async.commit_group;" ::: "memory")
#define CP_ASYNC_WAIT1()  asm volatile("cp.async.wait_group 1;" ::: "memory")

__device__ __forceinline__ void ldsm_x4(unsigned* r, uint32_t addr) {
    asm volatile("ldmatrix.sync.aligned.m8n8.x4.shared.b16 {%0,%1,%2,%3}, [%4];"
        : "=r"(r[0]), "=r"(r[1]), "=r"(r[2]), "=r"(r[3]) : "r"(addr));
}

// fp16 mma m16n8k16, fp32 accumulate
__device__ __forceinline__ void mma16(float* c, const unsigned* a, const unsigned* b) {
    asm volatile(
        "mma.sync.aligned.m16n8k16.row.col.f32.f16.f16.f32 "
        "{%0,%1,%2,%3},{%4,%5,%6,%7},{%8,%9},{%0,%1,%2,%3};\n"
        : "+f"(c[0]), "+f"(c[1]), "+f"(c[2]), "+f"(c[3])
        : "r"(a[0]), "r"(a[1]), "r"(a[2]), "r"(a[3]), "r"(b[0]), "r"(b[1]));
}

// tf32 mma m16n8k8 (kv / attn kernels)
__device__ __forceinline__ void mma8(float* c, const unsigned* a, const unsigned* b) {
    asm volatile(
        "mma.sync.aligned.m16n8k8.row.col.f32.tf32.tf32.f32 "
        "{%0,%1,%2,%3},{%4,%5,%6,%7},{%8,%9},{%0,%1,%2,%3};\n"
        : "+f"(c[0]), "+f"(c[1]), "+f"(c[2]), "+f"(c[3])
        : "r"(a[0]), "r"(a[1]), "r"(a[2]), "r"(a[3]), "r"(b[0]), "r"(b[1]));
}

// half pair -> two fp32 bit patterns (exact)
__device__ __forceinline__ void h2_to_u2(unsigned h2bits, unsigned& u0, unsigned& u1) {
    __half2 h = *(__half2*)&h2bits;
    float2 f = __half22float2(h);
    u0 = __float_as_uint(f.x);
    u1 = __float_as_uint(f.y);
}

// ---------------------------------------------------------------------------
// init: zero kv/ksum + trig table (runs every launch: graph replays)
// ---------------------------------------------------------------------------
__global__ void init_kernel() {
    int i = blockIdx.x * blockDim.x + threadIdx.x;
    if (i < BB*HH*DD*DD) g_kv[i] = 0.f;
    if (i < BB*HH*DD)    g_ksum[i] = 0.f;
    if (i < 128*16) {
        int pos = i >> 4, fi = i & 15;
        float freq = exp2f((float)fi * FREQ_COEF);
        float s, c;
        sincosf((float)pos * freq, &s, &c);
        g_trig[i*2]   = c;
        g_trig[i*2+1] = s;
    }
}

// ---------------------------------------------------------------------------
// convert x fp32 -> half mirror (8 elems/thread)
// ---------------------------------------------------------------------------
__global__ void convert_x_kernel(const float* __restrict__ x) {
    const size_t i = ((size_t)blockIdx.x * 256 + threadIdx.x) * 8;
    float4 a = *(const float4*)(x + i);
    float4 b = *(const float4*)(x + i + 4);
    __half2 h0 = __floats2half2_rn(a.x, a.y);
    __half2 h1 = __floats2half2_rn(a.z, a.w);
    __half2 h2 = __floats2half2_rn(b.x, b.y);
    __half2 h3 = __floats2half2_rn(b.z, b.w);
    *(uint4*)(g_xh + i) = make_uint4(*(unsigned*)&h0, *(unsigned*)&h1,
                                     *(unsigned*)&h2, *(unsigned*)&h3);
}

// ---------------------------------------------------------------------------
// Transpose weights to K-major half: src fp32 [512][N] -> dst half [N][512]
// ---------------------------------------------------------------------------
__global__ void transpose_w_kernel(const float* __restrict__ src,
                                   __half* __restrict__ dst, int N) {
    __shared__ float tile[32][33];
    const int k0 = blockIdx.y << 5, n0 = blockIdx.x << 5;
    const int tx = threadIdx.x, ty = threadIdx.y;   // 32 x 8
#pragma unroll
    for (int i = 0; i < 32; i += 8)
        tile[ty+i][tx] = src[(size_t)(k0+ty+i)*N + n0 + tx];
    __syncthreads();
#pragma unroll
    for (int i = 0; i < 32; i += 8)
        dst[(size_t)(n0+ty+i)*CC + k0 + tx] = __float2half_rn(tile[tx][ty+i]);
}

// ---------------------------------------------------------------------------
// Pipelined fp16 GEMM core: 3-stage cp.async, tile 128x128, warp 64x32, K=32.
// Dynamic smem: A stages [3][128][40], B stages [3][128][40] halves = 61440 B
// Fragments via ldmatrix.x4 (stride 40 halves = conflict-free LDSM).
// ---------------------------------------------------------------------------
#define STG_H 5120           // halves per stage buffer (128*40)
#define SMEM_PIPE_BYTES (6 * STG_H * 2)

__device__ __forceinline__ void issue_stage(
    uint32_t smbase, int stage, const __half* gA, const __half* gB,
    int m0, int n0, int k0, int tid)
{
    const int lrow = tid >> 1;            // 0..127
    const int lc8  = (tid & 1) << 4;      // 0 or 16 halves
    const uint32_t saA = smbase + (stage*STG_H + lrow*40 + lc8)*2;
    const __half* gpA = gA + (size_t)(m0 + lrow)*CC + k0 + lc8;
    CP_ASYNC_16(saA,      gpA);
    CP_ASYNC_16(saA + 16, gpA + 8);
    const uint32_t saB = smbase + ((3 + stage)*STG_H + lrow*40 + lc8)*2;
    const __half* gpB = gB + (size_t)(n0 + lrow)*CC + k0 + lc8;
    CP_ASYNC_16(saB,      gpB);
    CP_ASYNC_16(saB + 16, gpB + 8);
}

// compute one stage into c[4][4][4] using ldmatrix fragments
__device__ __forceinline__ void compute_stage(
    uint32_t aBase, uint32_t bBase, int stage, float c[4][4][4])
{
    const uint32_t aS = aBase + stage*(STG_H*2);
    const uint32_t bS = bBase + stage*(STG_H*2);
#pragma unroll
    for (int kk = 0; kk < 32; kk += 16) {
        unsigned a[4][4], b[2][4];
#pragma unroll
        for (int mf = 0; mf < 4; mf++)
            ldsm_x4(a[mf], aS + (mf*16*40 + kk)*2);
#pragma unroll
        for (int p = 0; p < 2; p++)
            ldsm_x4(b[p], bS + (p*16*40 + kk)*2);
#pragma unroll
        for (int mf = 0; mf < 4; mf++)
#pragma unroll
            for (int nf = 0; nf < 4; nf++)
                mma16(c[mf][nf], a[mf], &b[nf >> 1][(nf & 1) * 2]);
    }
}

// per-thread ldmatrix base addresses
// A x4 covers (rows m..m+16, k..k+8 | k+8..k+16): row = lane&15, koff = (lane>>4)*8
// B x4 covers (n..n+8|n+8..n+16) x (k..k+8|k+8..k+16):
//   row = ((lane>>4)<<3) + (lane&7), koff = ((lane>>3)&1)*8
__device__ __forceinline__ uint32_t a_frag_base(uint32_t smbase, int wm, int lane) {
    return smbase + ((wm + (lane & 15))*40 + ((lane >> 4) << 3))*2;
}
__device__ __forceinline__ uint32_t b_frag_base(uint32_t smbase, int wn, int lane) {
    return smbase + 3*STG_H*2 +
        ((wn + ((lane >> 4) << 3) + (lane & 7))*40 + (((lane >> 3) & 1) << 3))*2;
}

// ---------------------------------------------------------------------------
// GEMM1: qkv = x @ w_qkv + b_qkv, fused RoPE + elu+1, scatter half q/k/v.
// ---------------------------------------------------------------------------
__global__ __launch_bounds__(256, 2) void gemm_qkv_kernel(
    const float* __restrict__ bias)
{
    extern __shared__ __half smp[];
    const uint32_t smbase = smem_u32(smp);
    const int tid  = threadIdx.x;
    const int warp = tid >> 5, lane = tid & 31;
    const int gid  = lane >> 2, tig = lane & 3;
    const int m0 = blockIdx.y << 7, n0 = blockIdx.x << 7;
    const int wm = (warp >> 2) << 6;
    const int wn = (warp & 3) << 5;

    const uint32_t aB = a_frag_base(smbase, wm, lane);
    const uint32_t bB = b_frag_base(smbase, wn, lane);

    float c[4][4][4];
#pragma unroll
    for (int i = 0; i < 4; i++)
#pragma unroll
        for (int j = 0; j < 4; j++)
#pragma unroll
            for (int r = 0; r < 4; r++) c[i][j][r] = 0.f;

    issue_stage(smbase, 0, g_xh, g_wt1, m0, n0, 0, tid);  CP_ASYNC_COMMIT();
    issue_stage(smbase, 1, g_xh, g_wt1, m0, n0, 32, tid); CP_ASYNC_COMMIT();

    for (int s = 0; s < 16; s++) {
        CP_ASYNC_WAIT1();
        __syncthreads();
        if (s + 2 < 16)
            issue_stage(smbase, (s+2)%3, g_xh, g_wt1, m0, n0, (s+2)*32, tid);
        CP_ASYNC_COMMIT();
        compute_stage(aB, bB, s%3, c);
    }

    // --- epilogue: RoPE + elu+1, scatter half to g_q/g_k/g_v ---
    const int sect = n0 >> 9;             // 0=q 1=k 2=v
#pragma unroll
    for (int nf = 0; nf < 4; nf++) {
        const int col = n0 + wn + nf*8 + 2*tig;
        const int h   = (col >> 6) & 7;
        const int d   = col & 63;
        const float b0v = bias[col], b1v = bias[col+1];
        const int  fi  = (d & 31) >> 1;
        const bool axx = (d < 32);
#pragma unroll
        for (int mf = 0; mf < 4; mf++) {
#pragma unroll
            for (int hf = 0; hf < 2; hf++) {
                const int r    = m0 + wm + mf*16 + gid + 8*hf;
                const int bidx = r >> 14;
                const int t    = r & (NN-1);
                float v0 = c[mf][nf][2*hf]   + b0v;
                float v1 = c[mf][nf][2*hf+1] + b1v;
                const size_t base = ((size_t)(bidx*HH + h)*NN + t)*DD + d;
                if (sect == 2) {
                    *(__half2*)(g_v + base) = __floats2half2_rn(v0, v1);
                } else {
                    const int pos = axx ? (t & 127) : (t >> 7);
                    const float2 cs = *(const float2*)(g_trig + ((pos << 4) + fi)*2);
                    float orr = v0*cs.x - v1*cs.y;
                    float oii = v0*cs.y + v1*cs.x;
                    orr = (orr > 0.f) ? orr + 1.f : __expf(orr);
                    oii = (oii > 0.f) ? oii + 1.f : __expf(oii);
                    __half* dst = (sect == 0) ? g_q : g_k;
                    *(__half2*)(dst + base) = __floats2half2_rn(orr, oii);
                }
            }
        }
    }
}

// ---------------------------------------------------------------------------
// GEMM2: out = attn @ w_proj + b_proj (attn already half)
// ---------------------------------------------------------------------------
__global__ __launch_bounds__(256, 2) void gemm_proj_kernel(
    const float* __restrict__ bias,
    float* __restrict__ out)
{
    extern __shared__ __half smp[];
    const uint32_t smbase = smem_u32(smp);
    const int tid  = threadIdx.x;
    const int warp = tid >> 5, lane = tid & 31;
    const int gid  = lane >> 2, tig = lane & 3;
    const int m0 = blockIdx.y << 7, n0 = blockIdx.x << 7;
    const int wm = (warp >> 2) << 6;
    const int wn = (warp & 3) << 5;

    const uint32_t aB = a_frag_base(smbase, wm, lane);
    const uint32_t bB = b_frag_base(smbase, wn, lane);

    float c[4][4][4];
#pragma unroll
    for (int i = 0; i < 4; i++)
#pragma unroll
        for (int j = 0; j < 4; j++)
#pragma unroll
            for (int r = 0; r < 4; r++) c[i][j][r] = 0.f;

    issue_stage(smbase, 0, g_attn, g_wt2, m0, n0, 0, tid);  CP_ASYNC_COMMIT();
    issue_stage(smbase, 1, g_attn, g_wt2, m0, n0, 32, tid); CP_ASYNC_COMMIT();

    for (int s = 0; s < 16; s++) {
        CP_ASYNC_WAIT1();
        __syncthreads();
        if (s + 2 < 16)
            issue_stage(smbase, (s+2)%3, g_attn, g_wt2, m0, n0, (s+2)*32, tid);
        CP_ASYNC_COMMIT();
        compute_stage(aB, bB, s%3, c);
    }

#pragma unroll
    for (int nf = 0; nf < 4; nf++) {
        const int col = n0 + wn + nf*8 + 2*tig;
        const float b0v = bias[col], b1v = bias[col+1];
#pragma unroll
        for (int mf = 0; mf < 4; mf++) {
#pragma unroll
            for (int hf = 0; hf < 2; hf++) {
                const int r = m0 + wm + mf*16 + gid + 8*hf;
                *(float2*)(out + (size_t)r*CC + col) =
                    make_float2(c[mf][nf][2*hf] + b0v, c[mf][nf][2*hf+1] + b1v);
            }
        }
    }
}

// ---------------------------------------------------------------------------
// kv[b,h,d,e] = sum_n k[n,d] v[n,e];  ksum via ones-column. tf32 mma.
// ---------------------------------------------------------------------------
__global__ __launch_bounds__(256, 2) void kv_mma_kernel() {
    __shared__ unsigned Ks[64][68];   // [d][n]
    __shared__ unsigned Vs[64][72];   // [n][e], col 64 = 1.0

    const int tid  = threadIdx.x;
    const int warp = tid >> 5, lane = tid & 31;
    const int gid  = lane >> 2, tig = lane & 3;
    const int bh    = blockIdx.x;
    const int nbase = blockIdx.y << 10;
    const int wn  = (warp & 3) << 4;
    const int ksl = (warp >> 2) << 5;

    float c[4][2][4], cx[4][4];
#pragma unroll
    for (int i = 0; i < 4; i++) {
#pragma unroll
        for (int j = 0; j < 2; j++)
#pragma unroll
            for (int r = 0; r < 4; r++) c[i][j][r] = 0.f;
#pragma unroll
        for (int r = 0; r < 4; r++) cx[i][r] = 0.f;
    }

    if (tid < 64) {
        Vs[tid][64] = 0x3F800000u;
#pragma unroll
        for (int j = 65; j < 72; j++) Vs[tid][j] = 0u;
    }

    const __half* kb = g_k + (size_t)bh*NN*DD;
    const __half* vb = g_v + (size_t)bh*NN*DD;

    for (int s = 0; s < 16; s++) {
        const int n0 = nbase + s*64;
        {
            const int n  = tid & 63;
            const int db = (tid >> 6) << 2;
#pragma unroll
            for (int i = 0; i < 4; i++) {
                const int d4 = db + i*16;
                uint2 u = *(const uint2*)(kb + (size_t)(n0 + n)*DD + d4);
                unsigned u0,u1,u2,u3;
                h2_to_u2(u.x, u0, u1);
                h2_to_u2(u.y, u2, u3);
                Ks[d4+0][n] = u0; Ks[d4+1][n] = u1;
                Ks[d4+2][n] = u2; Ks[d4+3][n] = u3;
            }
        }
        {
            const int n  = tid >> 2;
            const int eb = (tid & 3) << 2;
#pragma unroll
            for (int i = 0; i < 4; i++) {
                const int e4 = eb + i*16;
                uint2 u = *(const uint2*)(vb + (size_t)(n0 + n)*DD + e4);
                unsigned u0,u1,u2,u3;
                h2_to_u2(u.x, u0, u1);
                h2_to_u2(u.y, u2, u3);
                Vs[n][e4+0] = u0; Vs[n][e4+1] = u1;
                Vs[n][e4+2] = u2; Vs[n][e4+3] = u3;
            }
        }
        __syncthreads();
#pragma unroll
        for (int kk2 = 0; kk2 < 32; kk2 += 8) {
            const int kk = ksl + kk2;
            unsigned a[4][4], b[2][2], bx[2];
#pragma unroll
            for (int mf = 0; mf < 4; mf++) {
                const int r = mf*16 + gid;
                a[mf][0] = Ks[r][kk+tig];
                a[mf][1] = Ks[r+8][kk+tig];
                a[mf][2] = Ks[r][kk+tig+4];
                a[mf][3] = Ks[r+8][kk+tig+4];
            }
#pragma unroll
            for (int nf = 0; nf < 2; nf++) {
                const int e = wn + nf*8 + gid;
                b[nf][0] = Vs[kk+tig][e];
                b[nf][1] = Vs[kk+tig+4][e];
            }
            if (wn == 0) { bx[0] = Vs[kk+tig][64+gid]; bx[1] = Vs[kk+tig+4][64+gid]; }
#pragma unroll
            for (int mf = 0; mf < 4; mf++) {
#pragma unroll
                for (int nf = 0; nf < 2; nf++) mma8(c[mf][nf], a[mf], b[nf]);
                if (wn == 0) mma8(cx[mf], a[mf], bx);
            }
        }
        __syncthreads();
    }

    float* kvp = g_kv + bh*DD*DD;
#pragma unroll
    for (int mf = 0; mf < 4; mf++)
#pragma unroll
        for (int nf = 0; nf < 2; nf++) {
            const int e = wn + nf*8 + 2*tig;
#pragma unroll
            for (int hf = 0; hf < 2; hf++) {
                const int dd = mf*16 + gid + 8*hf;
                atomicAdd(&kvp[dd*DD + e],     c[mf][nf][2*hf]);
                atomicAdd(&kvp[dd*DD + e + 1], c[mf][nf][2*hf+1]);
            }
        }
    if (wn == 0 && tig == 0) {
#pragma unroll
        for (int mf = 0; mf < 4; mf++)
#pragma unroll
            for (int hf = 0; hf < 2; hf++)
                atomicAdd(&g_ksum[bh*DD + mf*16 + gid + 8*hf], cx[mf][2*hf]);
    }
}

// ---------------------------------------------------------------------------
// attn = (q @ kv) * zinv  (tf32 mma); q half input, writes g_attn half.
// ---------------------------------------------------------------------------
__global__ __launch_bounds__(256) void attn_mma_kernel() {
    __shared__ unsigned Qs[64][68];
    __shared__ unsigned KVs[64][72];
    __shared__ float zbuf[64];

    const int tid  = threadIdx.x;
    const int warp = tid >> 5, lane = tid & 31;
    const int gid  = lane >> 2, tig = lane & 3;
    const int bh = blockIdx.x, b = bh >> 3, h = bh & 7;
    const int n0 = blockIdx.y << 6;
    const int wm = (warp >> 1) << 4;
    const int wn = (warp & 1) << 5;

    {
        const int d  = tid >> 2;
        const int eb = (tid & 3) << 2;
        const float* kvp = g_kv + bh*DD*DD;
#pragma unroll
        for (int i = 0; i < 4; i++) {
            const int e4 = eb + i*16;
            float4 t = *(const float4*)(kvp + d*DD + e4);
            *(uint4*)&KVs[d][e4] =
                make_uint4(f2tf(t.x), f2tf(t.y), f2tf(t.z), f2tf(t.w));
        }
    }
    if (tid < 64) {
        KVs[tid][64] = f2tf(g_ksum[bh*DD + tid]);
#pragma unroll
        for (int j = 65; j < 72; j++) KVs[tid][j] = 0u;
    }
    {
        const int r  = tid >> 2;
        const int db = (tid & 3) << 2;
        const __half* qb = g_q + ((size_t)bh*NN + n0)*DD;
#pragma unroll
        for (int i = 0; i < 4; i++) {
            const int d4 = db + i*16;
            uint2 u = *(const uint2*)(qb + (size_t)r*DD + d4);
            unsigned u0,u1,u2,u3;
            h2_to_u2(u.x, u0, u1);
            h2_to_u2(u.y, u2, u3);
            Qs[r][d4+0] = u0; Qs[r][d4+1] = u1;
            Qs[r][d4+2] = u2; Qs[r][d4+3] = u3;
        }
    }
    __syncthreads();

    float c[4][4], cz[4];
#pragma unroll
    for (int j = 0; j < 4; j++) {
#pragma unroll
        for (int r = 0; r < 4; r++) c[j][r] = 0.f;
        cz[j] = 0.f;
    }

#pragma unroll
    for (int kk = 0; kk < 64; kk += 8) {
        unsigned a[4], bfr[4][2], bz[2];
        const int r = wm + gid;
        a[0] = Qs[r][kk+tig];
        a[1] = Qs[r+8][kk+tig];
        a[2] = Qs[r][kk+tig+4];
        a[3] = Qs[r+8][kk+tig+4];
#pragma unroll
        for (int nf = 0; nf < 4; nf++) {
            const int e = wn + nf*8 + gid;
            bfr[nf][0] = KVs[kk+tig][e];
            bfr[nf][1] = KVs[kk+tig+4][e];
        }
        if (wn) { bz[0] = KVs[kk+tig][64+gid]; bz[1] = KVs[kk+tig+4][64+gid]; }
#pragma unroll
        for (int nf = 0; nf < 4; nf++) mma8(c[nf], a, bfr[nf]);
        if (wn) mma8(cz, a, bz);
    }
    if (wn && tig == 0) {
        zbuf[wm + gid]     = 1.f/(cz[0] + 1e-6f);
        zbuf[wm + gid + 8] = 1.f/(cz[2] + 1e-6f);
    }
    __syncthreads();

    __half* ob = g_attn + ((size_t)b*NN + n0)*CC + h*DD;
#pragma unroll
    for (int nf = 0; nf < 4; nf++) {
        const int e = wn + nf*8 + 2*tig;
#pragma unroll
        for (int hf = 0; hf < 2; hf++) {
            const int row = wm + gid + 8*hf;
            const float zi = zbuf[row];
            *(__half2*)(ob + (size_t)row*CC + e) =
                __floats2half2_rn(c[nf][2*hf]*zi, c[nf][2*hf+1]*zi);
        }
    }
}

// ---------------------------------------------------------------------------
extern "C" void kernel_launch(void* const* d_in, const int* in_sizes, int n_in,
                              void* d_out, int out_size) {
    const float* x      = (const float*)d_in[0];
    const float* w_qkv  = (const float*)d_in[1];
    const float* b_qkv  = (const float*)d_in[2];
    const float* w_proj = (const float*)d_in[3];
    const float* b_proj = (const float*)d_in[4];
    float* out = (float*)d_out;

    cudaFuncSetAttribute(gemm_qkv_kernel,
        cudaFuncAttributeMaxDynamicSharedMemorySize, SMEM_PIPE_BYTES);
    cudaFuncSetAttribute(gemm_proj_kernel,
        cudaFuncAttributeMaxDynamicSharedMemorySize, SMEM_PIPE_BYTES);

    __half* wt1p; __half* wt2p;
    cudaGetSymbolAddress((void**)&wt1p, g_wt1);
    cudaGetSymbolAddress((void**)&wt2p, g_wt2);

    init_kernel<<<512, 256>>>();
    convert_x_kernel<<<16384, 256>>>(x);
    transpose_w_kernel<<<dim3(48, 16), dim3(32, 8)>>>(w_qkv, wt1p, W3);
    transpose_w_kernel<<<dim3(16, 16), dim3(32, 8)>>>(w_proj, wt2p, CC);
    gemm_qkv_kernel<<<dim3(12, 512), 256, SMEM_PIPE_BYTES>>>(b_qkv);
    kv_mma_kernel<<<dim3(32, 16), 256>>>();
    attn_mma_kernel<<<dim3(32, 256), 256>>>();
    gemm_proj_kernel<<<dim3(4, 512), 256, SMEM_PIPE_BYTES>>>(b_proj, out);
}

// round 8
// speedup vs baseline: 6.5850x; 1.1337x over previous
#include <cuda_runtime.h>
#include <cuda_fp16.h>
#include <math.h>
#include <stdint.h>

// Problem constants (shape-specialized)
#define BB 4
#define NN 16384
#define CC 512
#define HH 8
#define DD 64
#define NT (BB*NN)     // 65536 rows
#define W3 (3*CC)      // 1536

#define FREQ_COEF (-0.20762050593046014f)

// Scratch (device globals: allocation-free rule)
__device__ __half g_xh[(size_t)NT*CC];     // x as half
__device__ __half g_q[(size_t)BB*HH*NN*DD];
__device__ __half g_k[(size_t)BB*HH*NN*DD];
__device__ __half g_v[(size_t)BB*HH*NN*DD];
__device__ __half g_attn[(size_t)NT*CC];
__device__ float  g_kv[BB*HH*DD*DD];
__device__ float  g_ksum[BB*HH*DD];
__device__ float  g_trig[128*16*2];        // [pos][fi][{cos,sin}]
__device__ __half g_wt1[(size_t)W3*CC];    // w_qkv^T  [n][k] half
__device__ __half g_wt2[(size_t)CC*CC];    // w_proj^T [n][k] half

// ---------------------------------------------------------------------------
// helpers
// ---------------------------------------------------------------------------
__device__ __forceinline__ uint32_t smem_u32(const void* p) {
    uint32_t a;
    asm("{ .reg .u64 t; cvta.to.shared.u64 t, %1; cvt.u32.u64 %0, t; }"
        : "=r"(a) : "l"(p));
    return a;
}

#define CP_ASYNC_16(sa, gp) \
    asm volatile("cp.async.cg.shared.global [%0], [%1], 16;" :: "r"(sa), "l"(gp))
#define CP_ASYNC_COMMIT() asm volatile("cp.async.commit_group;" ::: "memory")
#define CP_ASYNC_WAIT1()  asm volatile("cp.async.wait_group 1;" ::: "memory")

__device__ __forceinline__ void ldsm_x4(unsigned* r, uint32_t addr) {
    asm volatile("ldmatrix.sync.aligned.m8n8.x4.shared.b16 {%0,%1,%2,%3}, [%4];"
        : "=r"(r[0]), "=r"(r[1]), "=r"(r[2]), "=r"(r[3]) : "r"(addr));
}
__device__ __forceinline__ void ldsm_x4_t(unsigned* r, uint32_t addr) {
    asm volatile("ldmatrix.sync.aligned.m8n8.x4.trans.shared.b16 {%0,%1,%2,%3}, [%4];"
        : "=r"(r[0]), "=r"(r[1]), "=r"(r[2]), "=r"(r[3]) : "r"(addr));
}

// fp16 mma m16n8k16, fp32 accumulate
__device__ __forceinline__ void mma16(float* c, const unsigned* a, const unsigned* b) {
    asm volatile(
        "mma.sync.aligned.m16n8k16.row.col.f32.f16.f16.f32 "
        "{%0,%1,%2,%3},{%4,%5,%6,%7},{%8,%9},{%0,%1,%2,%3};\n"
        : "+f"(c[0]), "+f"(c[1]), "+f"(c[2]), "+f"(c[3])
        : "r"(a[0]), "r"(a[1]), "r"(a[2]), "r"(a[3]), "r"(b[0]), "r"(b[1]));
}

// ---------------------------------------------------------------------------
// init: zero kv/ksum + trig table (runs every launch: graph replays)
// ---------------------------------------------------------------------------
__global__ void init_kernel() {
    int i = blockIdx.x * blockDim.x + threadIdx.x;
    if (i < BB*HH*DD*DD) g_kv[i] = 0.f;
    if (i < BB*HH*DD)    g_ksum[i] = 0.f;
    if (i < 128*16) {
        int pos = i >> 4, fi = i & 15;
        float freq = exp2f((float)fi * FREQ_COEF);
        float s, c;
        sincosf((float)pos * freq, &s, &c);
        g_trig[i*2]   = c;
        g_trig[i*2+1] = s;
    }
}

// ---------------------------------------------------------------------------
// convert x fp32 -> half mirror (8 elems/thread)
// ---------------------------------------------------------------------------
__global__ void convert_x_kernel(const float* __restrict__ x) {
    const size_t i = ((size_t)blockIdx.x * 256 + threadIdx.x) * 8;
    float4 a = *(const float4*)(x + i);
    float4 b = *(const float4*)(x + i + 4);
    __half2 h0 = __floats2half2_rn(a.x, a.y);
    __half2 h1 = __floats2half2_rn(a.z, a.w);
    __half2 h2 = __floats2half2_rn(b.x, b.y);
    __half2 h3 = __floats2half2_rn(b.z, b.w);
    *(uint4*)(g_xh + i) = make_uint4(*(unsigned*)&h0, *(unsigned*)&h1,
                                     *(unsigned*)&h2, *(unsigned*)&h3);
}

// ---------------------------------------------------------------------------
// Transpose weights to K-major half: src fp32 [512][N] -> dst half [N][512]
// ---------------------------------------------------------------------------
__global__ void transpose_w_kernel(const float* __restrict__ src,
                                   __half* __restrict__ dst, int N) {
    __shared__ float tile[32][33];
    const int k0 = blockIdx.y << 5, n0 = blockIdx.x << 5;
    const int tx = threadIdx.x, ty = threadIdx.y;   // 32 x 8
#pragma unroll
    for (int i = 0; i < 32; i += 8)
        tile[ty+i][tx] = src[(size_t)(k0+ty+i)*N + n0 + tx];
    __syncthreads();
#pragma unroll
    for (int i = 0; i < 32; i += 8)
        dst[(size_t)(n0+ty+i)*CC + k0 + tx] = __float2half_rn(tile[tx][ty+i]);
}

// ---------------------------------------------------------------------------
// Pipelined fp16 GEMM core (unchanged from R5): 3-stage cp.async,
// tile 128x128, warp 64x32, K=32, ldmatrix fragments.
// ---------------------------------------------------------------------------
#define STG_H 5120           // halves per stage buffer (128*40)
#define SMEM_PIPE_BYTES (6 * STG_H * 2)

__device__ __forceinline__ void issue_stage(
    uint32_t smbase, int stage, const __half* gA, const __half* gB,
    int m0, int n0, int k0, int tid)
{
    const int lrow = tid >> 1;
    const int lc8  = (tid & 1) << 4;
    const uint32_t saA = smbase + (stage*STG_H + lrow*40 + lc8)*2;
    const __half* gpA = gA + (size_t)(m0 + lrow)*CC + k0 + lc8;
    CP_ASYNC_16(saA,      gpA);
    CP_ASYNC_16(saA + 16, gpA + 8);
    const uint32_t saB = smbase + ((3 + stage)*STG_H + lrow*40 + lc8)*2;
    const __half* gpB = gB + (size_t)(n0 + lrow)*CC + k0 + lc8;
    CP_ASYNC_16(saB,      gpB);
    CP_ASYNC_16(saB + 16, gpB + 8);
}

__device__ __forceinline__ void compute_stage(
    uint32_t aBase, uint32_t bBase, int stage, float c[4][4][4])
{
    const uint32_t aS = aBase + stage*(STG_H*2);
    const uint32_t bS = bBase + stage*(STG_H*2);
#pragma unroll
    for (int kk = 0; kk < 32; kk += 16) {
        unsigned a[4][4], b[2][4];
#pragma unroll
        for (int mf = 0; mf < 4; mf++)
            ldsm_x4(a[mf], aS + (mf*16*40 + kk)*2);
#pragma unroll
        for (int p = 0; p < 2; p++)
            ldsm_x4(b[p], bS + (p*16*40 + kk)*2);
#pragma unroll
        for (int mf = 0; mf < 4; mf++)
#pragma unroll
            for (int nf = 0; nf < 4; nf++)
                mma16(c[mf][nf], a[mf], &b[nf >> 1][(nf & 1) * 2]);
    }
}

__device__ __forceinline__ uint32_t a_frag_base(uint32_t smbase, int wm, int lane) {
    return smbase + ((wm + (lane & 15))*40 + ((lane >> 4) << 3))*2;
}
__device__ __forceinline__ uint32_t b_frag_base(uint32_t smbase, int wn, int lane) {
    return smbase + 3*STG_H*2 +
        ((wn + ((lane >> 4) << 3) + (lane & 7))*40 + (((lane >> 3) & 1) << 3))*2;
}

// ---------------------------------------------------------------------------
// GEMM1: qkv = x @ w_qkv + b_qkv, fused RoPE + elu+1, scatter half q/k/v.
// ---------------------------------------------------------------------------
__global__ __launch_bounds__(256, 2) void gemm_qkv_kernel(
    const float* __restrict__ bias)
{
    extern __shared__ __half smp[];
    const uint32_t smbase = smem_u32(smp);
    const int tid  = threadIdx.x;
    const int warp = tid >> 5, lane = tid & 31;
    const int gid  = lane >> 2, tig = lane & 3;
    const int m0 = blockIdx.y << 7, n0 = blockIdx.x << 7;
    const int wm = (warp >> 2) << 6;
    const int wn = (warp & 3) << 5;

    const uint32_t aB = a_frag_base(smbase, wm, lane);
    const uint32_t bB = b_frag_base(smbase, wn, lane);

    float c[4][4][4];
#pragma unroll
    for (int i = 0; i < 4; i++)
#pragma unroll
        for (int j = 0; j < 4; j++)
#pragma unroll
            for (int r = 0; r < 4; r++) c[i][j][r] = 0.f;

    issue_stage(smbase, 0, g_xh, g_wt1, m0, n0, 0, tid);  CP_ASYNC_COMMIT();
    issue_stage(smbase, 1, g_xh, g_wt1, m0, n0, 32, tid); CP_ASYNC_COMMIT();

    for (int s = 0; s < 16; s++) {
        CP_ASYNC_WAIT1();
        __syncthreads();
        if (s + 2 < 16)
            issue_stage(smbase, (s+2)%3, g_xh, g_wt1, m0, n0, (s+2)*32, tid);
        CP_ASYNC_COMMIT();
        compute_stage(aB, bB, s%3, c);
    }

    const int sect = n0 >> 9;             // 0=q 1=k 2=v
#pragma unroll
    for (int nf = 0; nf < 4; nf++) {
        const int col = n0 + wn + nf*8 + 2*tig;
        const int h   = (col >> 6) & 7;
        const int d   = col & 63;
        const float b0v = bias[col], b1v = bias[col+1];
        const int  fi  = (d & 31) >> 1;
        const bool axx = (d < 32);
#pragma unroll
        for (int mf = 0; mf < 4; mf++) {
#pragma unroll
            for (int hf = 0; hf < 2; hf++) {
                const int r    = m0 + wm + mf*16 + gid + 8*hf;
                const int bidx = r >> 14;
                const int t    = r & (NN-1);
                float v0 = c[mf][nf][2*hf]   + b0v;
                float v1 = c[mf][nf][2*hf+1] + b1v;
                const size_t base = ((size_t)(bidx*HH + h)*NN + t)*DD + d;
                if (sect == 2) {
                    *(__half2*)(g_v + base) = __floats2half2_rn(v0, v1);
                } else {
                    const int pos = axx ? (t & 127) : (t >> 7);
                    const float2 cs = *(const float2*)(g_trig + ((pos << 4) + fi)*2);
                    float orr = v0*cs.x - v1*cs.y;
                    float oii = v0*cs.y + v1*cs.x;
                    orr = (orr > 0.f) ? orr + 1.f : __expf(orr);
                    oii = (oii > 0.f) ? oii + 1.f : __expf(oii);
                    __half* dst = (sect == 0) ? g_q : g_k;
                    *(__half2*)(dst + base) = __floats2half2_rn(orr, oii);
                }
            }
        }
    }
}

// ---------------------------------------------------------------------------
// GEMM2: out = attn @ w_proj + b_proj (attn already half)
// ---------------------------------------------------------------------------
__global__ __launch_bounds__(256, 2) void gemm_proj_kernel(
    const float* __restrict__ bias,
    float* __restrict__ out)
{
    extern __shared__ __half smp[];
    const uint32_t smbase = smem_u32(smp);
    const int tid  = threadIdx.x;
    const int warp = tid >> 5, lane = tid & 31;
    const int gid  = lane >> 2, tig = lane & 3;
    const int m0 = blockIdx.y << 7, n0 = blockIdx.x << 7;
    const int wm = (warp >> 2) << 6;
    const int wn = (warp & 3) << 5;

    const uint32_t aB = a_frag_base(smbase, wm, lane);
    const uint32_t bB = b_frag_base(smbase, wn, lane);

    float c[4][4][4];
#pragma unroll
    for (int i = 0; i < 4; i++)
#pragma unroll
        for (int j = 0; j < 4; j++)
#pragma unroll
            for (int r = 0; r < 4; r++) c[i][j][r] = 0.f;

    issue_stage(smbase, 0, g_attn, g_wt2, m0, n0, 0, tid);  CP_ASYNC_COMMIT();
    issue_stage(smbase, 1, g_attn, g_wt2, m0, n0, 32, tid); CP_ASYNC_COMMIT();

    for (int s = 0; s < 16; s++) {
        CP_ASYNC_WAIT1();
        __syncthreads();
        if (s + 2 < 16)
            issue_stage(smbase, (s+2)%3, g_attn, g_wt2, m0, n0, (s+2)*32, tid);
        CP_ASYNC_COMMIT();
        compute_stage(aB, bB, s%3, c);
    }

#pragma unroll
    for (int nf = 0; nf < 4; nf++) {
        const int col = n0 + wn + nf*8 + 2*tig;
        const float b0v = bias[col], b1v = bias[col+1];
#pragma unroll
        for (int mf = 0; mf < 4; mf++) {
#pragma unroll
            for (int hf = 0; hf < 2; hf++) {
                const int r = m0 + wm + mf*16 + gid + 8*hf;
                *(float2*)(out + (size_t)r*CC + col) =
                    make_float2(c[mf][nf][2*hf] + b0v, c[mf][nf][2*hf+1] + b1v);
            }
        }
    }
}

// ---------------------------------------------------------------------------
// kv[b,h,d,e] = sum_n k[n,d] v[n,e];  ksum via ones-column (col 64).
// fp16 mma m16n8k16, trans-ldmatrix. Warp layout: 4 d-tiles x 2 seq-slices.
// ---------------------------------------------------------------------------
#define KT_S 72   // k tile stride (halves)
#define VT_S 88   // v tile stride (halves)

__global__ __launch_bounds__(256, 2) void kv_mma_kernel() {
    __shared__ __align__(16) __half Kt[64*KT_S];
    __shared__ __align__(16) __half Vt[64*VT_S];

    const int tid  = threadIdx.x;
    const int warp = tid >> 5, lane = tid & 31;
    const int gid  = lane >> 2, tig = lane & 3;
    const int bh    = blockIdx.x;
    const int nbase = blockIdx.y << 10;
    const int d0   = (warp & 3) << 4;     // m-tile (d)
    const int srow = (warp >> 2) << 5;    // seq slice 0/32

    const uint32_t ktB = smem_u32(Kt);
    const uint32_t vtB = smem_u32(Vt);

    // ones column (e=64), zeros 65-79
    if (tid < 64) {
        Vt[tid*VT_S + 64] = __float2half(1.f);
#pragma unroll
        for (int j = 65; j < 80; j++) Vt[tid*VT_S + j] = __float2half(0.f);
    }

    float c[9][4];
#pragma unroll
    for (int t = 0; t < 9; t++)
#pragma unroll
        for (int r = 0; r < 4; r++) c[t][r] = 0.f;

    const __half* kb = g_k + (size_t)bh*NN*DD;
    const __half* vb = g_v + (size_t)bh*NN*DD;

    // trans-ldsm per-lane address offsets
    const int at_row = ((lane >> 4) << 3) + (lane & 7);          // A: seq row
    const int at_col = d0 + (((lane >> 3) & 1) << 3);            // A: d col
    const int bt_row = (((lane >> 3) & 1) << 3) + (lane & 7);    // B: seq row
    const int bt_coff = ((lane >> 4) << 3);                      // B: e col off

    for (int s = 0; s < 16; s++) {
        const int n0 = nbase + s*64;
        // load k,v tiles (64 rows x 64 halves each), 2 uint4 per thread each
#pragma unroll
        for (int i = 0; i < 2; i++) {
            const int lin = i*256 + tid;
            const int row = lin >> 3, c8 = (lin & 7) << 3;
            *(uint4*)(Kt + row*KT_S + c8) =
                *(const uint4*)(kb + (size_t)(n0 + row)*DD + c8);
            *(uint4*)(Vt + row*VT_S + c8) =
                *(const uint4*)(vb + (size_t)(n0 + row)*DD + c8);
        }
        __syncthreads();
#pragma unroll
        for (int ks = 0; ks < 2; ks++) {
            const int s16 = srow + ks*16;
            unsigned a[4], b[5][4];
            ldsm_x4_t(a, ktB + ((s16 + at_row)*KT_S + at_col)*2);
#pragma unroll
            for (int bt = 0; bt < 5; bt++)
                ldsm_x4_t(b[bt], vtB + ((s16 + bt_row)*VT_S + bt*16 + bt_coff)*2);
#pragma unroll
            for (int t = 0; t < 9; t++)
                mma16(c[t], a, &b[t >> 1][(t & 1) * 2]);
        }
        __syncthreads();
    }

    float* kvp = g_kv + bh*DD*DD;
#pragma unroll
    for (int t = 0; t < 8; t++) {
        const int e = t*8 + 2*tig;
        atomicAdd(&kvp[(d0+gid)*DD + e],       c[t][0]);
        atomicAdd(&kvp[(d0+gid)*DD + e + 1],   c[t][1]);
        atomicAdd(&kvp[(d0+gid+8)*DD + e],     c[t][2]);
        atomicAdd(&kvp[(d0+gid+8)*DD + e + 1], c[t][3]);
    }
    if (tig == 0) {
        atomicAdd(&g_ksum[bh*DD + d0 + gid],     c[8][0]);
        atomicAdd(&g_ksum[bh*DD + d0 + gid + 8], c[8][2]);
    }
}

// ---------------------------------------------------------------------------
// attn = (q @ kv) * zinv  (fp16 mma); z via ksum column 64.
// Block: 128 seq rows; warps: 2 chunks x 4 m-tiles.
// ---------------------------------------------------------------------------
#define QT_S 72

__global__ __launch_bounds__(256, 2) void attn_mma_kernel() {
    __shared__ __align__(16) __half Qt[128*QT_S];
    __shared__ __align__(16) __half KVt[64*VT_S];
    __shared__ float zbuf[128];

    const int tid  = threadIdx.x;
    const int warp = tid >> 5, lane = tid & 31;
    const int gid  = lane >> 2, tig = lane & 3;
    const int bh = blockIdx.x, b = bh >> 3, h = bh & 7;
    const int n0 = blockIdx.y << 7;
    const int m0 = ((warp >> 2) << 6) + ((warp & 3) << 4);

    const uint32_t qtB  = smem_u32(Qt);
    const uint32_t kvtB = smem_u32(KVt);

    // kv tile fp32 -> half, [64][88]
    {
        const float* kvp = g_kv + bh*DD*DD;
#pragma unroll
        for (int i = 0; i < 4; i++) {
            const int lin = i*256 + tid;         // 1024 float4 total
            const int row = lin >> 4, e4 = (lin & 15) << 2;
            float4 t = *(const float4*)(kvp + row*DD + e4);
            __half2 h0 = __floats2half2_rn(t.x, t.y);
            __half2 h1 = __floats2half2_rn(t.z, t.w);
            *(uint2*)(KVt + row*VT_S + e4) = make_uint2(*(unsigned*)&h0, *(unsigned*)&h1);
        }
        if (tid < 64) {
            KVt[tid*VT_S + 64] = __float2half_rn(g_ksum[bh*DD + tid]);
#pragma unroll
            for (int j = 65; j < 80; j++) KVt[tid*VT_S + j] = __float2half(0.f);
        }
    }
    // q tile [128][72]
    {
        const __half* qb = g_q + ((size_t)bh*NN + n0)*DD;
#pragma unroll
        for (int i = 0; i < 4; i++) {
            const int lin = i*256 + tid;         // 1024 uint4
            const int row = lin >> 3, c8 = (lin & 7) << 3;
            *(uint4*)(Qt + row*QT_S + c8) =
                *(const uint4*)(qb + (size_t)row*DD + c8);
        }
    }
    __syncthreads();

    float c[9][4];
#pragma unroll
    for (int t = 0; t < 9; t++)
#pragma unroll
        for (int r = 0; r < 4; r++) c[t][r] = 0.f;

    const int a_row = m0 + (lane & 15);
    const int a_koff = ((lane >> 4) << 3);
    const int bt_row = (((lane >> 3) & 1) << 3) + (lane & 7);
    const int bt_coff = ((lane >> 4) << 3);

#pragma unroll
    for (int kk = 0; kk < 64; kk += 16) {
        unsigned a[4], b[5][4];
        ldsm_x4(a, qtB + (a_row*QT_S + kk + a_koff)*2);
#pragma unroll
        for (int bt = 0; bt < 5; bt++)
            ldsm_x4_t(b[bt], kvtB + ((kk + bt_row)*VT_S + bt*16 + bt_coff)*2);
#pragma unroll
        for (int t = 0; t < 9; t++)
            mma16(c[t], a, &b[t >> 1][(t & 1) * 2]);
    }

    if (tig == 0) {
        zbuf[m0 + gid]     = 1.f/(c[8][0] + 1e-6f);
        zbuf[m0 + gid + 8] = 1.f/(c[8][2] + 1e-6f);
    }
    __syncthreads();

    __half* ob = g_attn + ((size_t)b*NN + n0)*CC + h*DD;
    const float zi0 = zbuf[m0 + gid];
    const float zi1 = zbuf[m0 + gid + 8];
#pragma unroll
    for (int t = 0; t < 8; t++) {
        const int e = t*8 + 2*tig;
        *(__half2*)(ob + (size_t)(m0+gid)*CC + e) =
            __floats2half2_rn(c[t][0]*zi0, c[t][1]*zi0);
        *(__half2*)(ob + (size_t)(m0+gid+8)*CC + e) =
            __floats2half2_rn(c[t][2]*zi1, c[t][3]*zi1);
    }
}

// ---------------------------------------------------------------------------
extern "C" void kernel_launch(void* const* d_in, const int* in_sizes, int n_in,
                              void* d_out, int out_size) {
    const float* x      = (const float*)d_in[0];
    const float* w_qkv  = (const float*)d_in[1];
    const float* b_qkv  = (const float*)d_in[2];
    const float* w_proj = (const float*)d_in[3];
    const float* b_proj = (const float*)d_in[4];
    float* out = (float*)d_out;

    cudaFuncSetAttribute(gemm_qkv_kernel,
        cudaFuncAttributeMaxDynamicSharedMemorySize, SMEM_PIPE_BYTES);
    cudaFuncSetAttribute(gemm_proj_kernel,
        cudaFuncAttributeMaxDynamicSharedMemorySize, SMEM_PIPE_BYTES);

    __half* wt1p; __half* wt2p;
    cudaGetSymbolAddress((void**)&wt1p, g_wt1);
    cudaGetSymbolAddress((void**)&wt2p, g_wt2);

    init_kernel<<<512, 256>>>();
    convert_x_kernel<<<16384, 256>>>(x);
    transpose_w_kernel<<<dim3(48, 16), dim3(32, 8)>>>(w_qkv, wt1p, W3);
    transpose_w_kernel<<<dim3(16, 16), dim3(32, 8)>>>(w_proj, wt2p, CC);
    gemm_qkv_kernel<<<dim3(12, 512), 256, SMEM_PIPE_BYTES>>>(b_qkv);
    kv_mma_kernel<<<dim3(32, 16), 256>>>();
    attn_mma_kernel<<<dim3(32, 128), 256>>>();
    gemm_proj_kernel<<<dim3(4, 512), 256, SMEM_PIPE_BYTES>>>(b_proj, out);
}

// round 9
// speedup vs baseline: 6.9407x; 1.0540x over previous
#include <cuda_runtime.h>
#include <cuda_fp16.h>
#include <math.h>
#include <stdint.h>

// Problem constants (shape-specialized)
#define BB 4
#define NN 16384
#define CC 512
#define HH 8
#define DD 64
#define NT (BB*NN)     // 65536 rows
#define W3 (3*CC)      // 1536

#define FREQ_COEF (-0.20762050593046014f)
#define QSCALE 1048576.0f          // 2^20
#define QSCALE_INV (1.0f/1048576.0f)

// Scratch (device globals: allocation-free rule)
__device__ __half g_xh[(size_t)NT*CC];     // x as half
__device__ __half g_q[(size_t)BB*HH*NN*DD];
__device__ __half g_k[(size_t)BB*HH*NN*DD];
__device__ __half g_v[(size_t)BB*HH*NN*DD];
__device__ __half g_attn[(size_t)NT*CC];   // holds q'' = z*q*2^20, [n][h*64+d]
__device__ float  g_kv[BB*HH*DD*DD];
__device__ float  g_ksum[BB*HH*DD];
__device__ float  g_trig[128*16*2];        // [pos][fi][{cos,sin}]
__device__ __half g_wt1[(size_t)W3*CC];    // w_qkv^T  [n][k] half
__device__ __half g_mt[(size_t)BB*CC*CC];  // M^T per b: [b][j][h*64+d] half

// ---------------------------------------------------------------------------
// helpers
// ---------------------------------------------------------------------------
__device__ __forceinline__ uint32_t smem_u32(const void* p) {
    uint32_t a;
    asm("{ .reg .u64 t; cvta.to.shared.u64 t, %1; cvt.u32.u64 %0, t; }"
        : "=r"(a) : "l"(p));
    return a;
}

#define CP_ASYNC_16(sa, gp) \
    asm volatile("cp.async.cg.shared.global [%0], [%1], 16;" :: "r"(sa), "l"(gp))
#define CP_ASYNC_COMMIT() asm volatile("cp.async.commit_group;" ::: "memory")
#define CP_ASYNC_WAIT1()  asm volatile("cp.async.wait_group 1;" ::: "memory")

__device__ __forceinline__ void ldsm_x4(unsigned* r, uint32_t addr) {
    asm volatile("ldmatrix.sync.aligned.m8n8.x4.shared.b16 {%0,%1,%2,%3}, [%4];"
        : "=r"(r[0]), "=r"(r[1]), "=r"(r[2]), "=r"(r[3]) : "r"(addr));
}
__device__ __forceinline__ void ldsm_x4_t(unsigned* r, uint32_t addr) {
    asm volatile("ldmatrix.sync.aligned.m8n8.x4.trans.shared.b16 {%0,%1,%2,%3}, [%4];"
        : "=r"(r[0]), "=r"(r[1]), "=r"(r[2]), "=r"(r[3]) : "r"(addr));
}

// fp16 mma m16n8k16, fp32 accumulate
__device__ __forceinline__ void mma16(float* c, const unsigned* a, const unsigned* b) {
    asm volatile(
        "mma.sync.aligned.m16n8k16.row.col.f32.f16.f16.f32 "
        "{%0,%1,%2,%3},{%4,%5,%6,%7},{%8,%9},{%0,%1,%2,%3};\n"
        : "+f"(c[0]), "+f"(c[1]), "+f"(c[2]), "+f"(c[3])
        : "r"(a[0]), "r"(a[1]), "r"(a[2]), "r"(a[3]), "r"(b[0]), "r"(b[1]));
}

// ---------------------------------------------------------------------------
// init: zero kv/ksum + trig table (runs every launch: graph replays)
// ---------------------------------------------------------------------------
__global__ void init_kernel() {
    int i = blockIdx.x * blockDim.x + threadIdx.x;
    if (i < BB*HH*DD*DD) g_kv[i] = 0.f;
    if (i < BB*HH*DD)    g_ksum[i] = 0.f;
    if (i < 128*16) {
        int pos = i >> 4, fi = i & 15;
        float freq = exp2f((float)fi * FREQ_COEF);
        float s, c;
        sincosf((float)pos * freq, &s, &c);
        g_trig[i*2]   = c;
        g_trig[i*2+1] = s;
    }
}

// ---------------------------------------------------------------------------
// convert x fp32 -> half mirror (8 elems/thread)
// ---------------------------------------------------------------------------
__global__ void convert_x_kernel(const float* __restrict__ x) {
    const size_t i = ((size_t)blockIdx.x * 256 + threadIdx.x) * 8;
    float4 a = *(const float4*)(x + i);
    float4 b = *(const float4*)(x + i + 4);
    __half2 h0 = __floats2half2_rn(a.x, a.y);
    __half2 h1 = __floats2half2_rn(a.z, a.w);
    __half2 h2 = __floats2half2_rn(b.x, b.y);
    __half2 h3 = __floats2half2_rn(b.z, b.w);
    *(uint4*)(g_xh + i) = make_uint4(*(unsigned*)&h0, *(unsigned*)&h1,
                                     *(unsigned*)&h2, *(unsigned*)&h3);
}

// ---------------------------------------------------------------------------
// Transpose weights to K-major half: src fp32 [512][N] -> dst half [N][512]
// ---------------------------------------------------------------------------
__global__ void transpose_w_kernel(const float* __restrict__ src,
                                   __half* __restrict__ dst, int N) {
    __shared__ float tile[32][33];
    const int k0 = blockIdx.y << 5, n0 = blockIdx.x << 5;
    const int tx = threadIdx.x, ty = threadIdx.y;   // 32 x 8
#pragma unroll
    for (int i = 0; i < 32; i += 8)
        tile[ty+i][tx] = src[(size_t)(k0+ty+i)*N + n0 + tx];
    __syncthreads();
#pragma unroll
    for (int i = 0; i < 32; i += 8)
        dst[(size_t)(n0+ty+i)*CC + k0 + tx] = __float2half_rn(tile[tx][ty+i]);
}

// ---------------------------------------------------------------------------
// Pipelined fp16 GEMM core: 3-stage cp.async, tile 128x128, warp 64x32, K=32.
// ---------------------------------------------------------------------------
#define STG_H 5120           // halves per stage buffer (128*40)
#define SMEM_PIPE_BYTES (6 * STG_H * 2)

__device__ __forceinline__ void issue_stage(
    uint32_t smbase, int stage, const __half* gA, const __half* gB,
    int m0, int n0, int k0, int tid)
{
    const int lrow = tid >> 1;
    const int lc8  = (tid & 1) << 4;
    const uint32_t saA = smbase + (stage*STG_H + lrow*40 + lc8)*2;
    const __half* gpA = gA + (size_t)(m0 + lrow)*CC + k0 + lc8;
    CP_ASYNC_16(saA,      gpA);
    CP_ASYNC_16(saA + 16, gpA + 8);
    const uint32_t saB = smbase + ((3 + stage)*STG_H + lrow*40 + lc8)*2;
    const __half* gpB = gB + (size_t)(n0 + lrow)*CC + k0 + lc8;
    CP_ASYNC_16(saB,      gpB);
    CP_ASYNC_16(saB + 16, gpB + 8);
}

__device__ __forceinline__ void compute_stage(
    uint32_t aBase, uint32_t bBase, int stage, float c[4][4][4])
{
    const uint32_t aS = aBase + stage*(STG_H*2);
    const uint32_t bS = bBase + stage*(STG_H*2);
#pragma unroll
    for (int kk = 0; kk < 32; kk += 16) {
        unsigned a[4][4], b[2][4];
#pragma unroll
        for (int mf = 0; mf < 4; mf++)
            ldsm_x4(a[mf], aS + (mf*16*40 + kk)*2);
#pragma unroll
        for (int p = 0; p < 2; p++)
            ldsm_x4(b[p], bS + (p*16*40 + kk)*2);
#pragma unroll
        for (int mf = 0; mf < 4; mf++)
#pragma unroll
            for (int nf = 0; nf < 4; nf++)
                mma16(c[mf][nf], a[mf], &b[nf >> 1][(nf & 1) * 2]);
    }
}

__device__ __forceinline__ uint32_t a_frag_base(uint32_t smbase, int wm, int lane) {
    return smbase + ((wm + (lane & 15))*40 + ((lane >> 4) << 3))*2;
}
__device__ __forceinline__ uint32_t b_frag_base(uint32_t smbase, int wn, int lane) {
    return smbase + 3*STG_H*2 +
        ((wn + ((lane >> 4) << 3) + (lane & 7))*40 + (((lane >> 3) & 1) << 3))*2;
}

// ---------------------------------------------------------------------------
// GEMM1: qkv = x @ w_qkv + b_qkv, fused RoPE + elu+1, scatter half q/k/v.
// ---------------------------------------------------------------------------
__global__ __launch_bounds__(256, 2) void gemm_qkv_kernel(
    const float* __restrict__ bias)
{
    extern __shared__ __half smp[];
    const uint32_t smbase = smem_u32(smp);
    const int tid  = threadIdx.x;
    const int warp = tid >> 5, lane = tid & 31;
    const int gid  = lane >> 2, tig = lane & 3;
    const int m0 = blockIdx.y << 7, n0 = blockIdx.x << 7;
    const int wm = (warp >> 2) << 6;
    const int wn = (warp & 3) << 5;

    const uint32_t aB = a_frag_base(smbase, wm, lane);
    const uint32_t bB = b_frag_base(smbase, wn, lane);

    float c[4][4][4];
#pragma unroll
    for (int i = 0; i < 4; i++)
#pragma unroll
        for (int j = 0; j < 4; j++)
#pragma unroll
            for (int r = 0; r < 4; r++) c[i][j][r] = 0.f;

    issue_stage(smbase, 0, g_xh, g_wt1, m0, n0, 0, tid);  CP_ASYNC_COMMIT();
    issue_stage(smbase, 1, g_xh, g_wt1, m0, n0, 32, tid); CP_ASYNC_COMMIT();

    for (int s = 0; s < 16; s++) {
        CP_ASYNC_WAIT1();
        __syncthreads();
        if (s + 2 < 16)
            issue_stage(smbase, (s+2)%3, g_xh, g_wt1, m0, n0, (s+2)*32, tid);
        CP_ASYNC_COMMIT();
        compute_stage(aB, bB, s%3, c);
    }

    const int sect = n0 >> 9;             // 0=q 1=k 2=v
#pragma unroll
    for (int nf = 0; nf < 4; nf++) {
        const int col = n0 + wn + nf*8 + 2*tig;
        const int h   = (col >> 6) & 7;
        const int d   = col & 63;
        const float b0v = bias[col], b1v = bias[col+1];
        const int  fi  = (d & 31) >> 1;
        const bool axx = (d < 32);
#pragma unroll
        for (int mf = 0; mf < 4; mf++) {
#pragma unroll
            for (int hf = 0; hf < 2; hf++) {
                const int r    = m0 + wm + mf*16 + gid + 8*hf;
                const int bidx = r >> 14;
                const int t    = r & (NN-1);
                float v0 = c[mf][nf][2*hf]   + b0v;
                float v1 = c[mf][nf][2*hf+1] + b1v;
                const size_t base = ((size_t)(bidx*HH + h)*NN + t)*DD + d;
                if (sect == 2) {
                    *(__half2*)(g_v + base) = __floats2half2_rn(v0, v1);
                } else {
                    const int pos = axx ? (t & 127) : (t >> 7);
                    const float2 cs = *(const float2*)(g_trig + ((pos << 4) + fi)*2);
                    float orr = v0*cs.x - v1*cs.y;
                    float oii = v0*cs.y + v1*cs.x;
                    orr = (orr > 0.f) ? orr + 1.f : __expf(orr);
                    oii = (oii > 0.f) ? oii + 1.f : __expf(oii);
                    __half* dst = (sect == 0) ? g_q : g_k;
                    *(__half2*)(dst + base) = __floats2half2_rn(orr, oii);
                }
            }
        }
    }
}

// ---------------------------------------------------------------------------
// GEMM2: out = q'' @ M_stack[b] * 2^-20 + b_proj
// A = g_attn (q''), B = g_mt per batch (b = blockIdx.y >> 7).
// ---------------------------------------------------------------------------
__global__ __launch_bounds__(256, 2) void gemm_proj_kernel(
    const float* __restrict__ bias,
    float* __restrict__ out)
{
    extern __shared__ __half smp[];
    const uint32_t smbase = smem_u32(smp);
    const int tid  = threadIdx.x;
    const int warp = tid >> 5, lane = tid & 31;
    const int gid  = lane >> 2, tig = lane & 3;
    const int m0 = blockIdx.y << 7, n0 = blockIdx.x << 7;
    const int wm = (warp >> 2) << 6;
    const int wn = (warp & 3) << 5;
    const __half* gB = g_mt + (size_t)(blockIdx.y >> 7)*CC*CC;

    const uint32_t aB = a_frag_base(smbase, wm, lane);
    const uint32_t bB = b_frag_base(smbase, wn, lane);

    float c[4][4][4];
#pragma unroll
    for (int i = 0; i < 4; i++)
#pragma unroll
        for (int j = 0; j < 4; j++)
#pragma unroll
            for (int r = 0; r < 4; r++) c[i][j][r] = 0.f;

    issue_stage(smbase, 0, g_attn, gB, m0, n0, 0, tid);  CP_ASYNC_COMMIT();
    issue_stage(smbase, 1, g_attn, gB, m0, n0, 32, tid); CP_ASYNC_COMMIT();

    for (int s = 0; s < 16; s++) {
        CP_ASYNC_WAIT1();
        __syncthreads();
        if (s + 2 < 16)
            issue_stage(smbase, (s+2)%3, g_attn, gB, m0, n0, (s+2)*32, tid);
        CP_ASYNC_COMMIT();
        compute_stage(aB, bB, s%3, c);
    }

#pragma unroll
    for (int nf = 0; nf < 4; nf++) {
        const int col = n0 + wn + nf*8 + 2*tig;
        const float b0v = bias[col], b1v = bias[col+1];
#pragma unroll
        for (int mf = 0; mf < 4; mf++) {
#pragma unroll
            for (int hf = 0; hf < 2; hf++) {
                const int r = m0 + wm + mf*16 + gid + 8*hf;
                *(float2*)(out + (size_t)r*CC + col) =
                    make_float2(c[mf][nf][2*hf]*QSCALE_INV + b0v,
                                c[mf][nf][2*hf+1]*QSCALE_INV + b1v);
            }
        }
    }
}

// ---------------------------------------------------------------------------
// kv[b,h,d,e] = sum_n k[n,d] v[n,e];  ksum via ones-column (col 64).
// fp16 mma, trans-ldmatrix, 3-stage cp.async pipeline.
// ---------------------------------------------------------------------------
#define KT_S 72   // k tile stride (halves)
#define VT_S 88   // v tile stride (halves)
#define KV_STG_H (64*KT_S + 64*VT_S)     // 10240 halves per stage
#define KV_SMEM_BYTES (3 * KV_STG_H * 2) // 61440

__device__ __forceinline__ void kv_issue(
    uint32_t smbase, int stage, const __half* kb, const __half* vb,
    int n0, int tid)
{
    const uint32_t stB = smbase + stage*(KV_STG_H*2);
#pragma unroll
    for (int i = 0; i < 2; i++) {
        const int lin = i*256 + tid;
        const int row = lin >> 3, c8 = (lin & 7) << 3;
        CP_ASYNC_16(stB + (row*KT_S + c8)*2,
                    kb + (size_t)(n0 + row)*DD + c8);
        CP_ASYNC_16(stB + (64*KT_S + row*VT_S + c8)*2,
                    vb + (size_t)(n0 + row)*DD + c8);
    }
}

__global__ __launch_bounds__(256, 2) void kv_mma_kernel() {
    extern __shared__ __half kvsm[];
    const uint32_t smbase = smem_u32(kvsm);

    const int tid  = threadIdx.x;
    const int warp = tid >> 5, lane = tid & 31;
    const int gid  = lane >> 2, tig = lane & 3;
    const int bh    = blockIdx.x;
    const int nbase = blockIdx.y << 10;
    const int d0   = (warp & 3) << 4;     // m-tile (d)
    const int srow = (warp >> 2) << 5;    // seq slice 0/32

    // ones column (e=64), zeros 65-79, in all 3 stage buffers
    if (tid < 64) {
#pragma unroll
        for (int st = 0; st < 3; st++) {
            __half* Vt = kvsm + st*KV_STG_H + 64*KT_S;
            Vt[tid*VT_S + 64] = __float2half(1.f);
#pragma unroll
            for (int j = 65; j < 80; j++) Vt[tid*VT_S + j] = __float2half(0.f);
        }
    }
    __syncthreads();

    float c[9][4];
#pragma unroll
    for (int t = 0; t < 9; t++)
#pragma unroll
        for (int r = 0; r < 4; r++) c[t][r] = 0.f;

    const __half* kb = g_k + (size_t)bh*NN*DD;
    const __half* vb = g_v + (size_t)bh*NN*DD;

    const int at_row = ((lane >> 4) << 3) + (lane & 7);
    const int at_col = d0 + (((lane >> 3) & 1) << 3);
    const int bt_row = (((lane >> 3) & 1) << 3) + (lane & 7);
    const int bt_coff = ((lane >> 4) << 3);

    kv_issue(smbase, 0, kb, vb, nbase, tid);       CP_ASYNC_COMMIT();
    kv_issue(smbase, 1, kb, vb, nbase + 64, tid);  CP_ASYNC_COMMIT();

    for (int s = 0; s < 16; s++) {
        CP_ASYNC_WAIT1();
        __syncthreads();
        if (s + 2 < 16)
            kv_issue(smbase, (s+2)%3, kb, vb, nbase + (s+2)*64, tid);
        CP_ASYNC_COMMIT();
        const uint32_t ktB = smbase + (s%3)*(KV_STG_H*2);
        const uint32_t vtB = ktB + 64*KT_S*2;
#pragma unroll
        for (int ks = 0; ks < 2; ks++) {
            const int s16 = srow + ks*16;
            unsigned a[4], b[5][4];
            ldsm_x4_t(a, ktB + ((s16 + at_row)*KT_S + at_col)*2);
#pragma unroll
            for (int bt = 0; bt < 5; bt++)
                ldsm_x4_t(b[bt], vtB + ((s16 + bt_row)*VT_S + bt*16 + bt_coff)*2);
#pragma unroll
            for (int t = 0; t < 9; t++)
                mma16(c[t], a, &b[t >> 1][(t & 1) * 2]);
        }
    }

    float* kvp = g_kv + bh*DD*DD;
#pragma unroll
    for (int t = 0; t < 8; t++) {
        const int e = t*8 + 2*tig;
        atomicAdd(&kvp[(d0+gid)*DD + e],       c[t][0]);
        atomicAdd(&kvp[(d0+gid)*DD + e + 1],   c[t][1]);
        atomicAdd(&kvp[(d0+gid+8)*DD + e],     c[t][2]);
        atomicAdd(&kvp[(d0+gid+8)*DD + e + 1], c[t][3]);
    }
    if (tig == 0) {
        atomicAdd(&g_ksum[bh*DD + d0 + gid],     c[8][0]);
        atomicAdd(&g_ksum[bh*DD + d0 + gid + 8], c[8][2]);
    }
}

// ---------------------------------------------------------------------------
// M^T[b][j][h*64+d] = sum_e kv[b,h,d,e] * w_proj[h*64+e, j]   (half out)
// grid (4 b, 8 h, 8 j-chunks), block 256.
// ---------------------------------------------------------------------------
__global__ __launch_bounds__(256) void m_precompute_kernel(
    const float* __restrict__ w_proj)
{
    __shared__ float kvs[64][65];
    __shared__ float ws[64][65];
    const int b = blockIdx.x, h = blockIdx.y, j0 = blockIdx.z << 6;
    const int tid = threadIdx.x;
    const float* kvp = g_kv + ((b*HH + h)*DD*DD);

#pragma unroll
    for (int i = 0; i < 16; i++) {
        const int lin = i*256 + tid;          // 4096
        const int r = lin >> 6, cidx = lin & 63;
        kvs[r][cidx] = kvp[r*DD + cidx];
        ws[r][cidx]  = w_proj[(size_t)(h*DD + r)*CC + j0 + cidx];
    }
    __syncthreads();

    const int d = tid & 63;
    const int jg = tid >> 6;                  // 0..3
#pragma unroll
    for (int jj = 0; jj < 16; jj++) {
        const int j = jg*16 + jj;
        float acc = 0.f;
#pragma unroll
        for (int e = 0; e < 64; e++)
            acc = fmaf(kvs[d][e], ws[e][j], acc);
        g_mt[((size_t)b*CC + j0 + j)*CC + h*DD + d] = __float2half_rn(acc);
    }
}

// ---------------------------------------------------------------------------
// q''[b*NN+n][h*64+d] = q[b,h,n,d] * 2^20 / (q[b,h,n,:].ksum[b,h,:] + 1e-6)
// grid (32 bh, 512), block 256: 32 rows/block, 8 threads/row.
// ---------------------------------------------------------------------------
__global__ __launch_bounds__(256) void zq_kernel() {
    const int bh = blockIdx.x, b = bh >> 3, h = bh & 7;
    const int tid = threadIdx.x;
    const int r8 = tid >> 3;            // row in chunk 0..31
    const int t8 = tid & 7;             // 0..7
    const int n  = (blockIdx.y << 5) + r8;

    uint4 u = *(const uint4*)(g_q + ((size_t)bh*NN + n)*DD + t8*8);
    float f[8];
    {
        __half2* hp = (__half2*)&u;
#pragma unroll
        for (int i = 0; i < 4; i++) {
            float2 t = __half22float2(hp[i]);
            f[2*i] = t.x; f[2*i+1] = t.y;
        }
    }
    const float* ks = g_ksum + bh*DD + t8*8;
    float dot = 0.f;
#pragma unroll
    for (int i = 0; i < 8; i++) dot = fmaf(f[i], ks[i], dot);
    dot += __shfl_xor_sync(0xffffffffu, dot, 1);
    dot += __shfl_xor_sync(0xffffffffu, dot, 2);
    dot += __shfl_xor_sync(0xffffffffu, dot, 4);
    const float z = QSCALE / (dot + 1e-6f);

    __half2 o[4];
#pragma unroll
    for (int i = 0; i < 4; i++)
        o[i] = __floats2half2_rn(f[2*i]*z, f[2*i+1]*z);
    *(uint4*)(g_attn + ((size_t)b*NN + n)*CC + h*DD + t8*8) =
        *(uint4*)o;
}

// ---------------------------------------------------------------------------
extern "C" void kernel_launch(void* const* d_in, const int* in_sizes, int n_in,
                              void* d_out, int out_size) {
    const float* x      = (const float*)d_in[0];
    const float* w_qkv  = (const float*)d_in[1];
    const float* b_qkv  = (const float*)d_in[2];
    const float* w_proj = (const float*)d_in[3];
    const float* b_proj = (const float*)d_in[4];
    float* out = (float*)d_out;

    cudaFuncSetAttribute(gemm_qkv_kernel,
        cudaFuncAttributeMaxDynamicSharedMemorySize, SMEM_PIPE_BYTES);
    cudaFuncSetAttribute(gemm_proj_kernel,
        cudaFuncAttributeMaxDynamicSharedMemorySize, SMEM_PIPE_BYTES);
    cudaFuncSetAttribute(kv_mma_kernel,
        cudaFuncAttributeMaxDynamicSharedMemorySize, KV_SMEM_BYTES);

    __half* wt1p;
    cudaGetSymbolAddress((void**)&wt1p, g_wt1);

    init_kernel<<<512, 256>>>();
    convert_x_kernel<<<16384, 256>>>(x);
    transpose_w_kernel<<<dim3(48, 16), dim3(32, 8)>>>(w_qkv, wt1p, W3);
    gemm_qkv_kernel<<<dim3(12, 512), 256, SMEM_PIPE_BYTES>>>(b_qkv);
    kv_mma_kernel<<<dim3(32, 16), 256, KV_SMEM_BYTES>>>();
    m_precompute_kernel<<<dim3(4, 8, 8), 256>>>(w_proj);
    zq_kernel<<<dim3(32, 512), 256>>>();
    gemm_proj_kernel<<<dim3(4, 512), 256, SMEM_PIPE_BYTES>>>(b_proj, out);
}

// round 10
// speedup vs baseline: 7.0995x; 1.0229x over previous
#include <cuda_runtime.h>
#include <cuda_fp16.h>
#include <math.h>
#include <stdint.h>

// Problem constants (shape-specialized)
#define BB 4
#define NN 16384
#define CC 512
#define HH 8
#define DD 64
#define NT (BB*NN)     // 65536 rows
#define W3 (3*CC)      // 1536

#define FREQ_COEF (-0.20762050593046014f)
#define QSCALE 1048576.0f          // 2^20
#define QSCALE_INV (1.0f/1048576.0f)

// Scratch (device globals: allocation-free rule)
__device__ __half g_xh[(size_t)NT*CC];     // x as half
__device__ __half g_q[(size_t)BB*HH*NN*DD];
__device__ __half g_k[(size_t)BB*HH*NN*DD];
__device__ __half g_v[(size_t)BB*HH*NN*DD];
__device__ __half g_attn[(size_t)NT*CC];   // holds q'' = z*q*2^20, [n][h*64+d]
__device__ float  g_kv[BB*HH*DD*DD];
__device__ float  g_ksum[BB*HH*DD];
__device__ float  g_trig[128*16*2];        // [pos][fi][{cos,sin}]
__device__ __half g_wt1[(size_t)W3*CC];    // w_qkv^T  [n][k] half
__device__ __half g_mt[(size_t)BB*CC*CC];  // M^T per b: [b][j][h*64+d] half

// ---------------------------------------------------------------------------
// helpers
// ---------------------------------------------------------------------------
__device__ __forceinline__ uint32_t smem_u32(const void* p) {
    uint32_t a;
    asm("{ .reg .u64 t; cvta.to.shared.u64 t, %1; cvt.u32.u64 %0, t; }"
        : "=r"(a) : "l"(p));
    return a;
}

#define CP_ASYNC_16(sa, gp) \
    asm volatile("cp.async.cg.shared.global [%0], [%1], 16;" :: "r"(sa), "l"(gp))
#define CP_ASYNC_COMMIT() asm volatile("cp.async.commit_group;" ::: "memory")
#define CP_ASYNC_WAIT1()  asm volatile("cp.async.wait_group 1;" ::: "memory")

__device__ __forceinline__ void ldsm_x4(unsigned* r, uint32_t addr) {
    asm volatile("ldmatrix.sync.aligned.m8n8.x4.shared.b16 {%0,%1,%2,%3}, [%4];"
        : "=r"(r[0]), "=r"(r[1]), "=r"(r[2]), "=r"(r[3]) : "r"(addr));
}
__device__ __forceinline__ void ldsm_x4_t(unsigned* r, uint32_t addr) {
    asm volatile("ldmatrix.sync.aligned.m8n8.x4.trans.shared.b16 {%0,%1,%2,%3}, [%4];"
        : "=r"(r[0]), "=r"(r[1]), "=r"(r[2]), "=r"(r[3]) : "r"(addr));
}

// fp16 mma m16n8k16, fp32 accumulate
__device__ __forceinline__ void mma16(float* c, const unsigned* a, const unsigned* b) {
    asm volatile(
        "mma.sync.aligned.m16n8k16.row.col.f32.f16.f16.f32 "
        "{%0,%1,%2,%3},{%4,%5,%6,%7},{%8,%9},{%0,%1,%2,%3};\n"
        : "+f"(c[0]), "+f"(c[1]), "+f"(c[2]), "+f"(c[3])
        : "r"(a[0]), "r"(a[1]), "r"(a[2]), "r"(a[3]), "r"(b[0]), "r"(b[1]));
}

// ---------------------------------------------------------------------------
// init: zero kv/ksum + trig table (runs every launch: graph replays)
// ---------------------------------------------------------------------------
__global__ void init_kernel() {
    int i = blockIdx.x * blockDim.x + threadIdx.x;
    if (i < BB*HH*DD*DD) g_kv[i] = 0.f;
    if (i < BB*HH*DD)    g_ksum[i] = 0.f;
    if (i < 128*16) {
        int pos = i >> 4, fi = i & 15;
        float freq = exp2f((float)fi * FREQ_COEF);
        float s, c;
        sincosf((float)pos * freq, &s, &c);
        g_trig[i*2]   = c;
        g_trig[i*2+1] = s;
    }
}

// ---------------------------------------------------------------------------
// convert x fp32 -> half mirror (8 elems/thread)
// ---------------------------------------------------------------------------
__global__ void convert_x_kernel(const float* __restrict__ x) {
    const size_t i = ((size_t)blockIdx.x * 256 + threadIdx.x) * 8;
    float4 a = *(const float4*)(x + i);
    float4 b = *(const float4*)(x + i + 4);
    __half2 h0 = __floats2half2_rn(a.x, a.y);
    __half2 h1 = __floats2half2_rn(a.z, a.w);
    __half2 h2 = __floats2half2_rn(b.x, b.y);
    __half2 h3 = __floats2half2_rn(b.z, b.w);
    *(uint4*)(g_xh + i) = make_uint4(*(unsigned*)&h0, *(unsigned*)&h1,
                                     *(unsigned*)&h2, *(unsigned*)&h3);
}

// ---------------------------------------------------------------------------
// Transpose weights to K-major half: src fp32 [512][N] -> dst half [N][512]
// ---------------------------------------------------------------------------
__global__ void transpose_w_kernel(const float* __restrict__ src,
                                   __half* __restrict__ dst, int N) {
    __shared__ float tile[32][33];
    const int k0 = blockIdx.y << 5, n0 = blockIdx.x << 5;
    const int tx = threadIdx.x, ty = threadIdx.y;   // 32 x 8
#pragma unroll
    for (int i = 0; i < 32; i += 8)
        tile[ty+i][tx] = src[(size_t)(k0+ty+i)*N + n0 + tx];
    __syncthreads();
#pragma unroll
    for (int i = 0; i < 32; i += 8)
        dst[(size_t)(n0+ty+i)*CC + k0 + tx] = __float2half_rn(tile[tx][ty+i]);
}

// ---------------------------------------------------------------------------
// Pipelined fp16 GEMM core: 3-stage cp.async, tile 128x128, warp 64x32, K=64.
// Stage buffer: A [128][72] + B [128][72] halves = 36864 B; 3 stages = 110592.
// Stride 72 halves (36 words): LDSM rows step 4 banks -> conflict-free.
// ---------------------------------------------------------------------------
#define TIL_H 9216             // halves per tile (128*72)
#define STG_H (2*TIL_H)        // halves per stage (A+B)
#define SMEM_PIPE_BYTES (3 * STG_H * 2)   // 110592

__device__ __forceinline__ void issue_stage(
    uint32_t smbase, int stage, const __half* gA, const __half* gB,
    int m0, int n0, int k0, int tid)
{
    const uint32_t stB = smbase + stage*(STG_H*2);
#pragma unroll
    for (int i = 0; i < 4; i++) {
        const int lin = i*256 + tid;          // 1024 chunks per tile
        const int row = lin >> 3;
        const int c8  = (lin & 7) << 3;       // halves
        CP_ASYNC_16(stB + (row*72 + c8)*2,
                    gA + (size_t)(m0 + row)*CC + k0 + c8);
        CP_ASYNC_16(stB + (TIL_H + row*72 + c8)*2,
                    gB + (size_t)(n0 + row)*CC + k0 + c8);
    }
}

__device__ __forceinline__ void compute_stage(
    uint32_t aBase, uint32_t bBase, int stage, float c[4][4][4])
{
    const uint32_t aS = aBase + stage*(STG_H*2);
    const uint32_t bS = bBase + stage*(STG_H*2);
#pragma unroll
    for (int kk = 0; kk < 64; kk += 16) {
        unsigned a[4][4], b[2][4];
#pragma unroll
        for (int mf = 0; mf < 4; mf++)
            ldsm_x4(a[mf], aS + (mf*16*72 + kk)*2);
#pragma unroll
        for (int p = 0; p < 2; p++)
            ldsm_x4(b[p], bS + (p*16*72 + kk)*2);
#pragma unroll
        for (int mf = 0; mf < 4; mf++)
#pragma unroll
            for (int nf = 0; nf < 4; nf++)
                mma16(c[mf][nf], a[mf], &b[nf >> 1][(nf & 1) * 2]);
    }
}

__device__ __forceinline__ uint32_t a_frag_base(uint32_t smbase, int wm, int lane) {
    return smbase + ((wm + (lane & 15))*72 + ((lane >> 4) << 3))*2;
}
__device__ __forceinline__ uint32_t b_frag_base(uint32_t smbase, int wn, int lane) {
    return smbase + TIL_H*2 +
        ((wn + ((lane >> 4) << 3) + (lane & 7))*72 + (((lane >> 3) & 1) << 3))*2;
}

// ---------------------------------------------------------------------------
// GEMM1: qkv = x @ w_qkv + b_qkv, fused RoPE + elu+1, scatter half q/k/v.
// 8 K-stages of 64.
// ---------------------------------------------------------------------------
__global__ __launch_bounds__(256, 2) void gemm_qkv_kernel(
    const float* __restrict__ bias)
{
    extern __shared__ __half smp[];
    const uint32_t smbase = smem_u32(smp);
    const int tid  = threadIdx.x;
    const int warp = tid >> 5, lane = tid & 31;
    const int gid  = lane >> 2, tig = lane & 3;
    const int m0 = blockIdx.y << 7, n0 = blockIdx.x << 7;
    const int wm = (warp >> 2) << 6;
    const int wn = (warp & 3) << 5;

    const uint32_t aB = a_frag_base(smbase, wm, lane);
    const uint32_t bB = b_frag_base(smbase, wn, lane);

    float c[4][4][4];
#pragma unroll
    for (int i = 0; i < 4; i++)
#pragma unroll
        for (int j = 0; j < 4; j++)
#pragma unroll
            for (int r = 0; r < 4; r++) c[i][j][r] = 0.f;

    issue_stage(smbase, 0, g_xh, g_wt1, m0, n0, 0, tid);  CP_ASYNC_COMMIT();
    issue_stage(smbase, 1, g_xh, g_wt1, m0, n0, 64, tid); CP_ASYNC_COMMIT();

    for (int s = 0; s < 8; s++) {
        CP_ASYNC_WAIT1();
        __syncthreads();
        if (s + 2 < 8)
            issue_stage(smbase, (s+2)%3, g_xh, g_wt1, m0, n0, (s+2)*64, tid);
        CP_ASYNC_COMMIT();
        compute_stage(aB, bB, s%3, c);
    }

    const int sect = n0 >> 9;             // 0=q 1=k 2=v
#pragma unroll
    for (int nf = 0; nf < 4; nf++) {
        const int col = n0 + wn + nf*8 + 2*tig;
        const int h   = (col >> 6) & 7;
        const int d   = col & 63;
        const float b0v = bias[col], b1v = bias[col+1];
        const int  fi  = (d & 31) >> 1;
        const bool axx = (d < 32);
#pragma unroll
        for (int mf = 0; mf < 4; mf++) {
#pragma unroll
            for (int hf = 0; hf < 2; hf++) {
                const int r    = m0 + wm + mf*16 + gid + 8*hf;
                const int bidx = r >> 14;
                const int t    = r & (NN-1);
                float v0 = c[mf][nf][2*hf]   + b0v;
                float v1 = c[mf][nf][2*hf+1] + b1v;
                const size_t base = ((size_t)(bidx*HH + h)*NN + t)*DD + d;
                if (sect == 2) {
                    *(__half2*)(g_v + base) = __floats2half2_rn(v0, v1);
                } else {
                    const int pos = axx ? (t & 127) : (t >> 7);
                    const float2 cs = *(const float2*)(g_trig + ((pos << 4) + fi)*2);
                    float orr = v0*cs.x - v1*cs.y;
                    float oii = v0*cs.y + v1*cs.x;
                    orr = (orr > 0.f) ? orr + 1.f : __expf(orr);
                    oii = (oii > 0.f) ? oii + 1.f : __expf(oii);
                    __half* dst = (sect == 0) ? g_q : g_k;
                    *(__half2*)(dst + base) = __floats2half2_rn(orr, oii);
                }
            }
        }
    }
}

// ---------------------------------------------------------------------------
// GEMM2: out = q'' @ M_stack[b] * 2^-20 + b_proj
// ---------------------------------------------------------------------------
__global__ __launch_bounds__(256, 2) void gemm_proj_kernel(
    const float* __restrict__ bias,
    float* __restrict__ out)
{
    extern __shared__ __half smp[];
    const uint32_t smbase = smem_u32(smp);
    const int tid  = threadIdx.x;
    const int warp = tid >> 5, lane = tid & 31;
    const int gid  = lane >> 2, tig = lane & 3;
    const int m0 = blockIdx.y << 7, n0 = blockIdx.x << 7;
    const int wm = (warp >> 2) << 6;
    const int wn = (warp & 3) << 5;
    const __half* gB = g_mt + (size_t)(blockIdx.y >> 7)*CC*CC;

    const uint32_t aB = a_frag_base(smbase, wm, lane);
    const uint32_t bB = b_frag_base(smbase, wn, lane);

    float c[4][4][4];
#pragma unroll
    for (int i = 0; i < 4; i++)
#pragma unroll
        for (int j = 0; j < 4; j++)
#pragma unroll
            for (int r = 0; r < 4; r++) c[i][j][r] = 0.f;

    issue_stage(smbase, 0, g_attn, gB, m0, n0, 0, tid);  CP_ASYNC_COMMIT();
    issue_stage(smbase, 1, g_attn, gB, m0, n0, 64, tid); CP_ASYNC_COMMIT();

    for (int s = 0; s < 8; s++) {
        CP_ASYNC_WAIT1();
        __syncthreads();
        if (s + 2 < 8)
            issue_stage(smbase, (s+2)%3, g_attn, gB, m0, n0, (s+2)*64, tid);
        CP_ASYNC_COMMIT();
        compute_stage(aB, bB, s%3, c);
    }

#pragma unroll
    for (int nf = 0; nf < 4; nf++) {
        const int col = n0 + wn + nf*8 + 2*tig;
        const float b0v = bias[col], b1v = bias[col+1];
#pragma unroll
        for (int mf = 0; mf < 4; mf++) {
#pragma unroll
            for (int hf = 0; hf < 2; hf++) {
                const int r = m0 + wm + mf*16 + gid + 8*hf;
                *(float2*)(out + (size_t)r*CC + col) =
                    make_float2(c[mf][nf][2*hf]*QSCALE_INV + b0v,
                                c[mf][nf][2*hf+1]*QSCALE_INV + b1v);
            }
        }
    }
}

// ---------------------------------------------------------------------------
// kv[b,h,d,e] = sum_n k[n,d] v[n,e];  ksum via ones-column (col 64).
// fp16 mma, trans-ldmatrix, 3-stage cp.async pipeline.
// ---------------------------------------------------------------------------
#define KT_S 72   // k tile stride (halves)
#define VT_S 88   // v tile stride (halves)
#define KV_STG_H (64*KT_S + 64*VT_S)     // 10240 halves per stage
#define KV_SMEM_BYTES (3 * KV_STG_H * 2) // 61440

__device__ __forceinline__ void kv_issue(
    uint32_t smbase, int stage, const __half* kb, const __half* vb,
    int n0, int tid)
{
    const uint32_t stB = smbase + stage*(KV_STG_H*2);
#pragma unroll
    for (int i = 0; i < 2; i++) {
        const int lin = i*256 + tid;
        const int row = lin >> 3, c8 = (lin & 7) << 3;
        CP_ASYNC_16(stB + (row*KT_S + c8)*2,
                    kb + (size_t)(n0 + row)*DD + c8);
        CP_ASYNC_16(stB + (64*KT_S + row*VT_S + c8)*2,
                    vb + (size_t)(n0 + row)*DD + c8);
    }
}

__global__ __launch_bounds__(256, 2) void kv_mma_kernel() {
    extern __shared__ __half kvsm[];
    const uint32_t smbase = smem_u32(kvsm);

    const int tid  = threadIdx.x;
    const int warp = tid >> 5, lane = tid & 31;
    const int gid  = lane >> 2, tig = lane & 3;
    const int bh    = blockIdx.x;
    const int nbase = blockIdx.y << 10;
    const int d0   = (warp & 3) << 4;     // m-tile (d)
    const int srow = (warp >> 2) << 5;    // seq slice 0/32

    if (tid < 64) {
#pragma unroll
        for (int st = 0; st < 3; st++) {
            __half* Vt = kvsm + st*KV_STG_H + 64*KT_S;
            Vt[tid*VT_S + 64] = __float2half(1.f);
#pragma unroll
            for (int j = 65; j < 80; j++) Vt[tid*VT_S + j] = __float2half(0.f);
        }
    }
    __syncthreads();

    float c[9][4];
#pragma unroll
    for (int t = 0; t < 9; t++)
#pragma unroll
        for (int r = 0; r < 4; r++) c[t][r] = 0.f;

    const __half* kb = g_k + (size_t)bh*NN*DD;
    const __half* vb = g_v + (size_t)bh*NN*DD;

    const int at_row = ((lane >> 4) << 3) + (lane & 7);
    const int at_col = d0 + (((lane >> 3) & 1) << 3);
    const int bt_row = (((lane >> 3) & 1) << 3) + (lane & 7);
    const int bt_coff = ((lane >> 4) << 3);

    kv_issue(smbase, 0, kb, vb, nbase, tid);       CP_ASYNC_COMMIT();
    kv_issue(smbase, 1, kb, vb, nbase + 64, tid);  CP_ASYNC_COMMIT();

    for (int s = 0; s < 16; s++) {
        CP_ASYNC_WAIT1();
        __syncthreads();
        if (s + 2 < 16)
            kv_issue(smbase, (s+2)%3, kb, vb, nbase + (s+2)*64, tid);
        CP_ASYNC_COMMIT();
        const uint32_t ktB = smbase + (s%3)*(KV_STG_H*2);
        const uint32_t vtB = ktB + 64*KT_S*2;
#pragma unroll
        for (int ks = 0; ks < 2; ks++) {
            const int s16 = srow + ks*16;
            unsigned a[4], b[5][4];
            ldsm_x4_t(a, ktB + ((s16 + at_row)*KT_S + at_col)*2);
#pragma unroll
            for (int bt = 0; bt < 5; bt++)
                ldsm_x4_t(b[bt], vtB + ((s16 + bt_row)*VT_S + bt*16 + bt_coff)*2);
#pragma unroll
            for (int t = 0; t < 9; t++)
                mma16(c[t], a, &b[t >> 1][(t & 1) * 2]);
        }
    }

    float* kvp = g_kv + bh*DD*DD;
#pragma unroll
    for (int t = 0; t < 8; t++) {
        const int e = t*8 + 2*tig;
        atomicAdd(&kvp[(d0+gid)*DD + e],       c[t][0]);
        atomicAdd(&kvp[(d0+gid)*DD + e + 1],   c[t][1]);
        atomicAdd(&kvp[(d0+gid+8)*DD + e],     c[t][2]);
        atomicAdd(&kvp[(d0+gid+8)*DD + e + 1], c[t][3]);
    }
    if (tig == 0) {
        atomicAdd(&g_ksum[bh*DD + d0 + gid],     c[8][0]);
        atomicAdd(&g_ksum[bh*DD + d0 + gid + 8], c[8][2]);
    }
}

// ---------------------------------------------------------------------------
// M^T[b][j][h*64+d] = sum_e kv[b,h,d,e] * w_proj[h*64+e, j]   (half out)
// ---------------------------------------------------------------------------
__global__ __launch_bounds__(256) void m_precompute_kernel(
    const float* __restrict__ w_proj)
{
    __shared__ float kvs[64][65];
    __shared__ float ws[64][65];
    const int b = blockIdx.x, h = blockIdx.y, j0 = blockIdx.z << 6;
    const int tid = threadIdx.x;
    const float* kvp = g_kv + ((b*HH + h)*DD*DD);

#pragma unroll
    for (int i = 0; i < 16; i++) {
        const int lin = i*256 + tid;          // 4096
        const int r = lin >> 6, cidx = lin & 63;
        kvs[r][cidx] = kvp[r*DD + cidx];
        ws[r][cidx]  = w_proj[(size_t)(h*DD + r)*CC + j0 + cidx];
    }
    __syncthreads();

    const int d = tid & 63;
    const int jg = tid >> 6;                  // 0..3
#pragma unroll
    for (int jj = 0; jj < 16; jj++) {
        const int j = jg*16 + jj;
        float acc = 0.f;
#pragma unroll
        for (int e = 0; e < 64; e++)
            acc = fmaf(kvs[d][e], ws[e][j], acc);
        g_mt[((size_t)b*CC + j0 + j)*CC + h*DD + d] = __float2half_rn(acc);
    }
}

// ---------------------------------------------------------------------------
// q''[b*NN+n][h*64+d] = q[b,h,n,d] * 2^20 / (q.ksum + 1e-6)
// ---------------------------------------------------------------------------
__global__ __launch_bounds__(256) void zq_kernel() {
    const int bh = blockIdx.x, b = bh >> 3, h = bh & 7;
    const int tid = threadIdx.x;
    const int r8 = tid >> 3;
    const int t8 = tid & 7;
    const int n  = (blockIdx.y << 5) + r8;

    uint4 u = *(const uint4*)(g_q + ((size_t)bh*NN + n)*DD + t8*8);
    float f[8];
    {
        __half2* hp = (__half2*)&u;
#pragma unroll
        for (int i = 0; i < 4; i++) {
            float2 t = __half22float2(hp[i]);
            f[2*i] = t.x; f[2*i+1] = t.y;
        }
    }
    const float* ks = g_ksum + bh*DD + t8*8;
    float dot = 0.f;
#pragma unroll
    for (int i = 0; i < 8; i++) dot = fmaf(f[i], ks[i], dot);
    dot += __shfl_xor_sync(0xffffffffu, dot, 1);
    dot += __shfl_xor_sync(0xffffffffu, dot, 2);
    dot += __shfl_xor_sync(0xffffffffu, dot, 4);
    const float z = QSCALE / (dot + 1e-6f);

    __half2 o[4];
#pragma unroll
    for (int i = 0; i < 4; i++)
        o[i] = __floats2half2_rn(f[2*i]*z, f[2*i+1]*z);
    *(uint4*)(g_attn + ((size_t)b*NN + n)*CC + h*DD + t8*8) =
        *(uint4*)o;
}

// ---------------------------------------------------------------------------
extern "C" void kernel_launch(void* const* d_in, const int* in_sizes, int n_in,
                              void* d_out, int out_size) {
    const float* x      = (const float*)d_in[0];
    const float* w_qkv  = (const float*)d_in[1];
    const float* b_qkv  = (const float*)d_in[2];
    const float* w_proj = (const float*)d_in[3];
    const float* b_proj = (const float*)d_in[4];
    float* out = (float*)d_out;

    cudaFuncSetAttribute(gemm_qkv_kernel,
        cudaFuncAttributeMaxDynamicSharedMemorySize, SMEM_PIPE_BYTES);
    cudaFuncSetAttribute(gemm_proj_kernel,
        cudaFuncAttributeMaxDynamicSharedMemorySize, SMEM_PIPE_BYTES);
    cudaFuncSetAttribute(kv_mma_kernel,
        cudaFuncAttributeMaxDynamicSharedMemorySize, KV_SMEM_BYTES);

    __half* wt1p;
    cudaGetSymbolAddress((void**)&wt1p, g_wt1);

    init_kernel<<<512, 256>>>();
    convert_x_kernel<<<16384, 256>>>(x);
    transpose_w_kernel<<<dim3(48, 16), dim3(32, 8)>>>(w_qkv, wt1p, W3);
    gemm_qkv_kernel<<<dim3(12, 512), 256, SMEM_PIPE_BYTES>>>(b_qkv);
    kv_mma_kernel<<<dim3(32, 16), 256, KV_SMEM_BYTES>>>();
    m_precompute_kernel<<<dim3(4, 8, 8), 256>>>(w_proj);
    zq_kernel<<<dim3(32, 512), 256>>>();
    gemm_proj_kernel<<<dim3(4, 512), 256, SMEM_PIPE_BYTES>>>(b_proj, out);
}

// round 11
// speedup vs baseline: 7.5543x; 1.0641x over previous
#include <cuda_runtime.h>
#include <cuda_fp16.h>
#include <math.h>
#include <stdint.h>

// Problem constants (shape-specialized)
#define BB 4
#define NN 16384
#define CC 512
#define HH 8
#define DD 64
#define NT (BB*NN)     // 65536 rows
#define W3 (3*CC)      // 1536

#define FREQ_COEF (-0.20762050593046014f)
#define QSCALE 1048576.0f          // 2^20
#define QSCALE_INV (1.0f/1048576.0f)

// Scratch (device globals: allocation-free rule)
__device__ __half g_xh[(size_t)NT*CC];     // x as half
__device__ __half g_q[(size_t)BB*HH*NN*DD];
__device__ __half g_k[(size_t)BB*HH*NN*DD];
__device__ __half g_v[(size_t)BB*HH*NN*DD];
__device__ __half g_attn[(size_t)NT*CC];   // holds q'' = z*q*2^20, [n][h*64+d]
__device__ float  g_kv[BB*HH*DD*DD];
__device__ float  g_ksum[BB*HH*DD];
__device__ float  g_trig[128*16*2];        // [pos][fi][{cos,sin}]
__device__ __half g_wt1[(size_t)W3*CC];    // w_qkv^T  [n][k] half
__device__ __half g_mt[(size_t)BB*CC*CC];  // M^T per b: [b][j][h*64+d] half

// ---------------------------------------------------------------------------
// helpers
// ---------------------------------------------------------------------------
__device__ __forceinline__ uint32_t smem_u32(const void* p) {
    uint32_t a;
    asm("{ .reg .u64 t; cvta.to.shared.u64 t, %1; cvt.u32.u64 %0, t; }"
        : "=r"(a) : "l"(p));
    return a;
}

#define CP_ASYNC_16(sa, gp) \
    asm volatile("cp.async.cg.shared.global [%0], [%1], 16;" :: "r"(sa), "l"(gp))

#define MBAR_INIT(addr, cnt) \
    asm volatile("mbarrier.init.shared.b64 [%0], %1;" :: "r"(addr), "r"(cnt) : "memory")

// arrive triggered when all of this thread's prior cp.async complete (.noinc:
// completion counted against the init expected-count)
#define CPA_MBAR_ARRIVE(addr) \
    asm volatile("cp.async.mbarrier.arrive.noinc.shared.b64 [%0];" :: "r"(addr) : "memory")

#define MBAR_ARRIVE(addr) \
    asm volatile("mbarrier.arrive.shared.b64 _, [%0];" :: "r"(addr) : "memory")

#define MBAR_WAIT(mbar_smem_addr, phase_parity) do { \
    uint32_t _mbar = (uint32_t)(mbar_smem_addr); \
    uint32_t _parity = (uint32_t)(phase_parity); \
    uint32_t _done; \
    asm volatile( \
        "{\n\t.reg .pred p;\n\t" \
        "mbarrier.try_wait.parity.acquire.cta.shared::cta.b64 p, [%1], %2;\n\t" \
        "selp.b32 %0, 1, 0, p;\n\t}" \
        : "=r"(_done) : "r"(_mbar), "r"(_parity) : "memory"); \
    if (!_done) { \
        asm volatile( \
            "{\n\t.reg .pred P1;\n\t" \
            "WAIT_LOOP_%=:\n\t" \
            "mbarrier.try_wait.parity.acquire.cta.shared::cta.b64 P1, [%0], %1, 0x989680;\n\t" \
            "@P1 bra.uni WAIT_DONE_%=;\n\t" \
            "bra.uni WAIT_LOOP_%=;\n\t" \
            "WAIT_DONE_%=:\n\t}" \
            :: "r"(_mbar), "r"(_parity) : "memory"); \
    } \
} while(0)

__device__ __forceinline__ void ldsm_x4(unsigned* r, uint32_t addr) {
    asm volatile("ldmatrix.sync.aligned.m8n8.x4.shared.b16 {%0,%1,%2,%3}, [%4];"
        : "=r"(r[0]), "=r"(r[1]), "=r"(r[2]), "=r"(r[3]) : "r"(addr));
}
__device__ __forceinline__ void ldsm_x4_t(unsigned* r, uint32_t addr) {
    asm volatile("ldmatrix.sync.aligned.m8n8.x4.trans.shared.b16 {%0,%1,%2,%3}, [%4];"
        : "=r"(r[0]), "=r"(r[1]), "=r"(r[2]), "=r"(r[3]) : "r"(addr));
}

// fp16 mma m16n8k16, fp32 accumulate
__device__ __forceinline__ void mma16(float* c, const unsigned* a, const unsigned* b) {
    asm volatile(
        "mma.sync.aligned.m16n8k16.row.col.f32.f16.f16.f32 "
        "{%0,%1,%2,%3},{%4,%5,%6,%7},{%8,%9},{%0,%1,%2,%3};\n"
        : "+f"(c[0]), "+f"(c[1]), "+f"(c[2]), "+f"(c[3])
        : "r"(a[0]), "r"(a[1]), "r"(a[2]), "r"(a[3]), "r"(b[0]), "r"(b[1]));
}

// ---------------------------------------------------------------------------
// init: zero kv/ksum + trig table (runs every launch: graph replays)
// ---------------------------------------------------------------------------
__global__ void init_kernel() {
    int i = blockIdx.x * blockDim.x + threadIdx.x;
    if (i < BB*HH*DD*DD) g_kv[i] = 0.f;
    if (i < BB*HH*DD)    g_ksum[i] = 0.f;
    if (i < 128*16) {
        int pos = i >> 4, fi = i & 15;
        float freq = exp2f((float)fi * FREQ_COEF);
        float s, c;
        sincosf((float)pos * freq, &s, &c);
        g_trig[i*2]   = c;
        g_trig[i*2+1] = s;
    }
}

// ---------------------------------------------------------------------------
// convert x fp32 -> half mirror (8 elems/thread)
// ---------------------------------------------------------------------------
__global__ void convert_x_kernel(const float* __restrict__ x) {
    const size_t i = ((size_t)blockIdx.x * 256 + threadIdx.x) * 8;
    float4 a = *(const float4*)(x + i);
    float4 b = *(const float4*)(x + i + 4);
    __half2 h0 = __floats2half2_rn(a.x, a.y);
    __half2 h1 = __floats2half2_rn(a.z, a.w);
    __half2 h2 = __floats2half2_rn(b.x, b.y);
    __half2 h3 = __floats2half2_rn(b.z, b.w);
    *(uint4*)(g_xh + i) = make_uint4(*(unsigned*)&h0, *(unsigned*)&h1,
                                     *(unsigned*)&h2, *(unsigned*)&h3);
}

// ---------------------------------------------------------------------------
// Transpose weights to K-major half: src fp32 [512][N] -> dst half [N][512]
// ---------------------------------------------------------------------------
__global__ void transpose_w_kernel(const float* __restrict__ src,
                                   __half* __restrict__ dst, int N) {
    __shared__ float tile[32][33];
    const int k0 = blockIdx.y << 5, n0 = blockIdx.x << 5;
    const int tx = threadIdx.x, ty = threadIdx.y;   // 32 x 8
#pragma unroll
    for (int i = 0; i < 32; i += 8)
        tile[ty+i][tx] = src[(size_t)(k0+ty+i)*N + n0 + tx];
    __syncthreads();
#pragma unroll
    for (int i = 0; i < 32; i += 8)
        dst[(size_t)(n0+ty+i)*CC + k0 + tx] = __float2half_rn(tile[tx][ty+i]);
}

// ---------------------------------------------------------------------------
// Pipelined fp16 GEMM core: 3-stage cp.async + mbarrier pipeline (warps drift),
// tile 128x128, warp 64x32, K=64. Stage = A[128][72] + B[128][72] halves.
// ---------------------------------------------------------------------------
#define TIL_H 9216             // halves per tile (128*72)
#define STG_H (2*TIL_H)        // halves per stage (A+B)
#define SMEM_PIPE_BYTES (3 * STG_H * 2)   // 110592

__device__ __forceinline__ void issue_stage(
    uint32_t smbase, int stage, const __half* gA, const __half* gB,
    int m0, int n0, int k0, int tid)
{
    const uint32_t stB = smbase + stage*(STG_H*2);
#pragma unroll
    for (int i = 0; i < 4; i++) {
        const int lin = i*256 + tid;          // 1024 chunks per tile
        const int row = lin >> 3;
        const int c8  = (lin & 7) << 3;       // halves
        CP_ASYNC_16(stB + (row*72 + c8)*2,
                    gA + (size_t)(m0 + row)*CC + k0 + c8);
        CP_ASYNC_16(stB + (TIL_H + row*72 + c8)*2,
                    gB + (size_t)(n0 + row)*CC + k0 + c8);
    }
}

__device__ __forceinline__ void compute_stage(
    uint32_t aBase, uint32_t bBase, int stage, float c[4][4][4])
{
    const uint32_t aS = aBase + stage*(STG_H*2);
    const uint32_t bS = bBase + stage*(STG_H*2);
#pragma unroll
    for (int kk = 0; kk < 64; kk += 16) {
        unsigned a[4][4], b[2][4];
#pragma unroll
        for (int mf = 0; mf < 4; mf++)
            ldsm_x4(a[mf], aS + (mf*16*72 + kk)*2);
#pragma unroll
        for (int p = 0; p < 2; p++)
            ldsm_x4(b[p], bS + (p*16*72 + kk)*2);
#pragma unroll
        for (int mf = 0; mf < 4; mf++)
#pragma unroll
            for (int nf = 0; nf < 4; nf++)
                mma16(c[mf][nf], a[mf], &b[nf >> 1][(nf & 1) * 2]);
    }
}

__device__ __forceinline__ uint32_t a_frag_base(uint32_t smbase, int wm, int lane) {
    return smbase + ((wm + (lane & 15))*72 + ((lane >> 4) << 3))*2;
}
__device__ __forceinline__ uint32_t b_frag_base(uint32_t smbase, int wn, int lane) {
    return smbase + TIL_H*2 +
        ((wn + ((lane >> 4) << 3) + (lane & 7))*72 + (((lane >> 3) & 1) << 3))*2;
}

// mbarrier pipeline driver: S stages total, 3 buffers.
// full[b]: completes when all 256 threads' copies landed (noinc, count 256)
// empty[b]: completes when all 256 threads finished reading (count 256)
#define PIPE_LOOP(S, ISSUE, COMPUTE)                                          \
    do {                                                                      \
        if (tid == 0) {                                                       \
            for (int i = 0; i < 3; i++) {                                     \
                MBAR_INIT(mbF + i*8, 256);                                    \
                MBAR_INIT(mbE + i*8, 256);                                    \
            }                                                                 \
        }                                                                     \
        __syncthreads();                                                      \
        ISSUE(0); CPA_MBAR_ARRIVE(mbF);                                       \
        ISSUE(1); CPA_MBAR_ARRIVE(mbF + 8);                                   \
        for (int s = 0; s < (S); s++) {                                       \
            const int buf = s % 3;                                            \
            const int t = s + 2;                                              \
            if (t < (S)) {                                                    \
                if (t >= 3) MBAR_WAIT(mbE + (t%3)*8, ((t/3) - 1) & 1);        \
                ISSUE(t); CPA_MBAR_ARRIVE(mbF + (t%3)*8);                     \
            }                                                                 \
            MBAR_WAIT(mbF + buf*8, (s/3) & 1);                                \
            COMPUTE(buf);                                                     \
            MBAR_ARRIVE(mbE + buf*8);                                         \
        }                                                                     \
    } while (0)

// ---------------------------------------------------------------------------
// GEMM1: qkv = x @ w_qkv + b_qkv, fused RoPE + elu+1, scatter half q/k/v.
// ---------------------------------------------------------------------------
__global__ __launch_bounds__(256, 2) void gemm_qkv_kernel(
    const float* __restrict__ bias)
{
    extern __shared__ __half smp[];
    __shared__ __align__(8) uint64_t mbars[6];
    const uint32_t smbase = smem_u32(smp);
    const uint32_t mbF = smem_u32(&mbars[0]);
    const uint32_t mbE = smem_u32(&mbars[3]);
    const int tid  = threadIdx.x;
    const int warp = tid >> 5, lane = tid & 31;
    const int gid  = lane >> 2, tig = lane & 3;
    const int m0 = blockIdx.y << 7, n0 = blockIdx.x << 7;
    const int wm = (warp >> 2) << 6;
    const int wn = (warp & 3) << 5;

    const uint32_t aB = a_frag_base(smbase, wm, lane);
    const uint32_t bB = b_frag_base(smbase, wn, lane);

    float c[4][4][4];
#pragma unroll
    for (int i = 0; i < 4; i++)
#pragma unroll
        for (int j = 0; j < 4; j++)
#pragma unroll
            for (int r = 0; r < 4; r++) c[i][j][r] = 0.f;

#define G1_ISSUE(t)   issue_stage(smbase, (t)%3, g_xh, g_wt1, m0, n0, (t)*64, tid)
#define G1_COMPUTE(b) compute_stage(aB, bB, (b), c)
    PIPE_LOOP(8, G1_ISSUE, G1_COMPUTE);
#undef G1_ISSUE
#undef G1_COMPUTE

    const int sect = n0 >> 9;             // 0=q 1=k 2=v
#pragma unroll
    for (int nf = 0; nf < 4; nf++) {
        const int col = n0 + wn + nf*8 + 2*tig;
        const int h   = (col >> 6) & 7;
        const int d   = col & 63;
        const float b0v = bias[col], b1v = bias[col+1];
        const int  fi  = (d & 31) >> 1;
        const bool axx = (d < 32);
#pragma unroll
        for (int mf = 0; mf < 4; mf++) {
#pragma unroll
            for (int hf = 0; hf < 2; hf++) {
                const int r    = m0 + wm + mf*16 + gid + 8*hf;
                const int bidx = r >> 14;
                const int t    = r & (NN-1);
                float v0 = c[mf][nf][2*hf]   + b0v;
                float v1 = c[mf][nf][2*hf+1] + b1v;
                const size_t base = ((size_t)(bidx*HH + h)*NN + t)*DD + d;
                if (sect == 2) {
                    *(__half2*)(g_v + base) = __floats2half2_rn(v0, v1);
                } else {
                    const int pos = axx ? (t & 127) : (t >> 7);
                    const float2 cs = *(const float2*)(g_trig + ((pos << 4) + fi)*2);
                    float orr = v0*cs.x - v1*cs.y;
                    float oii = v0*cs.y + v1*cs.x;
                    orr = (orr > 0.f) ? orr + 1.f : __expf(orr);
                    oii = (oii > 0.f) ? oii + 1.f : __expf(oii);
                    __half* dst = (sect == 0) ? g_q : g_k;
                    *(__half2*)(dst + base) = __floats2half2_rn(orr, oii);
                }
            }
        }
    }
}

// ---------------------------------------------------------------------------
// GEMM2: out = q'' @ M_stack[b] * 2^-20 + b_proj
// ---------------------------------------------------------------------------
__global__ __launch_bounds__(256, 2) void gemm_proj_kernel(
    const float* __restrict__ bias,
    float* __restrict__ out)
{
    extern __shared__ __half smp[];
    __shared__ __align__(8) uint64_t mbars[6];
    const uint32_t smbase = smem_u32(smp);
    const uint32_t mbF = smem_u32(&mbars[0]);
    const uint32_t mbE = smem_u32(&mbars[3]);
    const int tid  = threadIdx.x;
    const int warp = tid >> 5, lane = tid & 31;
    const int gid  = lane >> 2, tig = lane & 3;
    const int m0 = blockIdx.y << 7, n0 = blockIdx.x << 7;
    const int wm = (warp >> 2) << 6;
    const int wn = (warp & 3) << 5;
    const __half* gB = g_mt + (size_t)(blockIdx.y >> 7)*CC*CC;

    const uint32_t aB = a_frag_base(smbase, wm, lane);
    const uint32_t bB = b_frag_base(smbase, wn, lane);

    float c[4][4][4];
#pragma unroll
    for (int i = 0; i < 4; i++)
#pragma unroll
        for (int j = 0; j < 4; j++)
#pragma unroll
            for (int r = 0; r < 4; r++) c[i][j][r] = 0.f;

#define G2_ISSUE(t)   issue_stage(smbase, (t)%3, g_attn, gB, m0, n0, (t)*64, tid)
#define G2_COMPUTE(b) compute_stage(aB, bB, (b), c)
    PIPE_LOOP(8, G2_ISSUE, G2_COMPUTE);
#undef G2_ISSUE
#undef G2_COMPUTE

#pragma unroll
    for (int nf = 0; nf < 4; nf++) {
        const int col = n0 + wn + nf*8 + 2*tig;
        const float b0v = bias[col], b1v = bias[col+1];
#pragma unroll
        for (int mf = 0; mf < 4; mf++) {
#pragma unroll
            for (int hf = 0; hf < 2; hf++) {
                const int r = m0 + wm + mf*16 + gid + 8*hf;
                *(float2*)(out + (size_t)r*CC + col) =
                    make_float2(c[mf][nf][2*hf]*QSCALE_INV + b0v,
                                c[mf][nf][2*hf+1]*QSCALE_INV + b1v);
            }
        }
    }
}

// ---------------------------------------------------------------------------
// kv[b,h,d,e] = sum_n k[n,d] v[n,e];  ksum via ones-column (col 64).
// fp16 mma, trans-ldmatrix, 3-stage cp.async + mbarrier pipeline.
// ---------------------------------------------------------------------------
#define KT_S 72   // k tile stride (halves)
#define VT_S 88   // v tile stride (halves)
#define KV_STG_H (64*KT_S + 64*VT_S)     // 10240 halves per stage
#define KV_SMEM_BYTES (3 * KV_STG_H * 2) // 61440

__device__ __forceinline__ void kv_issue(
    uint32_t smbase, int stage, const __half* kb, const __half* vb,
    int n0, int tid)
{
    const uint32_t stB = smbase + stage*(KV_STG_H*2);
#pragma unroll
    for (int i = 0; i < 2; i++) {
        const int lin = i*256 + tid;
        const int row = lin >> 3, c8 = (lin & 7) << 3;
        CP_ASYNC_16(stB + (row*KT_S + c8)*2,
                    kb + (size_t)(n0 + row)*DD + c8);
        CP_ASYNC_16(stB + (64*KT_S + row*VT_S + c8)*2,
                    vb + (size_t)(n0 + row)*DD + c8);
    }
}

__global__ __launch_bounds__(256, 2) void kv_mma_kernel() {
    extern __shared__ __half kvsm[];
    __shared__ __align__(8) uint64_t mbars[6];
    const uint32_t smbase = smem_u32(kvsm);
    const uint32_t mbF = smem_u32(&mbars[0]);
    const uint32_t mbE = smem_u32(&mbars[3]);

    const int tid  = threadIdx.x;
    const int warp = tid >> 5, lane = tid & 31;
    const int gid  = lane >> 2, tig = lane & 3;
    const int bh    = blockIdx.x;
    const int nbase = blockIdx.y << 10;
    const int d0   = (warp & 3) << 4;     // m-tile (d)
    const int srow = (warp >> 2) << 5;    // seq slice 0/32

    if (tid < 64) {
#pragma unroll
        for (int st = 0; st < 3; st++) {
            __half* Vt = kvsm + st*KV_STG_H + 64*KT_S;
            Vt[tid*VT_S + 64] = __float2half(1.f);
#pragma unroll
            for (int j = 65; j < 80; j++) Vt[tid*VT_S + j] = __float2half(0.f);
        }
    }
    __syncthreads();

    float c[9][4];
#pragma unroll
    for (int t = 0; t < 9; t++)
#pragma unroll
        for (int r = 0; r < 4; r++) c[t][r] = 0.f;

    const __half* kb = g_k + (size_t)bh*NN*DD;
    const __half* vb = g_v + (size_t)bh*NN*DD;

    const int at_row = ((lane >> 4) << 3) + (lane & 7);
    const int at_col = d0 + (((lane >> 3) & 1) << 3);
    const int bt_row = (((lane >> 3) & 1) << 3) + (lane & 7);
    const int bt_coff = ((lane >> 4) << 3);

#define KV_ISSUE(t) kv_issue(smbase, (t)%3, kb, vb, nbase + (t)*64, tid)
#define KV_COMPUTE(bufi)                                                       \
    do {                                                                       \
        const uint32_t ktB = smbase + (bufi)*(KV_STG_H*2);                     \
        const uint32_t vtB = ktB + 64*KT_S*2;                                  \
        _Pragma("unroll")                                                      \
        for (int ks = 0; ks < 2; ks++) {                                       \
            const int s16 = srow + ks*16;                                      \
            unsigned a[4], b[5][4];                                            \
            ldsm_x4_t(a, ktB + ((s16 + at_row)*KT_S + at_col)*2);              \
            _Pragma("unroll")                                                  \
            for (int bt = 0; bt < 5; bt++)                                     \
                ldsm_x4_t(b[bt], vtB + ((s16 + bt_row)*VT_S + bt*16 + bt_coff)*2); \
            _Pragma("unroll")                                                  \
            for (int t2 = 0; t2 < 9; t2++)                                     \
                mma16(c[t2], a, &b[t2 >> 1][(t2 & 1) * 2]);                    \
        }                                                                      \
    } while (0)
    PIPE_LOOP(16, KV_ISSUE, KV_COMPUTE);
#undef KV_ISSUE
#undef KV_COMPUTE

    float* kvp = g_kv + bh*DD*DD;
#pragma unroll
    for (int t = 0; t < 8; t++) {
        const int e = t*8 + 2*tig;
        atomicAdd(&kvp[(d0+gid)*DD + e],       c[t][0]);
        atomicAdd(&kvp[(d0+gid)*DD + e + 1],   c[t][1]);
        atomicAdd(&kvp[(d0+gid+8)*DD + e],     c[t][2]);
        atomicAdd(&kvp[(d0+gid+8)*DD + e + 1], c[t][3]);
    }
    if (tig == 0) {
        atomicAdd(&g_ksum[bh*DD + d0 + gid],     c[8][0]);
        atomicAdd(&g_ksum[bh*DD + d0 + gid + 8], c[8][2]);
    }
}

// ---------------------------------------------------------------------------
// M^T[b][j][h*64+d] = sum_e kv[b,h,d,e] * w_proj[h*64+e, j]   (half out)
// ---------------------------------------------------------------------------
__global__ __launch_bounds__(256) void m_precompute_kernel(
    const float* __restrict__ w_proj)
{
    __shared__ float kvs[64][65];
    __shared__ float ws[64][65];
    const int b = blockIdx.x, h = blockIdx.y, j0 = blockIdx.z << 6;
    const int tid = threadIdx.x;
    const float* kvp = g_kv + ((b*HH + h)*DD*DD);

#pragma unroll
    for (int i = 0; i < 16; i++) {
        const int lin = i*256 + tid;          // 4096
        const int r = lin >> 6, cidx = lin & 63;
        kvs[r][cidx] = kvp[r*DD + cidx];
        ws[r][cidx]  = w_proj[(size_t)(h*DD + r)*CC + j0 + cidx];
    }
    __syncthreads();

    const int d = tid & 63;
    const int jg = tid >> 6;                  // 0..3
#pragma unroll
    for (int jj = 0; jj < 16; jj++) {
        const int j = jg*16 + jj;
        float acc = 0.f;
#pragma unroll
        for (int e = 0; e < 64; e++)
            acc = fmaf(kvs[d][e], ws[e][j], acc);
        g_mt[((size_t)b*CC + j0 + j)*CC + h*DD + d] = __float2half_rn(acc);
    }
}

// ---------------------------------------------------------------------------
// q''[b*NN+n][h*64+d] = q[b,h,n,d] * 2^20 / (q.ksum + 1e-6)
// ---------------------------------------------------------------------------
__global__ __launch_bounds__(256) void zq_kernel() {
    const int bh = blockIdx.x, b = bh >> 3, h = bh & 7;
    const int tid = threadIdx.x;
    const int r8 = tid >> 3;
    const int t8 = tid & 7;
    const int n  = (blockIdx.y << 5) + r8;

    uint4 u = *(const uint4*)(g_q + ((size_t)bh*NN + n)*DD + t8*8);
    float f[8];
    {
        __half2* hp = (__half2*)&u;
#pragma unroll
        for (int i = 0; i < 4; i++) {
            float2 t = __half22float2(hp[i]);
            f[2*i] = t.x; f[2*i+1] = t.y;
        }
    }
    const float* ks = g_ksum + bh*DD + t8*8;
    float dot = 0.f;
#pragma unroll
    for (int i = 0; i < 8; i++) dot = fmaf(f[i], ks[i], dot);
    dot += __shfl_xor_sync(0xffffffffu, dot, 1);
    dot += __shfl_xor_sync(0xffffffffu, dot, 2);
    dot += __shfl_xor_sync(0xffffffffu, dot, 4);
    const float z = QSCALE / (dot + 1e-6f);

    __half2 o[4];
#pragma unroll
    for (int i = 0; i < 4; i++)
        o[i] = __floats2half2_rn(f[2*i]*z, f[2*i+1]*z);
    *(uint4*)(g_attn + ((size_t)b*NN + n)*CC + h*DD + t8*8) =
        *(uint4*)o;
}

// ---------------------------------------------------------------------------
extern "C" void kernel_launch(void* const* d_in, const int* in_sizes, int n_in,
                              void* d_out, int out_size) {
    const float* x      = (const float*)d_in[0];
    const float* w_qkv  = (const float*)d_in[1];
    const float* b_qkv  = (const float*)d_in[2];
    const float* w_proj = (const float*)d_in[3];
    const float* b_proj = (const float*)d_in[4];
    float* out = (float*)d_out;

    cudaFuncSetAttribute(gemm_qkv_kernel,
        cudaFuncAttributeMaxDynamicSharedMemorySize, SMEM_PIPE_BYTES);
    cudaFuncSetAttribute(gemm_proj_kernel,
        cudaFuncAttributeMaxDynamicSharedMemorySize, SMEM_PIPE_BYTES);
    cudaFuncSetAttribute(kv_mma_kernel,
        cudaFuncAttributeMaxDynamicSharedMemorySize, KV_SMEM_BYTES);

    __half* wt1p;
    cudaGetSymbolAddress((void**)&wt1p, g_wt1);

    init_kernel<<<512, 256>>>();
    convert_x_kernel<<<16384, 256>>>(x);
    transpose_w_kernel<<<dim3(48, 16), dim3(32, 8)>>>(w_qkv, wt1p, W3);
    gemm_qkv_kernel<<<dim3(12, 512), 256, SMEM_PIPE_BYTES>>>(b_qkv);
    kv_mma_kernel<<<dim3(32, 16), 256, KV_SMEM_BYTES>>>();
    m_precompute_kernel<<<dim3(4, 8, 8), 256>>>(w_proj);
    zq_kernel<<<dim3(32, 512), 256>>>();
    gemm_proj_kernel<<<dim3(4, 512), 256, SMEM_PIPE_BYTES>>>(b_proj, out);
}